// round 2
// baseline (speedup 1.0000x reference)
#include <cuda_runtime.h>
#include <cuda_bf16.h>
#include <math.h>

// Problem dims
#define NB 2048
#define NN 64
#define ND 256
#define NDH 128

// smem strides (floats)
#define XS_LD 260   // 64 x 260
#define QK_LD 260   // 64 x 260
#define A_LD  68    // 64 x 68
#define WB_LD 264   // 32 x 264 (transposed weight chunk: [kk][o])

#define XS_OFF 0
#define QK_OFF (64 * XS_LD)
#define AB_OFF (QK_OFF + 64 * QK_LD)
#define WB_OFF (AB_OFF + 64 * A_LD)
#define SMEM_FLOATS (WB_OFF + 32 * WB_LD)
#define SMEM_BYTES (SMEM_FLOATS * 4)

__device__ float g_Ast[2 * 64 * 64];  // softmax(adj0), softmax(adj1)

typedef unsigned long long ull;

#define FMA2(d, a, b) \
    asm("fma.rn.f32x2 %0, %1, %2, %0;" : "+l"(d) : "l"(a), "l"(b))

__device__ __forceinline__ float f4c(const float4& v, int u) {
    switch (u) {
        case 0: return v.x;
        case 1: return v.y;
        case 2: return v.z;
        default: return v.w;
    }
}

// Accumulate OUT[64][256] += A[64 rows][K] * B[K][256]
// A rows owned by thread: r = ty*4+ri, read As[r*lda + acol0 + kk]
// B read Bs[kk*ldb + c], thread cols c = tx*4 + 64*g + {0..3}
__device__ __forceinline__ void gemm_tile(
    ull acc[4][8],
    const float* __restrict__ As, int lda, int acol0,
    const float* __restrict__ Bs, int ldb, int kcnt,
    int tx, int ty)
{
    for (int kk4 = 0; kk4 < kcnt; kk4 += 4) {
        float4 av[4];
#pragma unroll
        for (int ri = 0; ri < 4; ri++)
            av[ri] = *(const float4*)(As + (ty * 4 + ri) * lda + acol0 + kk4);
#pragma unroll
        for (int u = 0; u < 4; u++) {
            const float* brow = Bs + (kk4 + u) * ldb + tx * 4;
            ulonglong2 b0 = *(const ulonglong2*)(brow);
            ulonglong2 b1 = *(const ulonglong2*)(brow + 64);
            ulonglong2 b2 = *(const ulonglong2*)(brow + 128);
            ulonglong2 b3 = *(const ulonglong2*)(brow + 192);
#pragma unroll
            for (int ri = 0; ri < 4; ri++) {
                float a = f4c(av[ri], u);
                ull aa;
                asm("mov.b64 %0, {%1, %2};" : "=l"(aa) : "f"(a), "f"(a));
                FMA2(acc[ri][0], aa, b0.x);
                FMA2(acc[ri][1], aa, b0.y);
                FMA2(acc[ri][2], aa, b1.x);
                FMA2(acc[ri][3], aa, b1.y);
                FMA2(acc[ri][4], aa, b2.x);
                FMA2(acc[ri][5], aa, b2.y);
                FMA2(acc[ri][6], aa, b3.x);
                FMA2(acc[ri][7], aa, b3.y);
            }
        }
    }
}

__device__ __forceinline__ void zero_acc(ull acc[4][8]) {
#pragma unroll
    for (int ri = 0; ri < 4; ri++)
#pragma unroll
        for (int j = 0; j < 8; j++) acc[ri][j] = 0ull;
}

// Store accumulator tile to dst (smem or global), optional bias add.
__device__ __forceinline__ void store_acc(
    ull acc[4][8], float* dst, int ldd,
    const float* __restrict__ bias, int tx, int ty)
{
#pragma unroll
    for (int ri = 0; ri < 4; ri++) {
        int r = ty * 4 + ri;
#pragma unroll
        for (int g = 0; g < 4; g++) {
            int c0 = tx * 4 + 64 * g;
            float x0, x1, x2, x3;
            asm("mov.b64 {%0, %1}, %2;" : "=f"(x0), "=f"(x1) : "l"(acc[ri][2 * g]));
            asm("mov.b64 {%0, %1}, %2;" : "=f"(x2), "=f"(x3) : "l"(acc[ri][2 * g + 1]));
            float4 o = make_float4(x0, x1, x2, x3);
            if (bias) {
                float4 bb = *(const float4*)(bias + c0);
                o.x += bb.x; o.y += bb.y; o.z += bb.z; o.w += bb.w;
            }
            *(float4*)(dst + (size_t)r * ldd + c0) = o;
        }
    }
}

// Stage transposed weight chunk: wbuf_t[kk][o] = W[o][k0+kk], kk in [0,32), o in [0,256)
// o < 128 rows come from w_lo, o >= 128 from w_hi (row o-128).
__device__ __forceinline__ void stage_w(
    float* wbuf_t, const float* __restrict__ w_lo,
    const float* __restrict__ w_hi, int k0, int tid)
{
    int o = (tid >> 3);          // base row group; add i*32
    int j = (tid & 7) * 4;       // column within chunk (4 floats)
#pragma unroll
    for (int i = 0; i < 8; i++) {
        int oo = i * 32 + o;
        const float* src = (oo < 128) ? (w_lo + (size_t)oo * ND)
                                      : (w_hi + (size_t)(oo - 128) * ND);
        float4 v = *(const float4*)(src + k0 + j);
        wbuf_t[(j + 0) * WB_LD + oo] = v.x;
        wbuf_t[(j + 1) * WB_LD + oo] = v.y;
        wbuf_t[(j + 2) * WB_LD + oo] = v.z;
        wbuf_t[(j + 3) * WB_LD + oo] = v.w;
    }
}

// LayerNorm over D=256 for 64 rows; warp-per-row, 8 rows per warp.
__device__ __forceinline__ void ln_rows(
    const float* __restrict__ src, int lds,
    float* dst, int ldd,
    const float* __restrict__ gg, const float* __restrict__ bb,
    bool leaky, int tid)
{
    int warp = tid >> 5, lane = tid & 31;
    for (int n = warp; n < 64; n += 8) {
        const float* row = src + (size_t)n * lds;
        float v[8];
        float s = 0.f, sq = 0.f;
#pragma unroll
        for (int i = 0; i < 8; i++) {
            float t = row[lane + 32 * i];
            v[i] = t;
            s += t;
            sq += t * t;
        }
#pragma unroll
        for (int off = 16; off > 0; off >>= 1) {
            s += __shfl_xor_sync(0xffffffffu, s, off);
            sq += __shfl_xor_sync(0xffffffffu, sq, off);
        }
        float mean = s * (1.0f / 256.0f);
        float var = sq * (1.0f / 256.0f) - mean * mean;
        float rstd = rsqrtf(var + 1e-5f);
#pragma unroll
        for (int i = 0; i < 8; i++) {
            int c = lane + 32 * i;
            float o = (v[i] - mean) * rstd * gg[c] + bb[c];
            if (leaky) o = (o >= 0.f) ? o : 0.1f * o;
            dst[(size_t)n * ldd + c] = o;
        }
    }
}

// Precompute softmax of the two static adjacency matrices (row softmax, 64x64).
__global__ void adj_softmax_kernel(const float* __restrict__ adj0,
                                   const float* __restrict__ adj1)
{
    const float* adj = blockIdx.x ? adj1 : adj0;
    float* dst = g_Ast + blockIdx.x * 4096;
    int r = threadIdx.x;  // 64 threads
    const float* row = adj + r * 64;
    float mx = -1e30f;
    for (int m = 0; m < 64; m++) mx = fmaxf(mx, row[m]);
    float s = 0.f;
    for (int m = 0; m < 64; m++) s += __expf(row[m] - mx);
    float inv = 1.0f / s;
    for (int m = 0; m < 64; m++) dst[r * 64 + m] = __expf(row[m] - mx) * inv;
}

__global__ void __launch_bounds__(256, 1) gconv_kernel(
    const float* __restrict__ graph,
    const float* __restrict__ ln_in_g, const float* __restrict__ ln_in_b,
    const float* __restrict__ th0, const float* __restrict__ ph0,
    const float* __restrict__ fcw0, const float* __restrict__ fcb0,
    const float* __restrict__ ln0_g, const float* __restrict__ ln0_b,
    const float* __restrict__ th1, const float* __restrict__ ph1,
    const float* __restrict__ fcw1, const float* __restrict__ fcb1,
    float* __restrict__ out)
{
    extern __shared__ float sm[];
    float* xs = sm + XS_OFF;
    float* qk = sm + QK_OFF;
    float* Ab = sm + AB_OFF;
    float* wb = sm + WB_OFF;

    int tid = threadIdx.x;
    int tx = tid & 15, ty = tid >> 4;
    int warp = tid >> 5, lane = tid & 31;
    int b = blockIdx.x;

    // ---- input LayerNorm: global graph[b] -> xs ----
    ln_rows(graph + (size_t)b * NN * ND, ND, xs, XS_LD, ln_in_g, ln_in_b, false, tid);
    __syncthreads();

#pragma unroll 1
    for (int l = 0; l < 2; l++) {
        const float* th = l ? th1 : th0;
        const float* ph = l ? ph1 : ph0;
        const float* fcw = l ? fcw1 : fcw0;
        const float* fcb = l ? fcb1 : fcb0;

        // ---- qk = xs @ [th;ph]^T  -> qk[64][256] (q: cols 0..127, k: 128..255) ----
        ull acc[4][8];
        zero_acc(acc);
        for (int k0 = 0; k0 < ND; k0 += 32) {
            __syncthreads();  // wb free
            stage_w(wb, th, ph, k0, tid);
            __syncthreads();
            gemm_tile(acc, xs, XS_LD, k0, wb, WB_LD, 32, tx, ty);
        }
        store_acc(acc, qk, QK_LD, nullptr, tx, ty);
        __syncthreads();

        // ---- scores[n][m] = dot(q[n], k[m]) / sqrt(128) -> Ab raw ----
        {
            float sacc[4][4] = {};
            for (int kk4 = 0; kk4 < NDH; kk4 += 4) {
                float4 aq[4], bk[4];
#pragma unroll
                for (int ri = 0; ri < 4; ri++)
                    aq[ri] = *(const float4*)(qk + (ty * 4 + ri) * QK_LD + kk4);
#pragma unroll
                for (int ci = 0; ci < 4; ci++)
                    bk[ci] = *(const float4*)(qk + (tx + 16 * ci) * QK_LD + 128 + kk4);
#pragma unroll
                for (int u = 0; u < 4; u++)
#pragma unroll
                    for (int ri = 0; ri < 4; ri++)
#pragma unroll
                        for (int ci = 0; ci < 4; ci++)
                            sacc[ri][ci] += f4c(aq[ri], u) * f4c(bk[ci], u);
            }
            const float sscale = 0.08838834764831845f;  // 1/sqrt(128)
#pragma unroll
            for (int ri = 0; ri < 4; ri++)
#pragma unroll
                for (int ci = 0; ci < 4; ci++)
                    Ab[(ty * 4 + ri) * A_LD + tx + 16 * ci] = sacc[ri][ci] * sscale;
        }
        __syncthreads();

        // ---- A_hat = A_static + row_softmax(scores), in place in Ab ----
        {
            const float* Ast = g_Ast + l * 4096;
            for (int n = warp; n < 64; n += 8) {
                float v0 = Ab[n * A_LD + lane];
                float v1 = Ab[n * A_LD + 32 + lane];
                float mx = fmaxf(v0, v1);
#pragma unroll
                for (int off = 16; off > 0; off >>= 1)
                    mx = fmaxf(mx, __shfl_xor_sync(0xffffffffu, mx, off));
                float e0 = __expf(v0 - mx);
                float e1 = __expf(v1 - mx);
                float ss = e0 + e1;
#pragma unroll
                for (int off = 16; off > 0; off >>= 1)
                    ss += __shfl_xor_sync(0xffffffffu, ss, off);
                float inv = 1.0f / ss;
                Ab[n * A_LD + lane] = Ast[n * 64 + lane] + e0 * inv;
                Ab[n * A_LD + 32 + lane] = Ast[n * 64 + 32 + lane] + e1 * inv;
            }
        }
        __syncthreads();

        // ---- agg = A_hat @ xs -> qk buffer (reused) ----
        zero_acc(acc);
        gemm_tile(acc, Ab, A_LD, 0, xs, XS_LD, 64, tx, ty);
        store_acc(acc, qk, QK_LD, nullptr, tx, ty);
        __syncthreads();

        // ---- fc: out = agg @ fcw^T + fcb ----
        zero_acc(acc);
        for (int k0 = 0; k0 < ND; k0 += 32) {
            __syncthreads();
            stage_w(wb, fcw, fcw + 128 * ND, k0, tid);
            __syncthreads();
            gemm_tile(acc, qk, QK_LD, k0, wb, WB_LD, 32, tx, ty);
        }
        if (l == 0) {
            store_acc(acc, xs, XS_LD, fcb, tx, ty);
            __syncthreads();
            // LN + LeakyReLU(0.1), in place in xs
            ln_rows(xs, XS_LD, xs, XS_LD, ln0_g, ln0_b, true, tid);
            __syncthreads();
        } else {
            store_acc(acc, out + (size_t)b * NN * ND, ND, fcb, tx, ty);
        }
    }
}

extern "C" void kernel_launch(void* const* d_in, const int* in_sizes, int n_in,
                              void* d_out, int out_size)
{
    const float* graph   = (const float*)d_in[0];
    const float* ln_in_g = (const float*)d_in[1];
    const float* ln_in_b = (const float*)d_in[2];
    const float* adj0    = (const float*)d_in[3];
    const float* th0     = (const float*)d_in[4];
    const float* ph0     = (const float*)d_in[5];
    const float* fcw0    = (const float*)d_in[6];
    const float* fcb0    = (const float*)d_in[7];
    const float* ln0_g   = (const float*)d_in[8];
    const float* ln0_b   = (const float*)d_in[9];
    const float* adj1    = (const float*)d_in[10];
    const float* th1     = (const float*)d_in[11];
    const float* ph1     = (const float*)d_in[12];
    const float* fcw1    = (const float*)d_in[13];
    const float* fcb1    = (const float*)d_in[14];
    float* out = (float*)d_out;

    cudaFuncSetAttribute(gconv_kernel,
                         cudaFuncAttributeMaxDynamicSharedMemorySize, SMEM_BYTES);

    adj_softmax_kernel<<<2, 64>>>(adj0, adj1);
    gconv_kernel<<<NB, 256, SMEM_BYTES>>>(
        graph, ln_in_g, ln_in_b,
        th0, ph0, fcw0, fcb0, ln0_g, ln0_b,
        th1, ph1, fcw1, fcb1, out);
}

// round 3
// speedup vs baseline: 1.1243x; 1.1243x over previous
#include <cuda_runtime.h>
#include <cuda_bf16.h>
#include <math.h>

// Problem dims
#define NB 2048
#define NN 64
#define ND 256
#define NDH 128

#define NT 512          // threads per CTA (16 warps)

// smem strides (floats)
#define XS_LD 260   // 64 x 260  (granule step/row = 65, odd -> conflict-free)
#define QK_LD 260
#define A_LD  68    // 64 x 68   (granule step/row = 17, odd)
#define WB_LD 260   // 32 x 260  transposed weight chunk: wb[kk][o]

#define XS_OFF 0
#define QK_OFF (64 * XS_LD)
#define AB_OFF (QK_OFF + 64 * QK_LD)
#define WB_OFF (AB_OFF + 64 * A_LD)
#define SMEM_FLOATS (WB_OFF + 32 * WB_LD)
#define SMEM_BYTES (SMEM_FLOATS * 4)

__device__ float g_Ast[2 * 64 * 64];  // softmax(adj0), softmax(adj1)

typedef unsigned long long ull;

#define FMA2(d, a, b) \
    asm("fma.rn.f32x2 %0, %1, %2, %0;" : "+l"(d) : "l"(a), "l"(b))

__device__ __forceinline__ ull packf2(float a, float b) {
    ull r;
    asm("mov.b64 %0, {%1, %2};" : "=l"(r) : "f"(a), "f"(b));
    return r;
}
__device__ __forceinline__ float2 unpackf2(ull v) {
    float x, y;
    asm("mov.b64 {%0, %1}, %2;" : "=f"(x), "=f"(y) : "l"(v));
    return make_float2(x, y);
}

__device__ __forceinline__ float f4c(const float4& v, int u) {
    switch (u) {
        case 0: return v.x;
        case 1: return v.y;
        case 2: return v.z;
        default: return v.w;
    }
}

// ---------------------------------------------------------------------------
// GEMM tile: OUT[64][256] += A[64][K] * B[K][256]
// Thread (m = lane&15, h = lane>>4, w = warp):
//   rows  r = m + 16*ri  (ri 0..3)          -> conflict-free A loads
//   cols  c = w*16 + h*8 + {0..7}           -> 16-way bcast B loads, 1 wf
// acc[ri][cu] : f32x2 pair of cols (c0+2cu, c0+2cu+1)
// ---------------------------------------------------------------------------
__device__ __forceinline__ void gemm_tile(
    ull acc[4][4],
    const float* __restrict__ As, int lda, int acol0,
    const float* __restrict__ Bs, int ldb, int kcnt,
    int m, int c0)
{
    for (int kk4 = 0; kk4 < kcnt; kk4 += 4) {
        float4 av[4];
#pragma unroll
        for (int ri = 0; ri < 4; ri++)
            av[ri] = *(const float4*)(As + (m + 16 * ri) * lda + acol0 + kk4);
#pragma unroll
        for (int u = 0; u < 4; u++) {
            const float* brow = Bs + (kk4 + u) * ldb + c0;
            ulonglong2 b0 = *(const ulonglong2*)(brow);
            ulonglong2 b1 = *(const ulonglong2*)(brow + 4);
#pragma unroll
            for (int ri = 0; ri < 4; ri++) {
                float a = f4c(av[ri], u);
                ull aa = packf2(a, a);
                FMA2(acc[ri][0], aa, b0.x);
                FMA2(acc[ri][1], aa, b0.y);
                FMA2(acc[ri][2], aa, b1.x);
                FMA2(acc[ri][3], aa, b1.y);
            }
        }
    }
}

__device__ __forceinline__ void zero_acc(ull acc[4][4]) {
#pragma unroll
    for (int ri = 0; ri < 4; ri++)
#pragma unroll
        for (int j = 0; j < 4; j++) acc[ri][j] = 0ull;
}

__device__ __forceinline__ void store_acc(
    ull acc[4][4], float* dst, int ldd,
    const float* __restrict__ bias, int m, int c0)
{
#pragma unroll
    for (int ri = 0; ri < 4; ri++) {
        int r = m + 16 * ri;
#pragma unroll
        for (int f = 0; f < 2; f++) {
            float2 p0 = unpackf2(acc[ri][2 * f]);
            float2 p1 = unpackf2(acc[ri][2 * f + 1]);
            float4 o = make_float4(p0.x, p0.y, p1.x, p1.y);
            int cc = c0 + 4 * f;
            if (bias) {
                float4 bb = *(const float4*)(bias + cc);
                o.x += bb.x; o.y += bb.y; o.z += bb.z; o.w += bb.w;
            }
            *(float4*)(dst + (size_t)r * ldd + cc) = o;
        }
    }
}

// ---------------------------------------------------------------------------
// Stage transposed weight chunk: wb[kk][o] = W[o][k0+kk], kk in [0,32), o in [0,256)
// Lane kk = tid&31 (conflict-free STS.128: granule 65*kk + o/4, 32 distinct),
// LDG: 32 consecutive kk per warp -> 128B coalesced segments.
// ---------------------------------------------------------------------------
__device__ __forceinline__ void stage_w(
    float* __restrict__ wb, const float* __restrict__ w_lo,
    const float* __restrict__ w_hi, int k0, int tid)
{
    int kk = tid & 31;
    int wv = tid >> 5;  // 0..15
#pragma unroll
    for (int it = 0; it < 4; it++) {
        int o0 = wv * 16 + it * 4;
        const float* s = (o0 < 128) ? (w_lo + (size_t)o0 * ND)
                                    : (w_hi + (size_t)(o0 - 128) * ND);
        float4 v;
        v.x = s[0 * ND + k0 + kk];
        v.y = s[1 * ND + k0 + kk];
        v.z = s[2 * ND + k0 + kk];
        v.w = s[3 * ND + k0 + kk];
        *(float4*)(wb + kk * WB_LD + o0) = v;
    }
}

// LayerNorm over D=256 for 64 rows; warp-per-row, 16 warps -> 4 rows/warp.
__device__ __forceinline__ void ln_rows(
    const float* __restrict__ src, int lds,
    float* dst, int ldd,
    const float* __restrict__ gg, const float* __restrict__ bb,
    bool leaky, int tid)
{
    int warp = tid >> 5, lane = tid & 31;
    for (int n = warp; n < 64; n += 16) {
        const float* row = src + (size_t)n * lds;
        float v[8];
        float s = 0.f, sq = 0.f;
#pragma unroll
        for (int i = 0; i < 8; i++) {
            float t = row[lane + 32 * i];
            v[i] = t;
            s += t;
            sq += t * t;
        }
#pragma unroll
        for (int off = 16; off > 0; off >>= 1) {
            s += __shfl_xor_sync(0xffffffffu, s, off);
            sq += __shfl_xor_sync(0xffffffffu, sq, off);
        }
        float mean = s * (1.0f / 256.0f);
        float var = sq * (1.0f / 256.0f) - mean * mean;
        float rstd = rsqrtf(var + 1e-5f);
#pragma unroll
        for (int i = 0; i < 8; i++) {
            int c = lane + 32 * i;
            float o = (v[i] - mean) * rstd * gg[c] + bb[c];
            if (leaky) o = (o >= 0.f) ? o : 0.1f * o;
            dst[(size_t)n * ldd + c] = o;
        }
    }
}

// Precompute softmax of the two static adjacency matrices (row softmax, 64x64).
__global__ void adj_softmax_kernel(const float* __restrict__ adj0,
                                   const float* __restrict__ adj1)
{
    const float* adj = blockIdx.x ? adj1 : adj0;
    float* dst = g_Ast + blockIdx.x * 4096;
    int r = threadIdx.x;  // 64 threads
    const float* row = adj + r * 64;
    float mx = -1e30f;
    for (int m = 0; m < 64; m++) mx = fmaxf(mx, row[m]);
    float s = 0.f;
    for (int m = 0; m < 64; m++) s += __expf(row[m] - mx);
    float inv = 1.0f / s;
    for (int m = 0; m < 64; m++) dst[r * 64 + m] = __expf(row[m] - mx) * inv;
}

__global__ void __launch_bounds__(NT, 1) gconv_kernel(
    const float* __restrict__ graph,
    const float* __restrict__ ln_in_g, const float* __restrict__ ln_in_b,
    const float* __restrict__ th0, const float* __restrict__ ph0,
    const float* __restrict__ fcw0, const float* __restrict__ fcb0,
    const float* __restrict__ ln0_g, const float* __restrict__ ln0_b,
    const float* __restrict__ th1, const float* __restrict__ ph1,
    const float* __restrict__ fcw1, const float* __restrict__ fcb1,
    float* __restrict__ out)
{
    extern __shared__ float sm[];
    float* xs = sm + XS_OFF;
    float* qk = sm + QK_OFF;
    float* Ab = sm + AB_OFF;
    float* wb = sm + WB_OFF;

    int tid = threadIdx.x;
    int warp = tid >> 5, lane = tid & 31;
    int m = lane & 15;              // row group within warp
    int c0 = warp * 16 + (lane >> 4) * 8;  // col base (8 cols per thread)
    int b = blockIdx.x;

    // ---- input LayerNorm: global graph[b] -> xs ----
    ln_rows(graph + (size_t)b * NN * ND, ND, xs, XS_LD, ln_in_g, ln_in_b, false, tid);
    __syncthreads();

#pragma unroll 1
    for (int l = 0; l < 2; l++) {
        const float* th = l ? th1 : th0;
        const float* ph = l ? ph1 : ph0;
        const float* fcw = l ? fcw1 : fcw0;
        const float* fcb = l ? fcb1 : fcb0;

        // ---- qk = xs @ [th;ph]^T -> qk[64][256] (q: cols 0..127, k: 128..255) ----
        ull acc[4][4];
        zero_acc(acc);
        for (int k0 = 0; k0 < ND; k0 += 32) {
            __syncthreads();  // wb free
            stage_w(wb, th, ph, k0, tid);
            __syncthreads();
            gemm_tile(acc, xs, XS_LD, k0, wb, WB_LD, 32, m, c0);
        }
        store_acc(acc, qk, QK_LD, nullptr, m, c0);
        __syncthreads();

        // ---- scores[n][mm] = dot(q[n], k[mm]) / sqrt(128) -> Ab raw ----
        // thread: n = tid>>3 (64 rows), mm = (tid&7) + 8*ci, ci 0..7
        {
            int n = tid >> 3;
            int t7 = tid & 7;
            ull sacc[8];
#pragma unroll
            for (int ci = 0; ci < 8; ci++) sacc[ci] = 0ull;
            for (int kk4 = 0; kk4 < NDH; kk4 += 4) {
                ulonglong2 qv = *(const ulonglong2*)(qk + n * QK_LD + kk4);
#pragma unroll
                for (int ci = 0; ci < 8; ci++) {
                    int mm = t7 + 8 * ci;
                    ulonglong2 kv = *(const ulonglong2*)(qk + mm * QK_LD + 128 + kk4);
                    FMA2(sacc[ci], qv.x, kv.x);
                    FMA2(sacc[ci], qv.y, kv.y);
                }
            }
            const float sscale = 0.08838834764831845f;  // 1/sqrt(128)
#pragma unroll
            for (int ci = 0; ci < 8; ci++) {
                float2 p = unpackf2(sacc[ci]);
                Ab[n * A_LD + t7 + 8 * ci] = (p.x + p.y) * sscale;
            }
        }
        __syncthreads();

        // ---- A_hat = A_static + row_softmax(scores), in place in Ab ----
        {
            const float* Ast = g_Ast + l * 4096;
            for (int n = warp; n < 64; n += 16) {
                float v0 = Ab[n * A_LD + lane];
                float v1 = Ab[n * A_LD + 32 + lane];
                float mx = fmaxf(v0, v1);
#pragma unroll
                for (int off = 16; off > 0; off >>= 1)
                    mx = fmaxf(mx, __shfl_xor_sync(0xffffffffu, mx, off));
                float e0 = __expf(v0 - mx);
                float e1 = __expf(v1 - mx);
                float ss = e0 + e1;
#pragma unroll
                for (int off = 16; off > 0; off >>= 1)
                    ss += __shfl_xor_sync(0xffffffffu, ss, off);
                float inv = 1.0f / ss;
                Ab[n * A_LD + lane] = Ast[n * 64 + lane] + e0 * inv;
                Ab[n * A_LD + 32 + lane] = Ast[n * 64 + 32 + lane] + e1 * inv;
            }
        }
        __syncthreads();

        // ---- agg = A_hat @ xs -> qk buffer (reused) ----
        zero_acc(acc);
        gemm_tile(acc, Ab, A_LD, 0, xs, XS_LD, 64, m, c0);
        store_acc(acc, qk, QK_LD, nullptr, m, c0);
        __syncthreads();

        // ---- fc: out = agg @ fcw^T + fcb ----
        zero_acc(acc);
        for (int k0 = 0; k0 < ND; k0 += 32) {
            __syncthreads();
            stage_w(wb, fcw, fcw + 128 * ND, k0, tid);
            __syncthreads();
            gemm_tile(acc, qk, QK_LD, k0, wb, WB_LD, 32, m, c0);
        }
        if (l == 0) {
            store_acc(acc, xs, XS_LD, fcb, m, c0);
            __syncthreads();
            // LN + LeakyReLU(0.1), in place in xs
            ln_rows(xs, XS_LD, xs, XS_LD, ln0_g, ln0_b, true, tid);
            __syncthreads();
        } else {
            store_acc(acc, out + (size_t)b * NN * ND, ND, fcb, m, c0);
        }
    }
}

extern "C" void kernel_launch(void* const* d_in, const int* in_sizes, int n_in,
                              void* d_out, int out_size)
{
    const float* graph   = (const float*)d_in[0];
    const float* ln_in_g = (const float*)d_in[1];
    const float* ln_in_b = (const float*)d_in[2];
    const float* adj0    = (const float*)d_in[3];
    const float* th0     = (const float*)d_in[4];
    const float* ph0     = (const float*)d_in[5];
    const float* fcw0    = (const float*)d_in[6];
    const float* fcb0    = (const float*)d_in[7];
    const float* ln0_g   = (const float*)d_in[8];
    const float* ln0_b   = (const float*)d_in[9];
    const float* adj1    = (const float*)d_in[10];
    const float* th1     = (const float*)d_in[11];
    const float* ph1     = (const float*)d_in[12];
    const float* fcw1    = (const float*)d_in[13];
    const float* fcb1    = (const float*)d_in[14];
    float* out = (float*)d_out;

    cudaFuncSetAttribute(gconv_kernel,
                         cudaFuncAttributeMaxDynamicSharedMemorySize, SMEM_BYTES);

    adj_softmax_kernel<<<2, 64>>>(adj0, adj1);
    gconv_kernel<<<NB, NT, SMEM_BYTES>>>(
        graph, ln_in_g, ln_in_b,
        th0, ph0, fcw0, fcb0, ln0_g, ln0_b,
        th1, ph1, fcw1, fcb1, out);
}

// round 4
// speedup vs baseline: 1.1253x; 1.0009x over previous
#include <cuda_runtime.h>
#include <cuda_bf16.h>
#include <math.h>

// Problem dims
#define NB 2048
#define NN 64
#define ND 256
#define NDH 128

#define NT 512          // threads per CTA (16 warps)

// smem strides (floats)
#define XS_LD 260   // 64 x 260  (granule step/row = 65, odd -> conflict-free)
#define QK_LD 260
#define A_LD  68    // 64 x 68   (granule step/row = 17, odd)
#define WB_LD 260   // 32 x 260  transposed weight chunk: wb[kk][o]

#define XS_OFF 0
#define QK_OFF (64 * XS_LD)
#define AB_OFF (QK_OFF + 64 * QK_LD)
#define WB_OFF (AB_OFF + 64 * A_LD)
#define SMEM_FLOATS (WB_OFF + 32 * WB_LD)
#define SMEM_BYTES (SMEM_FLOATS * 4)

__device__ float g_Ast[2 * 64 * 64];  // softmax(adj0), softmax(adj1)

typedef unsigned long long ull;

#define FMA2(d, a, b) \
    asm("fma.rn.f32x2 %0, %1, %2, %0;" : "+l"(d) : "l"(a), "l"(b))

__device__ __forceinline__ ull packf2(float a, float b) {
    ull r;
    asm("mov.b64 %0, {%1, %2};" : "=l"(r) : "f"(a), "f"(b));
    return r;
}
__device__ __forceinline__ float2 unpackf2(ull v) {
    float x, y;
    asm("mov.b64 {%0, %1}, %2;" : "=f"(x), "=f"(y) : "l"(v));
    return make_float2(x, y);
}

__device__ __forceinline__ float f4c(const float4& v, int u) {
    switch (u) {
        case 0: return v.x;
        case 1: return v.y;
        case 2: return v.z;
        default: return v.w;
    }
}

// ---------------------------------------------------------------------------
// GEMM tile: OUT[64][256] += A[64][K] * B[K][256]
// Thread (m = lane&15, h = lane>>4, w = warp):
//   rows  r = m + 16*ri  (ri 0..3)          -> conflict-free A loads
//   cols  c = w*16 + h*8 + {0..7}           -> 16-way bcast B loads, 1 wf
// acc[ri][cu] : f32x2 pair of cols (c0+2cu, c0+2cu+1)
// ---------------------------------------------------------------------------
__device__ __forceinline__ void gemm_tile(
    ull acc[4][4],
    const float* __restrict__ As, int lda, int acol0,
    const float* __restrict__ Bs, int ldb, int kcnt,
    int m, int c0)
{
    for (int kk4 = 0; kk4 < kcnt; kk4 += 4) {
        float4 av[4];
#pragma unroll
        for (int ri = 0; ri < 4; ri++)
            av[ri] = *(const float4*)(As + (m + 16 * ri) * lda + acol0 + kk4);
#pragma unroll
        for (int u = 0; u < 4; u++) {
            const float* brow = Bs + (kk4 + u) * ldb + c0;
            ulonglong2 b0 = *(const ulonglong2*)(brow);
            ulonglong2 b1 = *(const ulonglong2*)(brow + 4);
#pragma unroll
            for (int ri = 0; ri < 4; ri++) {
                float a = f4c(av[ri], u);
                ull aa = packf2(a, a);
                FMA2(acc[ri][0], aa, b0.x);
                FMA2(acc[ri][1], aa, b0.y);
                FMA2(acc[ri][2], aa, b1.x);
                FMA2(acc[ri][3], aa, b1.y);
            }
        }
    }
}

__device__ __forceinline__ void zero_acc(ull acc[4][4]) {
#pragma unroll
    for (int ri = 0; ri < 4; ri++)
#pragma unroll
        for (int j = 0; j < 4; j++) acc[ri][j] = 0ull;
}

__device__ __forceinline__ void store_acc(
    ull acc[4][4], float* dst, int ldd,
    const float* __restrict__ bias, int m, int c0)
{
#pragma unroll
    for (int ri = 0; ri < 4; ri++) {
        int r = m + 16 * ri;
#pragma unroll
        for (int f = 0; f < 2; f++) {
            float2 p0 = unpackf2(acc[ri][2 * f]);
            float2 p1 = unpackf2(acc[ri][2 * f + 1]);
            float4 o = make_float4(p0.x, p0.y, p1.x, p1.y);
            int cc = c0 + 4 * f;
            if (bias) {
                float4 bb = *(const float4*)(bias + cc);
                o.x += bb.x; o.y += bb.y; o.z += bb.z; o.w += bb.w;
            }
            *(float4*)(dst + (size_t)r * ldd + cc) = o;
        }
    }
}

// ---------------------------------------------------------------------------
// Stage transposed weight chunk: wb[kk][o] = W[o][k0+kk], kk in [0,32), o in [0,256)
// Lane kk = tid&31 (conflict-free STS.128: granule 65*kk + o/4, 32 distinct),
// LDG: 32 consecutive kk per warp -> 128B coalesced segments.
// ---------------------------------------------------------------------------
__device__ __forceinline__ void stage_w(
    float* __restrict__ wb, const float* __restrict__ w_lo,
    const float* __restrict__ w_hi, int k0, int tid)
{
    int kk = tid & 31;
    int wv = tid >> 5;  // 0..15
#pragma unroll
    for (int it = 0; it < 4; it++) {
        int o0 = wv * 16 + it * 4;
        const float* s = (o0 < 128) ? (w_lo + (size_t)o0 * ND)
                                    : (w_hi + (size_t)(o0 - 128) * ND);
        float4 v;
        v.x = s[0 * ND + k0 + kk];
        v.y = s[1 * ND + k0 + kk];
        v.z = s[2 * ND + k0 + kk];
        v.w = s[3 * ND + k0 + kk];
        *(float4*)(wb + kk * WB_LD + o0) = v;
    }
}

// LayerNorm over D=256 for 64 rows; warp-per-row, 16 warps -> 4 rows/warp.
__device__ __forceinline__ void ln_rows(
    const float* __restrict__ src, int lds,
    float* dst, int ldd,
    const float* __restrict__ gg, const float* __restrict__ bb,
    bool leaky, int tid)
{
    int warp = tid >> 5, lane = tid & 31;
    for (int n = warp; n < 64; n += 16) {
        const float* row = src + (size_t)n * lds;
        float v[8];
        float s = 0.f, sq = 0.f;
#pragma unroll
        for (int i = 0; i < 8; i++) {
            float t = row[lane + 32 * i];
            v[i] = t;
            s += t;
            sq += t * t;
        }
#pragma unroll
        for (int off = 16; off > 0; off >>= 1) {
            s += __shfl_xor_sync(0xffffffffu, s, off);
            sq += __shfl_xor_sync(0xffffffffu, sq, off);
        }
        float mean = s * (1.0f / 256.0f);
        float var = sq * (1.0f / 256.0f) - mean * mean;
        float rstd = rsqrtf(var + 1e-5f);
#pragma unroll
        for (int i = 0; i < 8; i++) {
            int c = lane + 32 * i;
            float o = (v[i] - mean) * rstd * gg[c] + bb[c];
            if (leaky) o = (o >= 0.f) ? o : 0.1f * o;
            dst[(size_t)n * ldd + c] = o;
        }
    }
}

// Precompute softmax of the two static adjacency matrices (row softmax, 64x64).
__global__ void adj_softmax_kernel(const float* __restrict__ adj0,
                                   const float* __restrict__ adj1)
{
    const float* adj = blockIdx.x ? adj1 : adj0;
    float* dst = g_Ast + blockIdx.x * 4096;
    int r = threadIdx.x;  // 64 threads
    const float* row = adj + r * 64;
    float mx = -1e30f;
    for (int m = 0; m < 64; m++) mx = fmaxf(mx, row[m]);
    float s = 0.f;
    for (int m = 0; m < 64; m++) s += __expf(row[m] - mx);
    float inv = 1.0f / s;
    for (int m = 0; m < 64; m++) dst[r * 64 + m] = __expf(row[m] - mx) * inv;
}

__global__ void __launch_bounds__(NT, 1) gconv_kernel(
    const float* __restrict__ graph,
    const float* __restrict__ ln_in_g, const float* __restrict__ ln_in_b,
    const float* __restrict__ th0, const float* __restrict__ ph0,
    const float* __restrict__ fcw0, const float* __restrict__ fcb0,
    const float* __restrict__ ln0_g, const float* __restrict__ ln0_b,
    const float* __restrict__ th1, const float* __restrict__ ph1,
    const float* __restrict__ fcw1, const float* __restrict__ fcb1,
    float* __restrict__ out)
{
    extern __shared__ float sm[];
    float* xs = sm + XS_OFF;
    float* qk = sm + QK_OFF;
    float* Ab = sm + AB_OFF;
    float* wb = sm + WB_OFF;

    int tid = threadIdx.x;
    int warp = tid >> 5, lane = tid & 31;
    int m = lane & 15;              // row group within warp
    int c0 = warp * 16 + (lane >> 4) * 8;  // col base (8 cols per thread)
    int b = blockIdx.x;

    // ---- input LayerNorm: global graph[b] -> xs ----
    ln_rows(graph + (size_t)b * NN * ND, ND, xs, XS_LD, ln_in_g, ln_in_b, false, tid);
    __syncthreads();

#pragma unroll 1
    for (int l = 0; l < 2; l++) {
        const float* th = l ? th1 : th0;
        const float* ph = l ? ph1 : ph0;
        const float* fcw = l ? fcw1 : fcw0;
        const float* fcb = l ? fcb1 : fcb0;

        // ---- qk = xs @ [th;ph]^T -> qk[64][256] (q: cols 0..127, k: 128..255) ----
        ull acc[4][4];
        zero_acc(acc);
        for (int k0 = 0; k0 < ND; k0 += 32) {
            __syncthreads();  // wb free
            stage_w(wb, th, ph, k0, tid);
            __syncthreads();
            gemm_tile(acc, xs, XS_LD, k0, wb, WB_LD, 32, m, c0);
        }
        store_acc(acc, qk, QK_LD, nullptr, m, c0);
        __syncthreads();

        // ---- scores[n][mm] = dot(q[n], k[mm]) / sqrt(128) -> Ab raw ----
        // thread: n = tid>>3 (64 rows), mm = (tid&7) + 8*ci, ci 0..7
        {
            int n = tid >> 3;
            int t7 = tid & 7;
            ull sacc[8];
#pragma unroll
            for (int ci = 0; ci < 8; ci++) sacc[ci] = 0ull;
            for (int kk4 = 0; kk4 < NDH; kk4 += 4) {
                ulonglong2 qv = *(const ulonglong2*)(qk + n * QK_LD + kk4);
#pragma unroll
                for (int ci = 0; ci < 8; ci++) {
                    int mm = t7 + 8 * ci;
                    ulonglong2 kv = *(const ulonglong2*)(qk + mm * QK_LD + 128 + kk4);
                    FMA2(sacc[ci], qv.x, kv.x);
                    FMA2(sacc[ci], qv.y, kv.y);
                }
            }
            const float sscale = 0.08838834764831845f;  // 1/sqrt(128)
#pragma unroll
            for (int ci = 0; ci < 8; ci++) {
                float2 p = unpackf2(sacc[ci]);
                Ab[n * A_LD + t7 + 8 * ci] = (p.x + p.y) * sscale;
            }
        }
        __syncthreads();

        // ---- A_hat = A_static + row_softmax(scores), in place in Ab ----
        {
            const float* Ast = g_Ast + l * 4096;
            for (int n = warp; n < 64; n += 16) {
                float v0 = Ab[n * A_LD + lane];
                float v1 = Ab[n * A_LD + 32 + lane];
                float mx = fmaxf(v0, v1);
#pragma unroll
                for (int off = 16; off > 0; off >>= 1)
                    mx = fmaxf(mx, __shfl_xor_sync(0xffffffffu, mx, off));
                float e0 = __expf(v0 - mx);
                float e1 = __expf(v1 - mx);
                float ss = e0 + e1;
#pragma unroll
                for (int off = 16; off > 0; off >>= 1)
                    ss += __shfl_xor_sync(0xffffffffu, ss, off);
                float inv = 1.0f / ss;
                Ab[n * A_LD + lane] = Ast[n * 64 + lane] + e0 * inv;
                Ab[n * A_LD + 32 + lane] = Ast[n * 64 + 32 + lane] + e1 * inv;
            }
        }
        __syncthreads();

        // ---- agg = A_hat @ xs -> qk buffer (reused) ----
        zero_acc(acc);
        gemm_tile(acc, Ab, A_LD, 0, xs, XS_LD, 64, m, c0);
        store_acc(acc, qk, QK_LD, nullptr, m, c0);
        __syncthreads();

        // ---- fc: out = agg @ fcw^T + fcb ----
        zero_acc(acc);
        for (int k0 = 0; k0 < ND; k0 += 32) {
            __syncthreads();
            stage_w(wb, fcw, fcw + 128 * ND, k0, tid);
            __syncthreads();
            gemm_tile(acc, qk, QK_LD, k0, wb, WB_LD, 32, m, c0);
        }
        if (l == 0) {
            store_acc(acc, xs, XS_LD, fcb, m, c0);
            __syncthreads();
            // LN + LeakyReLU(0.1), in place in xs
            ln_rows(xs, XS_LD, xs, XS_LD, ln0_g, ln0_b, true, tid);
            __syncthreads();
        } else {
            store_acc(acc, out + (size_t)b * NN * ND, ND, fcb, m, c0);
        }
    }
}

extern "C" void kernel_launch(void* const* d_in, const int* in_sizes, int n_in,
                              void* d_out, int out_size)
{
    const float* graph   = (const float*)d_in[0];
    const float* ln_in_g = (const float*)d_in[1];
    const float* ln_in_b = (const float*)d_in[2];
    const float* adj0    = (const float*)d_in[3];
    const float* th0     = (const float*)d_in[4];
    const float* ph0     = (const float*)d_in[5];
    const float* fcw0    = (const float*)d_in[6];
    const float* fcb0    = (const float*)d_in[7];
    const float* ln0_g   = (const float*)d_in[8];
    const float* ln0_b   = (const float*)d_in[9];
    const float* adj1    = (const float*)d_in[10];
    const float* th1     = (const float*)d_in[11];
    const float* ph1     = (const float*)d_in[12];
    const float* fcw1    = (const float*)d_in[13];
    const float* fcb1    = (const float*)d_in[14];
    float* out = (float*)d_out;

    cudaFuncSetAttribute(gconv_kernel,
                         cudaFuncAttributeMaxDynamicSharedMemorySize, SMEM_BYTES);

    adj_softmax_kernel<<<2, 64>>>(adj0, adj1);
    gconv_kernel<<<NB, NT, SMEM_BYTES>>>(
        graph, ln_in_g, ln_in_b,
        th0, ph0, fcw0, fcb0, ln0_g, ln0_b,
        th1, ph1, fcw1, fcb1, out);
}

// round 6
// speedup vs baseline: 2.3306x; 2.0710x over previous
#include <cuda_runtime.h>
#include <cuda_bf16.h>
#include <math.h>

#define NB 2048
#define NT 512

typedef unsigned long long ull;
typedef unsigned int u32;
typedef unsigned short u16;

// element strides
#define X_LD 264     // bf16 tiles [64][264]
#define QK_LD 264
#define ABF_LD 68    // fp32 scores
#define AB_LD 72     // bf16 A_hat tiles
#define W_LD 40      // bf16 weight chunk [256][40]
#define FC_LD 260    // fp32 fc-out

// smem byte offsets
#define XH_OFF 0
#define XL_OFF 33792
#define QKH_OFF 67584
#define QKL_OFF 101376
#define ABF_OFF 67584        // alias QK region (live only after scores read QK)
#define ABH_OFF 84992
#define ABL_OFF 94208
#define WB_OFF 135168        // 2 bufs x (20480 hi + 20480 lo) = 81920
#define FC_OFF 135168        // alias WBUF (live only after fc GEMM done)
#define SMEM_BYTES 217088

__device__ float g_Ast[2 * 64 * 64];
__device__ __nv_bfloat16 g_W[2][2][2][65536];  // [layer][qk|fc][hi|lo][o*256 + k]

// ---------------- PTX wrappers ----------------
__device__ __forceinline__ u32 smem_u32(const void* p) {
    u32 a;
    asm("{ .reg .u64 t; cvta.to.shared.u64 t, %1; cvt.u32.u64 %0, t; }" : "=r"(a) : "l"(p));
    return a;
}
__device__ __forceinline__ void ldmx4(u32 a, u32 r[4]) {
    asm volatile("ldmatrix.sync.aligned.m8n8.x4.shared.b16 {%0,%1,%2,%3}, [%4];"
                 : "=r"(r[0]), "=r"(r[1]), "=r"(r[2]), "=r"(r[3]) : "r"(a));
}
__device__ __forceinline__ void ldmx4t(u32 a, u32 r[4]) {
    asm volatile("ldmatrix.sync.aligned.m8n8.x4.trans.shared.b16 {%0,%1,%2,%3}, [%4];"
                 : "=r"(r[0]), "=r"(r[1]), "=r"(r[2]), "=r"(r[3]) : "r"(a));
}
__device__ __forceinline__ void mma16816(float d[4], const u32 a[4], u32 b0, u32 b1) {
    asm volatile("mma.sync.aligned.m16n8k16.row.col.f32.bf16.bf16.f32 "
                 "{%0,%1,%2,%3}, {%4,%5,%6,%7}, {%8,%9}, {%0,%1,%2,%3};"
                 : "+f"(d[0]), "+f"(d[1]), "+f"(d[2]), "+f"(d[3])
                 : "r"(a[0]), "r"(a[1]), "r"(a[2]), "r"(a[3]), "r"(b0), "r"(b1));
}
#define CP16(s, g) asm volatile("cp.async.cg.shared.global [%0], [%1], 16;" :: "r"(s), "l"(g))
#define CPCOMMIT() asm volatile("cp.async.commit_group;" ::: "memory")
#define CPWAIT1() asm volatile("cp.async.wait_group 1;" ::: "memory")
#define CPWAIT0() asm volatile("cp.async.wait_group 0;" ::: "memory")

__device__ __forceinline__ u32 pack_hi2(float v0, float v1) {
    __nv_bfloat16 h0 = __float2bfloat16(v0), h1 = __float2bfloat16(v1);
    return (u32)__bfloat16_as_ushort(h0) | ((u32)__bfloat16_as_ushort(h1) << 16);
}
__device__ __forceinline__ u32 pack_lo2(float v0, float v1) {
    __nv_bfloat16 h0 = __float2bfloat16(v0), h1 = __float2bfloat16(v1);
    __nv_bfloat16 l0 = __float2bfloat16(v0 - __bfloat162float(h0));
    __nv_bfloat16 l1 = __float2bfloat16(v1 - __bfloat162float(h1));
    return (u32)__bfloat16_as_ushort(l0) | ((u32)__bfloat16_as_ushort(l1) << 16);
}

// ---------------- weight GEMM (qk / fc): C[64 n][256 o] ----------------
// A = X tiles (non-trans ldmatrix), B = W[o][k] row-major (= B^T, non-trans ldmatrix).
// K=256 streamed in 8 chunks of 32 via double-buffered cp.async.
__device__ __forceinline__ void wgemm_tc(
    char* smc, u32 smb,
    const __nv_bfloat16* __restrict__ wH, const __nv_bfloat16* __restrict__ wL,
    u32 xh_off, u32 xl_off,
    float cacc[8][4], int warp, int lane, int tid)
{
    int n0 = (warp & 3) * 16;
    int o0 = (warp >> 2) * 64;
#pragma unroll
    for (int t = 0; t < 8; t++)
#pragma unroll
        for (int j = 0; j < 4; j++) cacc[t][j] = 0.f;

    int arow = n0 + (lane & 15);
    int acolsel = 8 * (lane >> 4);
    int brow_local = (lane & 7) + 8 * ((lane >> 4) & 1);
    int bksel = 8 * ((lane >> 3) & 1);

    // stage chunk 0 -> buf 0
#pragma unroll
    for (int j = 0; j < 4; j++) {
        int idx = tid + j * NT;
        int part = idx >> 10, r = (idx >> 2) & 255, seg = idx & 3;
        const __nv_bfloat16* src = (part ? wL : wH) + r * 256 + seg * 8;
        CP16(smb + WB_OFF + part * 20480 + r * 80 + seg * 16, src);
    }
    CPCOMMIT();

#pragma unroll 1
    for (int c = 0; c < 8; c++) {
        if (c < 7) {
#pragma unroll
            for (int j = 0; j < 4; j++) {
                int idx = tid + j * NT;
                int part = idx >> 10, r = (idx >> 2) & 255, seg = idx & 3;
                const __nv_bfloat16* src = (part ? wL : wH) + r * 256 + (c + 1) * 32 + seg * 8;
                CP16(smb + WB_OFF + ((c + 1) & 1) * 40960 + part * 20480 + r * 80 + seg * 16, src);
            }
            CPCOMMIT();
            CPWAIT1();
        } else {
            CPWAIT0();
        }
        __syncthreads();
        u32 wb = smb + WB_OFF + (c & 1) * 40960;
#pragma unroll
        for (int ks = 0; ks < 2; ks++) {
            int kg = c * 32 + ks * 16;
            u32 ah[4], al[4];
            ldmx4(smb + xh_off + (u32)(arow * X_LD + kg + acolsel) * 2, ah);
            ldmx4(smb + xl_off + (u32)(arow * X_LD + kg + acolsel) * 2, al);
#pragma unroll
            for (int p = 0; p < 4; p++) {
                int orow = o0 + p * 16 + brow_local;
                int kloc = ks * 16 + bksel;
                u32 bh[4], bl[4];
                ldmx4(wb + (u32)(orow * W_LD + kloc) * 2, bh);
                ldmx4(wb + 20480u + (u32)(orow * W_LD + kloc) * 2, bl);
                mma16816(cacc[2 * p], ah, bh[0], bh[1]);
                mma16816(cacc[2 * p], ah, bl[0], bl[1]);
                mma16816(cacc[2 * p], al, bh[0], bh[1]);
                mma16816(cacc[2 * p + 1], ah, bh[2], bh[3]);
                mma16816(cacc[2 * p + 1], ah, bl[2], bl[3]);
                mma16816(cacc[2 * p + 1], al, bh[2], bh[3]);
            }
        }
        __syncthreads();
    }
}

// write C frags as bf16 hi/lo split tiles
__device__ __forceinline__ void store_split_frag(
    char* smc, const float cacc[8][4], int n0, int o0,
    u32 hoff, u32 loff, int ld, int lane)
{
    int r = n0 + (lane >> 2);
    int cbase = o0 + 2 * (lane & 3);
#pragma unroll
    for (int t = 0; t < 8; t++) {
        int col = cbase + t * 8;
#pragma unroll
        for (int rr = 0; rr < 2; rr++) {
            float v0 = cacc[t][rr * 2], v1 = cacc[t][rr * 2 + 1];
            u32 off = (u32)((r + rr * 8) * ld + col) * 2;
            *(u32*)(smc + hoff + off) = pack_hi2(v0, v1);
            *(u32*)(smc + loff + off) = pack_lo2(v0, v1);
        }
    }
}

// ---------------- scores: C[64 n][64 m] = q @ k^T ----------------
__device__ __forceinline__ void scores_tc(char* smc, u32 smb, float sacc[2][4],
                                          int warp, int lane)
{
    int n0 = (warp & 3) * 16;
    int m0 = (warp >> 2) * 16;
#pragma unroll
    for (int t = 0; t < 2; t++)
#pragma unroll
        for (int j = 0; j < 4; j++) sacc[t][j] = 0.f;
    int arow = n0 + (lane & 15);
    int acolsel = 8 * (lane >> 4);
    int brow = m0 + (lane & 7) + 8 * ((lane >> 4) & 1);
    int bksel = 8 * ((lane >> 3) & 1);
#pragma unroll
    for (int ks = 0; ks < 8; ks++) {
        int kg = ks * 16;
        u32 ah[4], al[4], bh[4], bl[4];
        ldmx4(smb + QKH_OFF + (u32)(arow * QK_LD + kg + acolsel) * 2, ah);
        ldmx4(smb + QKL_OFF + (u32)(arow * QK_LD + kg + acolsel) * 2, al);
        ldmx4(smb + QKH_OFF + (u32)(brow * QK_LD + 128 + kg + bksel) * 2, bh);
        ldmx4(smb + QKL_OFF + (u32)(brow * QK_LD + 128 + kg + bksel) * 2, bl);
        mma16816(sacc[0], ah, bh[0], bh[1]);
        mma16816(sacc[0], ah, bl[0], bl[1]);
        mma16816(sacc[0], al, bh[0], bh[1]);
        mma16816(sacc[1], ah, bh[2], bh[3]);
        mma16816(sacc[1], ah, bl[2], bl[3]);
        mma16816(sacc[1], al, bh[2], bh[3]);
    }
}

// ---------------- agg: C[64 n][256 d] = A_hat @ X ----------------
__device__ __forceinline__ void agg_tc(char* smc, u32 smb, float cacc[8][4],
                                       int warp, int lane)
{
    int n0 = (warp & 3) * 16;
    int d0 = (warp >> 2) * 64;
#pragma unroll
    for (int t = 0; t < 8; t++)
#pragma unroll
        for (int j = 0; j < 4; j++) cacc[t][j] = 0.f;
    int arow = n0 + (lane & 15);
    int acolsel = 8 * (lane >> 4);
    int xrow = lane & 15;
    int xcol = 8 * (lane >> 4);
#pragma unroll
    for (int ks = 0; ks < 4; ks++) {
        int kg = ks * 16;
        u32 ah[4], al[4];
        ldmx4(smb + ABH_OFF + (u32)(arow * AB_LD + kg + acolsel) * 2, ah);
        ldmx4(smb + ABL_OFF + (u32)(arow * AB_LD + kg + acolsel) * 2, al);
#pragma unroll
        for (int p = 0; p < 4; p++) {
            int xr = kg + xrow;
            int xc = d0 + p * 16 + xcol;
            u32 bh[4], bl[4];
            ldmx4t(smb + XH_OFF + (u32)(xr * X_LD + xc) * 2, bh);
            ldmx4t(smb + XL_OFF + (u32)(xr * X_LD + xc) * 2, bl);
            mma16816(cacc[2 * p], ah, bh[0], bh[1]);
            mma16816(cacc[2 * p], ah, bl[0], bl[1]);
            mma16816(cacc[2 * p], al, bh[0], bh[1]);
            mma16816(cacc[2 * p + 1], ah, bh[2], bh[3]);
            mma16816(cacc[2 * p + 1], ah, bl[2], bl[3]);
            mma16816(cacc[2 * p + 1], al, bh[2], bh[3]);
        }
    }
}

// ---------------- LayerNorm -> split bf16 X tiles ----------------
__device__ __forceinline__ void ln_split(
    char* smc, const float* __restrict__ src, int lds, const float* __restrict__ bias,
    const float* __restrict__ gg, const float* __restrict__ bb, bool leaky, int tid)
{
    int warp = tid >> 5, lane = tid & 31;
    for (int n = warp; n < 64; n += 16) {
        const float* row = src + (size_t)n * lds;
        float v[8];
        float s = 0.f, sq = 0.f;
#pragma unroll
        for (int i = 0; i < 4; i++) {
            int c = 2 * lane + 64 * i;
            float2 t = *(const float2*)(row + c);
            if (bias) {
                float2 bv = *(const float2*)(bias + c);
                t.x += bv.x; t.y += bv.y;
            }
            v[2 * i] = t.x; v[2 * i + 1] = t.y;
            s += t.x + t.y;
            sq += t.x * t.x + t.y * t.y;
        }
#pragma unroll
        for (int off = 16; off > 0; off >>= 1) {
            s += __shfl_xor_sync(0xffffffffu, s, off);
            sq += __shfl_xor_sync(0xffffffffu, sq, off);
        }
        float mean = s * (1.0f / 256.0f);
        float var = sq * (1.0f / 256.0f) - mean * mean;
        float rstd = rsqrtf(var + 1e-5f);
#pragma unroll
        for (int i = 0; i < 4; i++) {
            int c = 2 * lane + 64 * i;
            float o0 = (v[2 * i] - mean) * rstd * gg[c] + bb[c];
            float o1 = (v[2 * i + 1] - mean) * rstd * gg[c + 1] + bb[c + 1];
            if (leaky) {
                o0 = (o0 >= 0.f) ? o0 : 0.1f * o0;
                o1 = (o1 >= 0.f) ? o1 : 0.1f * o1;
            }
            u32 off2 = (u32)(n * X_LD + c) * 2;
            *(u32*)(smc + XH_OFF + off2) = pack_hi2(o0, o1);
            *(u32*)(smc + XL_OFF + off2) = pack_lo2(o0, o1);
        }
    }
}

// ---------------- prologue kernels ----------------
__global__ void adj_softmax_kernel(const float* __restrict__ adj0,
                                   const float* __restrict__ adj1)
{
    const float* adj = blockIdx.x ? adj1 : adj0;
    float* dst = g_Ast + blockIdx.x * 4096;
    int r = threadIdx.x;
    const float* row = adj + r * 64;
    float mx = -1e30f;
    for (int m = 0; m < 64; m++) mx = fmaxf(mx, row[m]);
    float s = 0.f;
    for (int m = 0; m < 64; m++) s += __expf(row[m] - mx);
    float inv = 1.0f / s;
    for (int m = 0; m < 64; m++) dst[r * 64 + m] = __expf(row[m] - mx) * inv;
}

__global__ void prep_weights(
    const float* __restrict__ th0, const float* __restrict__ ph0, const float* __restrict__ fcw0,
    const float* __restrict__ th1, const float* __restrict__ ph1, const float* __restrict__ fcw1)
{
    int idx = blockIdx.x * blockDim.x + threadIdx.x;  // 0..262143
    int k = idx & 255, r = (idx >> 8) & 255, g = (idx >> 16) & 1, l = idx >> 17;
    const float* th = l ? th1 : th0;
    const float* pw = l ? ph1 : ph0;
    const float* fw = l ? fcw1 : fcw0;
    float v;
    if (g == 0) v = (r < 128) ? th[r * 256 + k] : pw[(r - 128) * 256 + k];
    else        v = fw[r * 256 + k];
    __nv_bfloat16 hb = __float2bfloat16(v);
    __nv_bfloat16 lb = __float2bfloat16(v - __bfloat162float(hb));
    g_W[l][g][0][r * 256 + k] = hb;
    g_W[l][g][1][r * 256 + k] = lb;
}

// ---------------- main kernel ----------------
__global__ void __launch_bounds__(NT, 1) gconv_kernel(
    const float* __restrict__ graph,
    const float* __restrict__ ln_in_g, const float* __restrict__ ln_in_b,
    const float* __restrict__ fcb0,
    const float* __restrict__ ln0_g, const float* __restrict__ ln0_b,
    const float* __restrict__ fcb1,
    float* __restrict__ out)
{
    extern __shared__ char smc[];
    u32 smb = smem_u32(smc);
    int tid = threadIdx.x;
    int warp = tid >> 5, lane = tid & 31;
    int b = blockIdx.x;
    int n0 = (warp & 3) * 16;
    int o0 = (warp >> 2) * 64;

    // input LN + split
    ln_split(smc, graph + (size_t)b * 64 * 256, 256, nullptr, ln_in_g, ln_in_b, false, tid);
    __syncthreads();

    float cacc[8][4];

#pragma unroll 1
    for (int l = 0; l < 2; l++) {
        // ---- qk = X @ W_qk^T ----
        wgemm_tc(smc, smb, g_W[l][0][0], g_W[l][0][1], XH_OFF, XL_OFF, cacc, warp, lane, tid);
        store_split_frag(smc, cacc, n0, o0, QKH_OFF, QKL_OFF, QK_LD, lane);
        __syncthreads();

        // ---- scores = q @ k^T / sqrt(128) ----
        {
            float sacc[2][4];
            scores_tc(smc, smb, sacc, warp, lane);
            __syncthreads();  // QK reads done before aliasing writes to ABF
            const float sscale = 0.08838834764831845f;
            float* abf = (float*)(smc + ABF_OFF);
            int m0 = (warp >> 2) * 16;
            int r = n0 + (lane >> 2);
            int cb = m0 + 2 * (lane & 3);
#pragma unroll
            for (int t = 0; t < 2; t++) {
#pragma unroll
                for (int rr = 0; rr < 2; rr++) {
                    float2 p;
                    p.x = sacc[t][rr * 2] * sscale;
                    p.y = sacc[t][rr * 2 + 1] * sscale;
                    *(float2*)(abf + (r + rr * 8) * ABF_LD + cb + t * 8) = p;
                }
            }
        }
        __syncthreads();

        // ---- A_hat = Ast + softmax(scores) -> split tiles ----
        {
            const float* Ast = g_Ast + l * 4096;
            float* abf = (float*)(smc + ABF_OFF);
            for (int n = warp; n < 64; n += 16) {
                float v0 = abf[n * ABF_LD + lane];
                float v1 = abf[n * ABF_LD + 32 + lane];
                float mx = fmaxf(v0, v1);
#pragma unroll
                for (int off = 16; off > 0; off >>= 1)
                    mx = fmaxf(mx, __shfl_xor_sync(0xffffffffu, mx, off));
                float e0 = __expf(v0 - mx);
                float e1 = __expf(v1 - mx);
                float ss = e0 + e1;
#pragma unroll
                for (int off = 16; off > 0; off >>= 1)
                    ss += __shfl_xor_sync(0xffffffffu, ss, off);
                float inv = 1.0f / ss;
                float a0 = Ast[n * 64 + lane] + e0 * inv;
                float a1 = Ast[n * 64 + 32 + lane] + e1 * inv;
                __nv_bfloat16 h0 = __float2bfloat16(a0);
                __nv_bfloat16 h1 = __float2bfloat16(a1);
                u16* abh = (u16*)(smc + ABH_OFF);
                u16* abl = (u16*)(smc + ABL_OFF);
                abh[n * AB_LD + lane]      = __bfloat16_as_ushort(h0);
                abh[n * AB_LD + 32 + lane] = __bfloat16_as_ushort(h1);
                abl[n * AB_LD + lane] =
                    __bfloat16_as_ushort(__float2bfloat16(a0 - __bfloat162float(h0)));
                abl[n * AB_LD + 32 + lane] =
                    __bfloat16_as_ushort(__float2bfloat16(a1 - __bfloat162float(h1)));
            }
        }
        __syncthreads();

        // ---- agg = A_hat @ X -> overwrite X tiles ----
        agg_tc(smc, smb, cacc, warp, lane);
        __syncthreads();  // all X reads done before overwrite
        store_split_frag(smc, cacc, n0, o0, XH_OFF, XL_OFF, X_LD, lane);
        __syncthreads();

        // ---- fc = agg @ W_fc^T -> fp32 (FC region aliases WBUF) ----
        wgemm_tc(smc, smb, g_W[l][1][0], g_W[l][1][1], XH_OFF, XL_OFF, cacc, warp, lane, tid);
        {
            float* fco = (float*)(smc + FC_OFF);
            int r = n0 + (lane >> 2);
            int cb = o0 + 2 * (lane & 3);
#pragma unroll
            for (int t = 0; t < 8; t++) {
#pragma unroll
                for (int rr = 0; rr < 2; rr++) {
                    float2 p;
                    p.x = cacc[t][rr * 2];
                    p.y = cacc[t][rr * 2 + 1];
                    *(float2*)(fco + (r + rr * 8) * FC_LD + cb + t * 8) = p;
                }
            }
        }
        __syncthreads();

        if (l == 0) {
            // LN(fc + bias) + leaky -> new X tiles
            ln_split(smc, (float*)(smc + FC_OFF), FC_LD, fcb0, ln0_g, ln0_b, true, tid);
            __syncthreads();
        } else {
            // fc + bias -> global out
            const float* fco = (const float*)(smc + FC_OFF);
            float* og = out + (size_t)b * 64 * 256;
            for (int i = tid; i < 64 * 64; i += NT) {
                int rr = i >> 6, c4 = (i & 63) * 4;
                float4 v = *(const float4*)(fco + rr * FC_LD + c4);
                float4 bb = *(const float4*)(fcb1 + c4);
                v.x += bb.x; v.y += bb.y; v.z += bb.z; v.w += bb.w;
                *(float4*)(og + rr * 256 + c4) = v;
            }
        }
    }
}

extern "C" void kernel_launch(void* const* d_in, const int* in_sizes, int n_in,
                              void* d_out, int out_size)
{
    const float* graph   = (const float*)d_in[0];
    const float* ln_in_g = (const float*)d_in[1];
    const float* ln_in_b = (const float*)d_in[2];
    const float* adj0    = (const float*)d_in[3];
    const float* th0     = (const float*)d_in[4];
    const float* ph0     = (const float*)d_in[5];
    const float* fcw0    = (const float*)d_in[6];
    const float* fcb0    = (const float*)d_in[7];
    const float* ln0_g   = (const float*)d_in[8];
    const float* ln0_b   = (const float*)d_in[9];
    const float* adj1    = (const float*)d_in[10];
    const float* th1     = (const float*)d_in[11];
    const float* ph1     = (const float*)d_in[12];
    const float* fcw1    = (const float*)d_in[13];
    const float* fcb1    = (const float*)d_in[14];
    float* out = (float*)d_out;

    cudaFuncSetAttribute(gconv_kernel,
                         cudaFuncAttributeMaxDynamicSharedMemorySize, SMEM_BYTES);

    adj_softmax_kernel<<<2, 64>>>(adj0, adj1);
    prep_weights<<<512, 512>>>(th0, ph0, fcw0, th1, ph1, fcw1);
    gconv_kernel<<<NB, NT, SMEM_BYTES>>>(
        graph, ln_in_g, ln_in_b, fcb0, ln0_g, ln0_b, fcb1, out);
}

// round 7
// speedup vs baseline: 3.3379x; 1.4322x over previous
#include <cuda_runtime.h>
#include <cuda_bf16.h>
#include <math.h>

#define NB 2048
#define NT 512

typedef unsigned long long ull;
typedef unsigned int u32;
typedef unsigned short u16;

// element strides
#define X_LD 264     // bf16 tiles [64][264]
#define QK_LD 264
#define ABF_LD 68    // fp32 scores
#define AB_LD 72     // bf16 A_hat tiles
#define FC_LD 260    // fp32 fc-out

// smem byte offsets
#define XH_OFF 0
#define XL_OFF 33792
#define QKH_OFF 67584
#define QKL_OFF 101376
#define ABH_OFF 135168
#define ABL_OFF 144384
#define ABF_OFF 153600
#define FC_OFF 67584         // alias QK region (dead after scores)
#define SMEM_BYTES 171008

__device__ float g_Ast[2 * 64 * 64];
// fragment-packed weights: [layer][qk|fc][hi|lo], 131072 B each.
// index: (((o8*8 + kp)*32 + lane)*4 + slot) u32s; slot = (kstep&1)*2 + wsel.
__device__ uint4 g_Wf[2][2][2][8192];

// ---------------- PTX wrappers ----------------
__device__ __forceinline__ u32 smem_u32(const void* p) {
    u32 a;
    asm("{ .reg .u64 t; cvta.to.shared.u64 t, %1; cvt.u32.u64 %0, t; }" : "=r"(a) : "l"(p));
    return a;
}
__device__ __forceinline__ void ldmx4(u32 a, u32 r[4]) {
    asm volatile("ldmatrix.sync.aligned.m8n8.x4.shared.b16 {%0,%1,%2,%3}, [%4];"
                 : "=r"(r[0]), "=r"(r[1]), "=r"(r[2]), "=r"(r[3]) : "r"(a));
}
__device__ __forceinline__ void ldmx4t(u32 a, u32 r[4]) {
    asm volatile("ldmatrix.sync.aligned.m8n8.x4.trans.shared.b16 {%0,%1,%2,%3}, [%4];"
                 : "=r"(r[0]), "=r"(r[1]), "=r"(r[2]), "=r"(r[3]) : "r"(a));
}
__device__ __forceinline__ void mma16816(float d[4], const u32 a[4], u32 b0, u32 b1) {
    asm volatile("mma.sync.aligned.m16n8k16.row.col.f32.bf16.bf16.f32 "
                 "{%0,%1,%2,%3}, {%4,%5,%6,%7}, {%8,%9}, {%0,%1,%2,%3};"
                 : "+f"(d[0]), "+f"(d[1]), "+f"(d[2]), "+f"(d[3])
                 : "r"(a[0]), "r"(a[1]), "r"(a[2]), "r"(a[3]), "r"(b0), "r"(b1));
}

__device__ __forceinline__ u32 pack_hi2(float v0, float v1) {
    __nv_bfloat16 h0 = __float2bfloat16(v0), h1 = __float2bfloat16(v1);
    return (u32)__bfloat16_as_ushort(h0) | ((u32)__bfloat16_as_ushort(h1) << 16);
}
__device__ __forceinline__ u32 pack_lo2(float v0, float v1) {
    __nv_bfloat16 h0 = __float2bfloat16(v0), h1 = __float2bfloat16(v1);
    __nv_bfloat16 l0 = __float2bfloat16(v0 - __bfloat162float(h0));
    __nv_bfloat16 l1 = __float2bfloat16(v1 - __bfloat162float(h1));
    return (u32)__bfloat16_as_ushort(l0) | ((u32)__bfloat16_as_ushort(l1) << 16);
}

// ---------------- weight GEMM: C[64 n][256 o], warp tile 64n x 16o ----------------
// A = X tiles from smem (ldmatrix); B = fragment-packed weights direct from global.
__device__ __forceinline__ void wgemm_reg(
    u32 smb, u32 xh_off, u32 xl_off,
    const uint4* __restrict__ wH, const uint4* __restrict__ wL,
    float acc[4][2][4], int warp, int lane)
{
#pragma unroll
    for (int nf = 0; nf < 4; nf++)
#pragma unroll
        for (int o = 0; o < 2; o++)
#pragma unroll
            for (int j = 0; j < 4; j++) acc[nf][o][j] = 0.f;

    int arow = lane & 15;
    int acol = 8 * (lane >> 4);
    // frag index base for (o8 = warp*2 + o8i, kp): ((o8*8 + kp)*32 + lane)
    u32 fbase0 = (u32)(((warp * 2 + 0) * 8) * 32 + lane);
    u32 fbase1 = (u32)(((warp * 2 + 1) * 8) * 32 + lane);

    uint4 bh[2], bl[2];
    bh[0] = wH[fbase0]; bh[1] = wH[fbase1];
    bl[0] = wL[fbase0]; bl[1] = wL[fbase1];

#pragma unroll
    for (int kp = 0; kp < 8; kp++) {
        uint4 nh[2], nl[2];
        if (kp < 7) {
            nh[0] = wH[fbase0 + (kp + 1) * 32]; nh[1] = wH[fbase1 + (kp + 1) * 32];
            nl[0] = wL[fbase0 + (kp + 1) * 32]; nl[1] = wL[fbase1 + (kp + 1) * 32];
        }
#pragma unroll
        for (int ks = 0; ks < 2; ks++) {
            int kg = (kp * 2 + ks) * 16;
#pragma unroll
            for (int nf = 0; nf < 4; nf++) {
                u32 ah[4], al[4];
                u32 aoff = (u32)((nf * 16 + arow) * X_LD + kg + acol) * 2;
                ldmx4(smb + xh_off + aoff, ah);
                ldmx4(smb + xl_off + aoff, al);
#pragma unroll
                for (int o = 0; o < 2; o++) {
                    u32 b0h = ks ? bh[o].z : bh[o].x;
                    u32 b1h = ks ? bh[o].w : bh[o].y;
                    u32 b0l = ks ? bl[o].z : bl[o].x;
                    u32 b1l = ks ? bl[o].w : bl[o].y;
                    mma16816(acc[nf][o], ah, b0h, b1h);
                    mma16816(acc[nf][o], ah, b0l, b1l);
                    mma16816(acc[nf][o], al, b0h, b1h);
                }
            }
        }
        if (kp < 7) {
            bh[0] = nh[0]; bh[1] = nh[1];
            bl[0] = nl[0]; bl[1] = nl[1];
        }
    }
}

// store wgemm acc as bf16 hi/lo split tiles (qk epilogue)
__device__ __forceinline__ void wstore_split(
    char* smc, const float acc[4][2][4], u32 hoff, u32 loff, int ld, int warp, int lane)
{
    int rb = lane >> 2;
    int cb = warp * 16 + 2 * (lane & 3);
#pragma unroll
    for (int nf = 0; nf < 4; nf++)
#pragma unroll
        for (int o = 0; o < 2; o++)
#pragma unroll
            for (int rr = 0; rr < 2; rr++) {
                int r = nf * 16 + rb + rr * 8;
                int c = cb + o * 8;
                u32 off = (u32)(r * ld + c) * 2;
                float v0 = acc[nf][o][rr * 2], v1 = acc[nf][o][rr * 2 + 1];
                *(u32*)(smc + hoff + off) = pack_hi2(v0, v1);
                *(u32*)(smc + loff + off) = pack_lo2(v0, v1);
            }
}

// store wgemm acc as fp32 (fc epilogue)
__device__ __forceinline__ void wstore_f32(
    char* smc, const float acc[4][2][4], u32 foff, int ld, int warp, int lane)
{
    float* f = (float*)(smc + foff);
    int rb = lane >> 2;
    int cb = warp * 16 + 2 * (lane & 3);
#pragma unroll
    for (int nf = 0; nf < 4; nf++)
#pragma unroll
        for (int o = 0; o < 2; o++)
#pragma unroll
            for (int rr = 0; rr < 2; rr++) {
                int r = nf * 16 + rb + rr * 8;
                int c = cb + o * 8;
                float2 p = make_float2(acc[nf][o][rr * 2], acc[nf][o][rr * 2 + 1]);
                *(float2*)(f + r * ld + c) = p;
            }
}

// ---------------- scores: C[64 n][64 m] = q @ k^T (hi/lo split) ----------------
__device__ __forceinline__ void scores_tc(u32 smb, float sacc[2][4], int warp, int lane)
{
    int n0 = (warp & 3) * 16;
    int m0 = (warp >> 2) * 16;
#pragma unroll
    for (int t = 0; t < 2; t++)
#pragma unroll
        for (int j = 0; j < 4; j++) sacc[t][j] = 0.f;
    int arow = n0 + (lane & 15);
    int acolsel = 8 * (lane >> 4);
    int brow = m0 + (lane & 7) + 8 * ((lane >> 4) & 1);
    int bksel = 8 * ((lane >> 3) & 1);
#pragma unroll
    for (int ks = 0; ks < 8; ks++) {
        int kg = ks * 16;
        u32 ah[4], al[4], bh[4], bl[4];
        ldmx4(smb + QKH_OFF + (u32)(arow * QK_LD + kg + acolsel) * 2, ah);
        ldmx4(smb + QKL_OFF + (u32)(arow * QK_LD + kg + acolsel) * 2, al);
        ldmx4(smb + QKH_OFF + (u32)(brow * QK_LD + 128 + kg + bksel) * 2, bh);
        ldmx4(smb + QKL_OFF + (u32)(brow * QK_LD + 128 + kg + bksel) * 2, bl);
        mma16816(sacc[0], ah, bh[0], bh[1]);
        mma16816(sacc[0], ah, bl[0], bl[1]);
        mma16816(sacc[0], al, bh[0], bh[1]);
        mma16816(sacc[1], ah, bh[2], bh[3]);
        mma16816(sacc[1], ah, bl[2], bl[3]);
        mma16816(sacc[1], al, bh[2], bh[3]);
    }
}

// ---------------- agg: C[64 n][256 d] = A_hat @ X ----------------
__device__ __forceinline__ void agg_tc(char* smc, u32 smb, float cacc[8][4],
                                       int warp, int lane)
{
    int n0 = (warp & 3) * 16;
    int d0 = (warp >> 2) * 64;
#pragma unroll
    for (int t = 0; t < 8; t++)
#pragma unroll
        for (int j = 0; j < 4; j++) cacc[t][j] = 0.f;
    int arow = n0 + (lane & 15);
    int acolsel = 8 * (lane >> 4);
    int xrow = lane & 15;
    int xcol = 8 * (lane >> 4);
#pragma unroll
    for (int ks = 0; ks < 4; ks++) {
        int kg = ks * 16;
        u32 ah[4], al[4];
        ldmx4(smb + ABH_OFF + (u32)(arow * AB_LD + kg + acolsel) * 2, ah);
        ldmx4(smb + ABL_OFF + (u32)(arow * AB_LD + kg + acolsel) * 2, al);
#pragma unroll
        for (int p = 0; p < 4; p++) {
            int xr = kg + xrow;
            int xc = d0 + p * 16 + xcol;
            u32 bh[4], bl[4];
            ldmx4t(smb + XH_OFF + (u32)(xr * X_LD + xc) * 2, bh);
            ldmx4t(smb + XL_OFF + (u32)(xr * X_LD + xc) * 2, bl);
            mma16816(cacc[2 * p], ah, bh[0], bh[1]);
            mma16816(cacc[2 * p], ah, bl[0], bl[1]);
            mma16816(cacc[2 * p], al, bh[0], bh[1]);
            mma16816(cacc[2 * p + 1], ah, bh[2], bh[3]);
            mma16816(cacc[2 * p + 1], ah, bl[2], bl[3]);
            mma16816(cacc[2 * p + 1], al, bh[2], bh[3]);
        }
    }
}

// write agg C frags as bf16 hi/lo split tiles (warp layout n0=(warp&3)*16, d0=(warp>>2)*64)
__device__ __forceinline__ void store_split_frag(
    char* smc, const float cacc[8][4], int n0, int o0,
    u32 hoff, u32 loff, int ld, int lane)
{
    int r = n0 + (lane >> 2);
    int cbase = o0 + 2 * (lane & 3);
#pragma unroll
    for (int t = 0; t < 8; t++) {
        int col = cbase + t * 8;
#pragma unroll
        for (int rr = 0; rr < 2; rr++) {
            float v0 = cacc[t][rr * 2], v1 = cacc[t][rr * 2 + 1];
            u32 off = (u32)((r + rr * 8) * ld + col) * 2;
            *(u32*)(smc + hoff + off) = pack_hi2(v0, v1);
            *(u32*)(smc + loff + off) = pack_lo2(v0, v1);
        }
    }
}

// ---------------- LayerNorm -> split bf16 X tiles ----------------
__device__ __forceinline__ void ln_split(
    char* smc, const float* __restrict__ src, int lds, const float* __restrict__ bias,
    const float* __restrict__ gg, const float* __restrict__ bb, bool leaky, int tid)
{
    int warp = tid >> 5, lane = tid & 31;
    for (int n = warp; n < 64; n += 16) {
        const float* row = src + (size_t)n * lds;
        float v[8];
        float s = 0.f, sq = 0.f;
#pragma unroll
        for (int i = 0; i < 4; i++) {
            int c = 2 * lane + 64 * i;
            float2 t = *(const float2*)(row + c);
            if (bias) {
                float2 bv = *(const float2*)(bias + c);
                t.x += bv.x; t.y += bv.y;
            }
            v[2 * i] = t.x; v[2 * i + 1] = t.y;
            s += t.x + t.y;
            sq += t.x * t.x + t.y * t.y;
        }
#pragma unroll
        for (int off = 16; off > 0; off >>= 1) {
            s += __shfl_xor_sync(0xffffffffu, s, off);
            sq += __shfl_xor_sync(0xffffffffu, sq, off);
        }
        float mean = s * (1.0f / 256.0f);
        float var = sq * (1.0f / 256.0f) - mean * mean;
        float rstd = rsqrtf(var + 1e-5f);
#pragma unroll
        for (int i = 0; i < 4; i++) {
            int c = 2 * lane + 64 * i;
            float o0 = (v[2 * i] - mean) * rstd * gg[c] + bb[c];
            float o1 = (v[2 * i + 1] - mean) * rstd * gg[c + 1] + bb[c + 1];
            if (leaky) {
                o0 = (o0 >= 0.f) ? o0 : 0.1f * o0;
                o1 = (o1 >= 0.f) ? o1 : 0.1f * o1;
            }
            u32 off2 = (u32)(n * X_LD + c) * 2;
            *(u32*)(smc + XH_OFF + off2) = pack_hi2(o0, o1);
            *(u32*)(smc + XL_OFF + off2) = pack_lo2(o0, o1);
        }
    }
}

// ---------------- prologue kernels ----------------
// warp-parallel adj softmax: 128 rows, 1 row per warp
__global__ void adj_softmax_kernel(const float* __restrict__ adj0,
                                   const float* __restrict__ adj1)
{
    int gw = blockIdx.x * 16 + (threadIdx.x >> 5);
    int lane = threadIdx.x & 31;
    int mat = gw >> 6, r = gw & 63;
    const float* row = (mat ? adj1 : adj0) + r * 64;
    float v0 = row[lane], v1 = row[32 + lane];
    float mx = fmaxf(v0, v1);
#pragma unroll
    for (int off = 16; off > 0; off >>= 1)
        mx = fmaxf(mx, __shfl_xor_sync(0xffffffffu, mx, off));
    float e0 = __expf(v0 - mx), e1 = __expf(v1 - mx);
    float ss = e0 + e1;
#pragma unroll
    for (int off = 16; off > 0; off >>= 1)
        ss += __shfl_xor_sync(0xffffffffu, ss, off);
    float inv = 1.0f / ss;
    float* dst = g_Ast + mat * 4096 + r * 64;
    dst[lane] = e0 * inv;
    dst[32 + lane] = e1 * inv;
}

// split weights into fragment-packed hi/lo
__global__ void prep_weights(
    const float* __restrict__ th0, const float* __restrict__ ph0, const float* __restrict__ fcw0,
    const float* __restrict__ th1, const float* __restrict__ ph1, const float* __restrict__ fcw1)
{
    int idx = blockIdx.x * blockDim.x + threadIdx.x;  // 0..262143
    int k = idx & 255, r = (idx >> 8) & 255, g = (idx >> 16) & 1, l = idx >> 17;
    const float* th = l ? th1 : th0;
    const float* pw = l ? ph1 : ph0;
    const float* fw = l ? fcw1 : fcw0;
    float v;
    if (g == 0) v = (r < 128) ? th[r * 256 + k] : pw[(r - 128) * 256 + k];
    else        v = fw[r * 256 + k];
    __nv_bfloat16 hb = __float2bfloat16(v);
    __nv_bfloat16 lb = __float2bfloat16(v - __bfloat162float(hb));
    // fragment address: b0 = W[o8*8 + lane/4][kstep*16 + 2*(lane%4) (+1)], b1 = k+8,+9
    u32 o8 = (u32)(r >> 3);
    u32 kp = (u32)(k >> 5);
    u32 lane = (u32)((r & 7) * 4 + ((k >> 1) & 3));
    u32 slot = (u32)(((k >> 4) & 1) * 2 + ((k >> 3) & 1));
    u32 off16 = ((((o8 * 8 + kp) * 32 + lane) * 4 + slot) << 1) | (u32)(k & 1);
    ((u16*)g_Wf[l][g][0])[off16] = __bfloat16_as_ushort(hb);
    ((u16*)g_Wf[l][g][1])[off16] = __bfloat16_as_ushort(lb);
}

// ---------------- main kernel ----------------
__global__ void __launch_bounds__(NT, 1) gconv_kernel(
    const float* __restrict__ graph,
    const float* __restrict__ ln_in_g, const float* __restrict__ ln_in_b,
    const float* __restrict__ fcb0,
    const float* __restrict__ ln0_g, const float* __restrict__ ln0_b,
    const float* __restrict__ fcb1,
    float* __restrict__ out)
{
    extern __shared__ char smc[];
    u32 smb = smem_u32(smc);
    int tid = threadIdx.x;
    int warp = tid >> 5, lane = tid & 31;
    int b = blockIdx.x;

    // input LN + split
    ln_split(smc, graph + (size_t)b * 64 * 256, 256, nullptr, ln_in_g, ln_in_b, false, tid);
    __syncthreads();

    float wacc[4][2][4];
    float cacc[8][4];

#pragma unroll 1
    for (int l = 0; l < 2; l++) {
        // ---- qk = X @ W_qk^T ----
        wgemm_reg(smb, XH_OFF, XL_OFF, g_Wf[l][0][0], g_Wf[l][0][1], wacc, warp, lane);
        wstore_split(smc, wacc, QKH_OFF, QKL_OFF, QK_LD, warp, lane);
        __syncthreads();

        // ---- scores = q @ k^T / sqrt(128) ----
        {
            float sacc[2][4];
            scores_tc(smb, sacc, warp, lane);
            const float sscale = 0.08838834764831845f;
            float* abf = (float*)(smc + ABF_OFF);
            int n0 = (warp & 3) * 16;
            int m0 = (warp >> 2) * 16;
            int r = n0 + (lane >> 2);
            int cb = m0 + 2 * (lane & 3);
#pragma unroll
            for (int t = 0; t < 2; t++)
#pragma unroll
                for (int rr = 0; rr < 2; rr++) {
                    float2 p;
                    p.x = sacc[t][rr * 2] * sscale;
                    p.y = sacc[t][rr * 2 + 1] * sscale;
                    *(float2*)(abf + (r + rr * 8) * ABF_LD + cb + t * 8) = p;
                }
        }
        __syncthreads();

        // ---- A_hat = Ast + softmax(scores) -> split tiles ----
        {
            const float* Ast = g_Ast + l * 4096;
            float* abf = (float*)(smc + ABF_OFF);
            for (int n = warp; n < 64; n += 16) {
                float v0 = abf[n * ABF_LD + lane];
                float v1 = abf[n * ABF_LD + 32 + lane];
                float mx = fmaxf(v0, v1);
#pragma unroll
                for (int off = 16; off > 0; off >>= 1)
                    mx = fmaxf(mx, __shfl_xor_sync(0xffffffffu, mx, off));
                float e0 = __expf(v0 - mx);
                float e1 = __expf(v1 - mx);
                float ss = e0 + e1;
#pragma unroll
                for (int off = 16; off > 0; off >>= 1)
                    ss += __shfl_xor_sync(0xffffffffu, ss, off);
                float inv = 1.0f / ss;
                float a0 = Ast[n * 64 + lane] + e0 * inv;
                float a1 = Ast[n * 64 + 32 + lane] + e1 * inv;
                __nv_bfloat16 h0 = __float2bfloat16(a0);
                __nv_bfloat16 h1 = __float2bfloat16(a1);
                u16* abh = (u16*)(smc + ABH_OFF);
                u16* abl = (u16*)(smc + ABL_OFF);
                abh[n * AB_LD + lane]      = __bfloat16_as_ushort(h0);
                abh[n * AB_LD + 32 + lane] = __bfloat16_as_ushort(h1);
                abl[n * AB_LD + lane] =
                    __bfloat16_as_ushort(__float2bfloat16(a0 - __bfloat162float(h0)));
                abl[n * AB_LD + 32 + lane] =
                    __bfloat16_as_ushort(__float2bfloat16(a1 - __bfloat162float(h1)));
            }
        }
        __syncthreads();

        // ---- agg = A_hat @ X -> overwrite X tiles ----
        agg_tc(smc, smb, cacc, warp, lane);
        __syncthreads();  // all X reads done before overwrite
        store_split_frag(smc, cacc, (warp & 3) * 16, (warp >> 2) * 64,
                         XH_OFF, XL_OFF, X_LD, lane);
        __syncthreads();

        // ---- fc = agg @ W_fc^T -> fp32 (FC aliases QK region) ----
        wgemm_reg(smb, XH_OFF, XL_OFF, g_Wf[l][1][0], g_Wf[l][1][1], wacc, warp, lane);
        wstore_f32(smc, wacc, FC_OFF, FC_LD, warp, lane);
        __syncthreads();

        if (l == 0) {
            // LN(fc + bias) + leaky -> new X tiles
            ln_split(smc, (float*)(smc + FC_OFF), FC_LD, fcb0, ln0_g, ln0_b, true, tid);
            __syncthreads();
        } else {
            // fc + bias -> global out
            const float* fco = (const float*)(smc + FC_OFF);
            float* og = out + (size_t)b * 64 * 256;
            for (int i = tid; i < 64 * 64; i += NT) {
                int rr = i >> 6, c4 = (i & 63) * 4;
                float4 v = *(const float4*)(fco + rr * FC_LD + c4);
                float4 bb = *(const float4*)(fcb1 + c4);
                v.x += bb.x; v.y += bb.y; v.z += bb.z; v.w += bb.w;
                *(float4*)(og + rr * 256 + c4) = v;
            }
        }
    }
}

extern "C" void kernel_launch(void* const* d_in, const int* in_sizes, int n_in,
                              void* d_out, int out_size)
{
    const float* graph   = (const float*)d_in[0];
    const float* ln_in_g = (const float*)d_in[1];
    const float* ln_in_b = (const float*)d_in[2];
    const float* adj0    = (const float*)d_in[3];
    const float* th0     = (const float*)d_in[4];
    const float* ph0     = (const float*)d_in[5];
    const float* fcw0    = (const float*)d_in[6];
    const float* fcb0    = (const float*)d_in[7];
    const float* ln0_g   = (const float*)d_in[8];
    const float* ln0_b   = (const float*)d_in[9];
    const float* adj1    = (const float*)d_in[10];
    const float* th1     = (const float*)d_in[11];
    const float* ph1     = (const float*)d_in[12];
    const float* fcw1    = (const float*)d_in[13];
    const float* fcb1    = (const float*)d_in[14];
    float* out = (float*)d_out;

    cudaFuncSetAttribute(gconv_kernel,
                         cudaFuncAttributeMaxDynamicSharedMemorySize, SMEM_BYTES);

    adj_softmax_kernel<<<8, 512>>>(adj0, adj1);
    prep_weights<<<512, 512>>>(th0, ph0, fcw0, th1, ph1, fcw1);
    gconv_kernel<<<NB, NT, SMEM_BYTES>>>(
        graph, ln_in_g, ln_in_b, fcb0, ln0_g, ln0_b, fcb1, out);
}

// round 8
// speedup vs baseline: 4.4062x; 1.3201x over previous
#include <cuda_runtime.h>
#include <cuda_fp16.h>
#include <math.h>

#define NB 2048
#define NT 512

typedef unsigned long long ull;
typedef unsigned int u32;
typedef unsigned short u16;

// element strides
#define X_LD 264     // fp16 tiles [64][264]
#define QK_LD 264
#define ABF_LD 68    // fp32 scores
#define AB_LD 72     // fp16 A_hat (hi only)
#define FC_LD 260    // fp32 fc-out

// smem byte offsets
#define XH_OFF 0
#define XL_OFF 33792
#define QKH_OFF 67584
#define QKL_OFF 101376
#define ABH_OFF 135168
#define ABF_OFF 144384
#define FC_OFF 67584         // alias QK region (dead after scores)
#define SMEM_BYTES 161792

__device__ float g_Ast[2 * 64 * 64];
// fragment-packed weights: [layer][qk|fc][hi|lo], 131072 B each.
// index: (((o8*8 + kp)*32 + lane)*4 + slot) u32s; slot = (kstep&1)*2 + wsel.
__device__ uint4 g_Wf[2][2][2][8192];

// ---------------- PTX wrappers ----------------
__device__ __forceinline__ u32 smem_u32(const void* p) {
    u32 a;
    asm("{ .reg .u64 t; cvta.to.shared.u64 t, %1; cvt.u32.u64 %0, t; }" : "=r"(a) : "l"(p));
    return a;
}
__device__ __forceinline__ void ldmx4(u32 a, u32 r[4]) {
    asm volatile("ldmatrix.sync.aligned.m8n8.x4.shared.b16 {%0,%1,%2,%3}, [%4];"
                 : "=r"(r[0]), "=r"(r[1]), "=r"(r[2]), "=r"(r[3]) : "r"(a));
}
__device__ __forceinline__ void ldmx4t(u32 a, u32 r[4]) {
    asm volatile("ldmatrix.sync.aligned.m8n8.x4.trans.shared.b16 {%0,%1,%2,%3}, [%4];"
                 : "=r"(r[0]), "=r"(r[1]), "=r"(r[2]), "=r"(r[3]) : "r"(a));
}
__device__ __forceinline__ void mma16816(float d[4], const u32 a[4], u32 b0, u32 b1) {
    asm volatile("mma.sync.aligned.m16n8k16.row.col.f32.f16.f16.f32 "
                 "{%0,%1,%2,%3}, {%4,%5,%6,%7}, {%8,%9}, {%0,%1,%2,%3};"
                 : "+f"(d[0]), "+f"(d[1]), "+f"(d[2]), "+f"(d[3])
                 : "r"(a[0]), "r"(a[1]), "r"(a[2]), "r"(a[3]), "r"(b0), "r"(b1));
}

__device__ __forceinline__ u32 pack_h2(float v0, float v1) {
    __half2 h = __floats2half2_rn(v0, v1);
    return *(u32*)&h;
}
__device__ __forceinline__ u32 pack_l2(float v0, float v1) {
    float h0 = __half2float(__float2half_rn(v0));
    float h1 = __half2float(__float2half_rn(v1));
    __half2 h = __floats2half2_rn(v0 - h0, v1 - h1);
    return *(u32*)&h;
}

// ---------------- weight GEMM: C[64 n][256 o], warp tile 64n x 16o ----------------
// A = X hi tiles from smem (ldmatrix); B = fragment-packed W hi+lo direct from global.
__device__ __forceinline__ void wgemm_reg(
    u32 smb, u32 xh_off,
    const uint4* __restrict__ wH, const uint4* __restrict__ wL,
    float acc[4][2][4], int warp, int lane)
{
#pragma unroll
    for (int nf = 0; nf < 4; nf++)
#pragma unroll
        for (int o = 0; o < 2; o++)
#pragma unroll
            for (int j = 0; j < 4; j++) acc[nf][o][j] = 0.f;

    int arow = lane & 15;
    int acol = 8 * (lane >> 4);
    u32 fbase0 = (u32)(((warp * 2 + 0) * 8) * 32 + lane);
    u32 fbase1 = (u32)(((warp * 2 + 1) * 8) * 32 + lane);

    uint4 bh[2], bl[2];
    bh[0] = wH[fbase0]; bh[1] = wH[fbase1];
    bl[0] = wL[fbase0]; bl[1] = wL[fbase1];

#pragma unroll
    for (int kp = 0; kp < 8; kp++) {
        uint4 nh[2], nl[2];
        if (kp < 7) {
            nh[0] = wH[fbase0 + (kp + 1) * 32]; nh[1] = wH[fbase1 + (kp + 1) * 32];
            nl[0] = wL[fbase0 + (kp + 1) * 32]; nl[1] = wL[fbase1 + (kp + 1) * 32];
        }
#pragma unroll
        for (int ks = 0; ks < 2; ks++) {
            int kg = (kp * 2 + ks) * 16;
#pragma unroll
            for (int nf = 0; nf < 4; nf++) {
                u32 ah[4];
                u32 aoff = (u32)((nf * 16 + arow) * X_LD + kg + acol) * 2;
                ldmx4(smb + xh_off + aoff, ah);
#pragma unroll
                for (int o = 0; o < 2; o++) {
                    u32 b0h = ks ? bh[o].z : bh[o].x;
                    u32 b1h = ks ? bh[o].w : bh[o].y;
                    u32 b0l = ks ? bl[o].z : bl[o].x;
                    u32 b1l = ks ? bl[o].w : bl[o].y;
                    mma16816(acc[nf][o], ah, b0h, b1h);
                    mma16816(acc[nf][o], ah, b0l, b1l);
                }
            }
        }
        if (kp < 7) {
            bh[0] = nh[0]; bh[1] = nh[1];
            bl[0] = nl[0]; bl[1] = nl[1];
        }
    }
}

// store wgemm acc as fp16 hi (+lo if store_lo) split tiles (qk epilogue)
__device__ __forceinline__ void wstore_split(
    char* smc, const float acc[4][2][4], u32 hoff, u32 loff, int ld,
    int warp, int lane, bool store_lo)
{
    int rb = lane >> 2;
    int cb = warp * 16 + 2 * (lane & 3);
#pragma unroll
    for (int nf = 0; nf < 4; nf++)
#pragma unroll
        for (int o = 0; o < 2; o++)
#pragma unroll
            for (int rr = 0; rr < 2; rr++) {
                int r = nf * 16 + rb + rr * 8;
                int c = cb + o * 8;
                u32 off = (u32)(r * ld + c) * 2;
                float v0 = acc[nf][o][rr * 2], v1 = acc[nf][o][rr * 2 + 1];
                *(u32*)(smc + hoff + off) = pack_h2(v0, v1);
                if (store_lo) *(u32*)(smc + loff + off) = pack_l2(v0, v1);
            }
}

// store wgemm acc as fp32 (fc epilogue)
__device__ __forceinline__ void wstore_f32(
    char* smc, const float acc[4][2][4], u32 foff, int ld, int warp, int lane)
{
    float* f = (float*)(smc + foff);
    int rb = lane >> 2;
    int cb = warp * 16 + 2 * (lane & 3);
#pragma unroll
    for (int nf = 0; nf < 4; nf++)
#pragma unroll
        for (int o = 0; o < 2; o++)
#pragma unroll
            for (int rr = 0; rr < 2; rr++) {
                int r = nf * 16 + rb + rr * 8;
                int c = cb + o * 8;
                float2 p = make_float2(acc[nf][o][rr * 2], acc[nf][o][rr * 2 + 1]);
                *(float2*)(f + r * ld + c) = p;
            }
}

// ---------------- scores: C[64 n][64 m] = q @ k^T ----------------
// A = q hi; B = k hi + lo.
__device__ __forceinline__ void scores_tc(u32 smb, float sacc[2][4], int warp, int lane)
{
    int n0 = (warp & 3) * 16;
    int m0 = (warp >> 2) * 16;
#pragma unroll
    for (int t = 0; t < 2; t++)
#pragma unroll
        for (int j = 0; j < 4; j++) sacc[t][j] = 0.f;
    int arow = n0 + (lane & 15);
    int acolsel = 8 * (lane >> 4);
    int brow = m0 + (lane & 7) + 8 * ((lane >> 4) & 1);
    int bksel = 8 * ((lane >> 3) & 1);
#pragma unroll
    for (int ks = 0; ks < 8; ks++) {
        int kg = ks * 16;
        u32 ah[4], bh[4], bl[4];
        ldmx4(smb + QKH_OFF + (u32)(arow * QK_LD + kg + acolsel) * 2, ah);
        ldmx4(smb + QKH_OFF + (u32)(brow * QK_LD + 128 + kg + bksel) * 2, bh);
        ldmx4(smb + QKL_OFF + (u32)(brow * QK_LD + 128 + kg + bksel) * 2, bl);
        mma16816(sacc[0], ah, bh[0], bh[1]);
        mma16816(sacc[0], ah, bl[0], bl[1]);
        mma16816(sacc[1], ah, bh[2], bh[3]);
        mma16816(sacc[1], ah, bl[2], bl[3]);
    }
}

// ---------------- agg: C[64 n][256 d] = A_hat @ X ----------------
// A = A_hat hi; B = X hi + lo (trans ldmatrix).
__device__ __forceinline__ void agg_tc(char* smc, u32 smb, float cacc[8][4],
                                       int warp, int lane)
{
    int n0 = (warp & 3) * 16;
    int d0 = (warp >> 2) * 64;
#pragma unroll
    for (int t = 0; t < 8; t++)
#pragma unroll
        for (int j = 0; j < 4; j++) cacc[t][j] = 0.f;
    int arow = n0 + (lane & 15);
    int acolsel = 8 * (lane >> 4);
    int xrow = lane & 15;
    int xcol = 8 * (lane >> 4);
#pragma unroll
    for (int ks = 0; ks < 4; ks++) {
        int kg = ks * 16;
        u32 ah[4];
        ldmx4(smb + ABH_OFF + (u32)(arow * AB_LD + kg + acolsel) * 2, ah);
#pragma unroll
        for (int p = 0; p < 4; p++) {
            int xr = kg + xrow;
            int xc = d0 + p * 16 + xcol;
            u32 bh[4], bl[4];
            ldmx4t(smb + XH_OFF + (u32)(xr * X_LD + xc) * 2, bh);
            ldmx4t(smb + XL_OFF + (u32)(xr * X_LD + xc) * 2, bl);
            mma16816(cacc[2 * p], ah, bh[0], bh[1]);
            mma16816(cacc[2 * p], ah, bl[0], bl[1]);
            mma16816(cacc[2 * p + 1], ah, bh[2], bh[3]);
            mma16816(cacc[2 * p + 1], ah, bl[2], bl[3]);
        }
    }
}

// write agg C frags as fp16 hi tiles only (fc reads A hi only)
__device__ __forceinline__ void store_hi_frag(
    char* smc, const float cacc[8][4], int n0, int o0, u32 hoff, int ld, int lane)
{
    int r = n0 + (lane >> 2);
    int cbase = o0 + 2 * (lane & 3);
#pragma unroll
    for (int t = 0; t < 8; t++) {
        int col = cbase + t * 8;
#pragma unroll
        for (int rr = 0; rr < 2; rr++) {
            float v0 = cacc[t][rr * 2], v1 = cacc[t][rr * 2 + 1];
            u32 off = (u32)((r + rr * 8) * ld + col) * 2;
            *(u32*)(smc + hoff + off) = pack_h2(v0, v1);
        }
    }
}

// ---------------- LayerNorm -> split fp16 X tiles (hi + lo) ----------------
__device__ __forceinline__ void ln_split(
    char* smc, const float* __restrict__ src, int lds, const float* __restrict__ bias,
    const float* __restrict__ gg, const float* __restrict__ bb, bool leaky, int tid)
{
    int warp = tid >> 5, lane = tid & 31;
    for (int n = warp; n < 64; n += 16) {
        const float* row = src + (size_t)n * lds;
        float v[8];
        float s = 0.f, sq = 0.f;
#pragma unroll
        for (int i = 0; i < 4; i++) {
            int c = 2 * lane + 64 * i;
            float2 t = *(const float2*)(row + c);
            if (bias) {
                float2 bv = *(const float2*)(bias + c);
                t.x += bv.x; t.y += bv.y;
            }
            v[2 * i] = t.x; v[2 * i + 1] = t.y;
            s += t.x + t.y;
            sq += t.x * t.x + t.y * t.y;
        }
#pragma unroll
        for (int off = 16; off > 0; off >>= 1) {
            s += __shfl_xor_sync(0xffffffffu, s, off);
            sq += __shfl_xor_sync(0xffffffffu, sq, off);
        }
        float mean = s * (1.0f / 256.0f);
        float var = sq * (1.0f / 256.0f) - mean * mean;
        float rstd = rsqrtf(var + 1e-5f);
#pragma unroll
        for (int i = 0; i < 4; i++) {
            int c = 2 * lane + 64 * i;
            float o0 = (v[2 * i] - mean) * rstd * gg[c] + bb[c];
            float o1 = (v[2 * i + 1] - mean) * rstd * gg[c + 1] + bb[c + 1];
            if (leaky) {
                o0 = (o0 >= 0.f) ? o0 : 0.1f * o0;
                o1 = (o1 >= 0.f) ? o1 : 0.1f * o1;
            }
            u32 off2 = (u32)(n * X_LD + c) * 2;
            *(u32*)(smc + XH_OFF + off2) = pack_h2(o0, o1);
            *(u32*)(smc + XL_OFF + off2) = pack_l2(o0, o1);
        }
    }
}

// ---------------- prologue kernels ----------------
__global__ void adj_softmax_kernel(const float* __restrict__ adj0,
                                   const float* __restrict__ adj1)
{
    int gw = blockIdx.x * 16 + (threadIdx.x >> 5);
    int lane = threadIdx.x & 31;
    int mat = gw >> 6, r = gw & 63;
    const float* row = (mat ? adj1 : adj0) + r * 64;
    float v0 = row[lane], v1 = row[32 + lane];
    float mx = fmaxf(v0, v1);
#pragma unroll
    for (int off = 16; off > 0; off >>= 1)
        mx = fmaxf(mx, __shfl_xor_sync(0xffffffffu, mx, off));
    float e0 = __expf(v0 - mx), e1 = __expf(v1 - mx);
    float ss = e0 + e1;
#pragma unroll
    for (int off = 16; off > 0; off >>= 1)
        ss += __shfl_xor_sync(0xffffffffu, ss, off);
    float inv = 1.0f / ss;
    float* dst = g_Ast + mat * 4096 + r * 64;
    dst[lane] = e0 * inv;
    dst[32 + lane] = e1 * inv;
}

// split weights into fragment-packed fp16 hi/lo
__global__ void prep_weights(
    const float* __restrict__ th0, const float* __restrict__ ph0, const float* __restrict__ fcw0,
    const float* __restrict__ th1, const float* __restrict__ ph1, const float* __restrict__ fcw1)
{
    int idx = blockIdx.x * blockDim.x + threadIdx.x;  // 0..262143
    int k = idx & 255, r = (idx >> 8) & 255, g = (idx >> 16) & 1, l = idx >> 17;
    const float* th = l ? th1 : th0;
    const float* pw = l ? ph1 : ph0;
    const float* fw = l ? fcw1 : fcw0;
    float v;
    if (g == 0) v = (r < 128) ? th[r * 256 + k] : pw[(r - 128) * 256 + k];
    else        v = fw[r * 256 + k];
    __half hb = __float2half_rn(v);
    __half lb = __float2half_rn(v - __half2float(hb));
    u32 o8 = (u32)(r >> 3);
    u32 kp = (u32)(k >> 5);
    u32 lane = (u32)((r & 7) * 4 + ((k >> 1) & 3));
    u32 slot = (u32)(((k >> 4) & 1) * 2 + ((k >> 3) & 1));
    u32 off16 = ((((o8 * 8 + kp) * 32 + lane) * 4 + slot) << 1) | (u32)(k & 1);
    ((u16*)g_Wf[l][g][0])[off16] = __half_as_ushort(hb);
    ((u16*)g_Wf[l][g][1])[off16] = __half_as_ushort(lb);
}

// ---------------- main kernel ----------------
__global__ void __launch_bounds__(NT, 1) gconv_kernel(
    const float* __restrict__ graph,
    const float* __restrict__ ln_in_g, const float* __restrict__ ln_in_b,
    const float* __restrict__ fcb0,
    const float* __restrict__ ln0_g, const float* __restrict__ ln0_b,
    const float* __restrict__ fcb1,
    float* __restrict__ out)
{
    extern __shared__ char smc[];
    u32 smb = smem_u32(smc);
    int tid = threadIdx.x;
    int warp = tid >> 5, lane = tid & 31;
    int b = blockIdx.x;

    // input LN + split
    ln_split(smc, graph + (size_t)b * 64 * 256, 256, nullptr, ln_in_g, ln_in_b, false, tid);
    __syncthreads();

    float wacc[4][2][4];
    float cacc[8][4];

#pragma unroll 1
    for (int l = 0; l < 2; l++) {
        // ---- qk = X @ W_qk^T (A hi only) ----
        wgemm_reg(smb, XH_OFF, g_Wf[l][0][0], g_Wf[l][0][1], wacc, warp, lane);
        wstore_split(smc, wacc, QKH_OFF, QKL_OFF, QK_LD, warp, lane, warp >= 8);
        __syncthreads();

        // ---- scores = q @ k^T / sqrt(128) ----
        {
            float sacc[2][4];
            scores_tc(smb, sacc, warp, lane);
            const float sscale = 0.08838834764831845f;
            float* abf = (float*)(smc + ABF_OFF);
            int n0 = (warp & 3) * 16;
            int m0 = (warp >> 2) * 16;
            int r = n0 + (lane >> 2);
            int cb = m0 + 2 * (lane & 3);
#pragma unroll
            for (int t = 0; t < 2; t++)
#pragma unroll
                for (int rr = 0; rr < 2; rr++) {
                    float2 p;
                    p.x = sacc[t][rr * 2] * sscale;
                    p.y = sacc[t][rr * 2 + 1] * sscale;
                    *(float2*)(abf + (r + rr * 8) * ABF_LD + cb + t * 8) = p;
                }
        }
        __syncthreads();

        // ---- A_hat = Ast + softmax(scores) -> hi tile ----
        {
            const float* Ast = g_Ast + l * 4096;
            float* abf = (float*)(smc + ABF_OFF);
            u16* abh = (u16*)(smc + ABH_OFF);
            for (int n = warp; n < 64; n += 16) {
                float v0 = abf[n * ABF_LD + lane];
                float v1 = abf[n * ABF_LD + 32 + lane];
                float mx = fmaxf(v0, v1);
#pragma unroll
                for (int off = 16; off > 0; off >>= 1)
                    mx = fmaxf(mx, __shfl_xor_sync(0xffffffffu, mx, off));
                float e0 = __expf(v0 - mx);
                float e1 = __expf(v1 - mx);
                float ss = e0 + e1;
#pragma unroll
                for (int off = 16; off > 0; off >>= 1)
                    ss += __shfl_xor_sync(0xffffffffu, ss, off);
                float inv = 1.0f / ss;
                float a0 = Ast[n * 64 + lane] + e0 * inv;
                float a1 = Ast[n * 64 + 32 + lane] + e1 * inv;
                abh[n * AB_LD + lane]      = __half_as_ushort(__float2half_rn(a0));
                abh[n * AB_LD + 32 + lane] = __half_as_ushort(__float2half_rn(a1));
            }
        }
        __syncthreads();

        // ---- agg = A_hat @ X -> overwrite X hi tiles ----
        agg_tc(smc, smb, cacc, warp, lane);
        __syncthreads();  // all X reads done before overwrite
        store_hi_frag(smc, cacc, (warp & 3) * 16, (warp >> 2) * 64, XH_OFF, X_LD, lane);
        __syncthreads();

        // ---- fc = agg @ W_fc^T -> fp32 (FC aliases QK region) ----
        wgemm_reg(smb, XH_OFF, g_Wf[l][1][0], g_Wf[l][1][1], wacc, warp, lane);
        wstore_f32(smc, wacc, FC_OFF, FC_LD, warp, lane);
        __syncthreads();

        if (l == 0) {
            // LN(fc + bias) + leaky -> new X tiles (hi + lo)
            ln_split(smc, (float*)(smc + FC_OFF), FC_LD, fcb0, ln0_g, ln0_b, true, tid);
            __syncthreads();
        } else {
            // fc + bias -> global out
            const float* fco = (const float*)(smc + FC_OFF);
            float* og = out + (size_t)b * 64 * 256;
            for (int i = tid; i < 64 * 64; i += NT) {
                int rr = i >> 6, c4 = (i & 63) * 4;
                float4 v = *(const float4*)(fco + rr * FC_LD + c4);
                float4 bb = *(const float4*)(fcb1 + c4);
                v.x += bb.x; v.y += bb.y; v.z += bb.z; v.w += bb.w;
                *(float4*)(og + rr * 256 + c4) = v;
            }
        }
    }
}

extern "C" void kernel_launch(void* const* d_in, const int* in_sizes, int n_in,
                              void* d_out, int out_size)
{
    const float* graph   = (const float*)d_in[0];
    const float* ln_in_g = (const float*)d_in[1];
    const float* ln_in_b = (const float*)d_in[2];
    const float* adj0    = (const float*)d_in[3];
    const float* th0     = (const float*)d_in[4];
    const float* ph0     = (const float*)d_in[5];
    const float* fcw0    = (const float*)d_in[6];
    const float* fcb0    = (const float*)d_in[7];
    const float* ln0_g   = (const float*)d_in[8];
    const float* ln0_b   = (const float*)d_in[9];
    const float* adj1    = (const float*)d_in[10];
    const float* th1     = (const float*)d_in[11];
    const float* ph1     = (const float*)d_in[12];
    const float* fcw1    = (const float*)d_in[13];
    const float* fcb1    = (const float*)d_in[14];
    float* out = (float*)d_out;

    cudaFuncSetAttribute(gconv_kernel,
                         cudaFuncAttributeMaxDynamicSharedMemorySize, SMEM_BYTES);

    adj_softmax_kernel<<<8, 512>>>(adj0, adj1);
    prep_weights<<<512, 512>>>(th0, ph0, fcw0, th1, ph1, fcw1);
    gconv_kernel<<<NB, NT, SMEM_BYTES>>>(
        graph, ln_in_g, ln_in_b, fcb0, ln0_g, ln0_b, fcb1, out);
}

// round 9
// speedup vs baseline: 5.2357x; 1.1883x over previous
#include <cuda_runtime.h>
#include <cuda_fp16.h>
#include <math.h>

#define NB 2048
#define NT 512

typedef unsigned long long ull;
typedef unsigned int u32;
typedef unsigned short u16;

// element strides
#define X_LD 264     // fp16 tiles [64][264]
#define QK_LD 264
#define ABF_LD 68    // fp32 scores
#define AB_LD 72     // fp16 A_hat (hi only)
#define FC_LD 260    // fp32 fc-out (layer 0 only)

// smem byte offsets
#define XH_OFF 0
#define XL_OFF 33792
#define QKH_OFF 67584
#define ABH_OFF 101376
#define ABF_OFF 110592
#define FC_OFF 67584         // alias QKH+ABH+ABF (all dead when FC is written)
#define SMEM_BYTES 134144

__device__ float g_Ast[2 * 64 * 64];
// fragment-packed weights: [layer][qk|fc][hi|lo], 131072 B each.
// index: (((o8*8 + kp)*32 + lane)*4 + slot) u32s; slot = (kstep&1)*2 + wsel.
__device__ uint4 g_Wf[2][2][2][8192];

// ---------------- PTX wrappers ----------------
__device__ __forceinline__ u32 smem_u32(const void* p) {
    u32 a;
    asm("{ .reg .u64 t; cvta.to.shared.u64 t, %1; cvt.u32.u64 %0, t; }" : "=r"(a) : "l"(p));
    return a;
}
__device__ __forceinline__ void ldmx4(u32 a, u32 r[4]) {
    asm volatile("ldmatrix.sync.aligned.m8n8.x4.shared.b16 {%0,%1,%2,%3}, [%4];"
                 : "=r"(r[0]), "=r"(r[1]), "=r"(r[2]), "=r"(r[3]) : "r"(a));
}
__device__ __forceinline__ void ldmx4t(u32 a, u32 r[4]) {
    asm volatile("ldmatrix.sync.aligned.m8n8.x4.trans.shared.b16 {%0,%1,%2,%3}, [%4];"
                 : "=r"(r[0]), "=r"(r[1]), "=r"(r[2]), "=r"(r[3]) : "r"(a));
}
__device__ __forceinline__ void mma16816(float d[4], const u32 a[4], u32 b0, u32 b1) {
    asm volatile("mma.sync.aligned.m16n8k16.row.col.f32.f16.f16.f32 "
                 "{%0,%1,%2,%3}, {%4,%5,%6,%7}, {%8,%9}, {%0,%1,%2,%3};"
                 : "+f"(d[0]), "+f"(d[1]), "+f"(d[2]), "+f"(d[3])
                 : "r"(a[0]), "r"(a[1]), "r"(a[2]), "r"(a[3]), "r"(b0), "r"(b1));
}

__device__ __forceinline__ u32 pack_h2(float v0, float v1) {
    __half2 h = __floats2half2_rn(v0, v1);
    return *(u32*)&h;
}
__device__ __forceinline__ u32 pack_l2(float v0, float v1) {
    float h0 = __half2float(__float2half_rn(v0));
    float h1 = __half2float(__float2half_rn(v1));
    __half2 h = __floats2half2_rn(v0 - h0, v1 - h1);
    return *(u32*)&h;
}

// ---------------- weight GEMM: C[64 n][256 o], warp tile 64n x 16o ----------------
// A = X hi tiles from smem (ldmatrix); B = fragment-packed W direct from global.
// USE_LO: include the W-lo correction term (fc yes, qk no).
template <bool USE_LO>
__device__ __forceinline__ void wgemm_reg(
    u32 smb, u32 xh_off,
    const uint4* __restrict__ wH, const uint4* __restrict__ wL,
    float acc[4][2][4], int warp, int lane)
{
#pragma unroll
    for (int nf = 0; nf < 4; nf++)
#pragma unroll
        for (int o = 0; o < 2; o++)
#pragma unroll
            for (int j = 0; j < 4; j++) acc[nf][o][j] = 0.f;

    int arow = lane & 15;
    int acol = 8 * (lane >> 4);
    u32 fbase0 = (u32)(((warp * 2 + 0) * 8) * 32 + lane);
    u32 fbase1 = (u32)(((warp * 2 + 1) * 8) * 32 + lane);

    uint4 bh[2], bl[2];
    bh[0] = wH[fbase0]; bh[1] = wH[fbase1];
    if (USE_LO) { bl[0] = wL[fbase0]; bl[1] = wL[fbase1]; }

#pragma unroll
    for (int kp = 0; kp < 8; kp++) {
        uint4 nh[2], nl[2];
        if (kp < 7) {
            nh[0] = wH[fbase0 + (kp + 1) * 32]; nh[1] = wH[fbase1 + (kp + 1) * 32];
            if (USE_LO) {
                nl[0] = wL[fbase0 + (kp + 1) * 32]; nl[1] = wL[fbase1 + (kp + 1) * 32];
            }
        }
#pragma unroll
        for (int ks = 0; ks < 2; ks++) {
            int kg = (kp * 2 + ks) * 16;
#pragma unroll
            for (int nf = 0; nf < 4; nf++) {
                u32 ah[4];
                u32 aoff = (u32)((nf * 16 + arow) * X_LD + kg + acol) * 2;
                ldmx4(smb + xh_off + aoff, ah);
#pragma unroll
                for (int o = 0; o < 2; o++) {
                    u32 b0h = ks ? bh[o].z : bh[o].x;
                    u32 b1h = ks ? bh[o].w : bh[o].y;
                    mma16816(acc[nf][o], ah, b0h, b1h);
                    if (USE_LO) {
                        u32 b0l = ks ? bl[o].z : bl[o].x;
                        u32 b1l = ks ? bl[o].w : bl[o].y;
                        mma16816(acc[nf][o], ah, b0l, b1l);
                    }
                }
            }
        }
        if (kp < 7) {
            bh[0] = nh[0]; bh[1] = nh[1];
            if (USE_LO) { bl[0] = nl[0]; bl[1] = nl[1]; }
        }
    }
}

// store wgemm acc as fp16 hi tiles (qk epilogue)
__device__ __forceinline__ void wstore_hi(
    char* smc, const float acc[4][2][4], u32 hoff, int ld, int warp, int lane)
{
    int rb = lane >> 2;
    int cb = warp * 16 + 2 * (lane & 3);
#pragma unroll
    for (int nf = 0; nf < 4; nf++)
#pragma unroll
        for (int o = 0; o < 2; o++)
#pragma unroll
            for (int rr = 0; rr < 2; rr++) {
                int r = nf * 16 + rb + rr * 8;
                int c = cb + o * 8;
                *(u32*)(smc + hoff + (u32)(r * ld + c) * 2) =
                    pack_h2(acc[nf][o][rr * 2], acc[nf][o][rr * 2 + 1]);
            }
}

// store wgemm acc as fp32 to smem (fc epilogue, layer 0)
__device__ __forceinline__ void wstore_f32(
    char* smc, const float acc[4][2][4], u32 foff, int ld, int warp, int lane)
{
    float* f = (float*)(smc + foff);
    int rb = lane >> 2;
    int cb = warp * 16 + 2 * (lane & 3);
#pragma unroll
    for (int nf = 0; nf < 4; nf++)
#pragma unroll
        for (int o = 0; o < 2; o++)
#pragma unroll
            for (int rr = 0; rr < 2; rr++) {
                int r = nf * 16 + rb + rr * 8;
                int c = cb + o * 8;
                *(float2*)(f + r * ld + c) =
                    make_float2(acc[nf][o][rr * 2], acc[nf][o][rr * 2 + 1]);
            }
}

// store wgemm acc + bias directly to global (fc epilogue, layer 1)
__device__ __forceinline__ void wstore_global(
    const float acc[4][2][4], float* __restrict__ og,
    const float* __restrict__ bias, int warp, int lane)
{
    int rb = lane >> 2;
    int cb = warp * 16 + 2 * (lane & 3);
    float b00 = bias[cb], b01 = bias[cb + 1];
    float b10 = bias[cb + 8], b11 = bias[cb + 9];
#pragma unroll
    for (int nf = 0; nf < 4; nf++)
#pragma unroll
        for (int o = 0; o < 2; o++)
#pragma unroll
            for (int rr = 0; rr < 2; rr++) {
                int r = nf * 16 + rb + rr * 8;
                int c = cb + o * 8;
                float2 p;
                p.x = acc[nf][o][rr * 2] + (o ? b10 : b00);
                p.y = acc[nf][o][rr * 2 + 1] + (o ? b11 : b01);
                *(float2*)(og + r * 256 + c) = p;
            }
}

// ---------------- scores: C[64 n][64 m] = q @ k^T (hi only) ----------------
__device__ __forceinline__ void scores_tc(u32 smb, float sacc[2][4], int warp, int lane)
{
    int n0 = (warp & 3) * 16;
    int m0 = (warp >> 2) * 16;
#pragma unroll
    for (int t = 0; t < 2; t++)
#pragma unroll
        for (int j = 0; j < 4; j++) sacc[t][j] = 0.f;
    int arow = n0 + (lane & 15);
    int acolsel = 8 * (lane >> 4);
    int brow = m0 + (lane & 7) + 8 * ((lane >> 4) & 1);
    int bksel = 8 * ((lane >> 3) & 1);
#pragma unroll
    for (int ks = 0; ks < 8; ks++) {
        int kg = ks * 16;
        u32 ah[4], bh[4];
        ldmx4(smb + QKH_OFF + (u32)(arow * QK_LD + kg + acolsel) * 2, ah);
        ldmx4(smb + QKH_OFF + (u32)(brow * QK_LD + 128 + kg + bksel) * 2, bh);
        mma16816(sacc[0], ah, bh[0], bh[1]);
        mma16816(sacc[1], ah, bh[2], bh[3]);
    }
}

// ---------------- agg: C[64 n][256 d] = A_hat @ X (X hi + lo) ----------------
__device__ __forceinline__ void agg_tc(char* smc, u32 smb, float cacc[8][4],
                                       int warp, int lane)
{
    int n0 = (warp & 3) * 16;
    int d0 = (warp >> 2) * 64;
#pragma unroll
    for (int t = 0; t < 8; t++)
#pragma unroll
        for (int j = 0; j < 4; j++) cacc[t][j] = 0.f;
    int arow = n0 + (lane & 15);
    int acolsel = 8 * (lane >> 4);
    int xrow = lane & 15;
    int xcol = 8 * (lane >> 4);
#pragma unroll
    for (int ks = 0; ks < 4; ks++) {
        int kg = ks * 16;
        u32 ah[4];
        ldmx4(smb + ABH_OFF + (u32)(arow * AB_LD + kg + acolsel) * 2, ah);
#pragma unroll
        for (int p = 0; p < 4; p++) {
            int xr = kg + xrow;
            int xc = d0 + p * 16 + xcol;
            u32 bh[4], bl[4];
            ldmx4t(smb + XH_OFF + (u32)(xr * X_LD + xc) * 2, bh);
            ldmx4t(smb + XL_OFF + (u32)(xr * X_LD + xc) * 2, bl);
            mma16816(cacc[2 * p], ah, bh[0], bh[1]);
            mma16816(cacc[2 * p], ah, bl[0], bl[1]);
            mma16816(cacc[2 * p + 1], ah, bh[2], bh[3]);
            mma16816(cacc[2 * p + 1], ah, bl[2], bl[3]);
        }
    }
}

// write agg C frags as fp16 hi tiles only (fc reads A hi only)
__device__ __forceinline__ void store_hi_frag(
    char* smc, const float cacc[8][4], int n0, int o0, u32 hoff, int ld, int lane)
{
    int r = n0 + (lane >> 2);
    int cbase = o0 + 2 * (lane & 3);
#pragma unroll
    for (int t = 0; t < 8; t++) {
        int col = cbase + t * 8;
#pragma unroll
        for (int rr = 0; rr < 2; rr++) {
            u32 off = (u32)((r + rr * 8) * ld + col) * 2;
            *(u32*)(smc + hoff + off) = pack_h2(cacc[t][rr * 2], cacc[t][rr * 2 + 1]);
        }
    }
}

// ---------------- LayerNorm -> split fp16 X tiles (hi + lo) ----------------
__device__ __forceinline__ void ln_split(
    char* smc, const float* __restrict__ src, int lds, const float* __restrict__ bias,
    const float* __restrict__ gg, const float* __restrict__ bb, bool leaky, int tid)
{
    int warp = tid >> 5, lane = tid & 31;
    for (int n = warp; n < 64; n += 16) {
        const float* row = src + (size_t)n * lds;
        float v[8];
        float s = 0.f, sq = 0.f;
#pragma unroll
        for (int i = 0; i < 4; i++) {
            int c = 2 * lane + 64 * i;
            float2 t = *(const float2*)(row + c);
            if (bias) {
                float2 bv = *(const float2*)(bias + c);
                t.x += bv.x; t.y += bv.y;
            }
            v[2 * i] = t.x; v[2 * i + 1] = t.y;
            s += t.x + t.y;
            sq += t.x * t.x + t.y * t.y;
        }
#pragma unroll
        for (int off = 16; off > 0; off >>= 1) {
            s += __shfl_xor_sync(0xffffffffu, s, off);
            sq += __shfl_xor_sync(0xffffffffu, sq, off);
        }
        float mean = s * (1.0f / 256.0f);
        float var = sq * (1.0f / 256.0f) - mean * mean;
        float rstd = rsqrtf(var + 1e-5f);
#pragma unroll
        for (int i = 0; i < 4; i++) {
            int c = 2 * lane + 64 * i;
            float o0 = (v[2 * i] - mean) * rstd * gg[c] + bb[c];
            float o1 = (v[2 * i + 1] - mean) * rstd * gg[c + 1] + bb[c + 1];
            if (leaky) {
                o0 = (o0 >= 0.f) ? o0 : 0.1f * o0;
                o1 = (o1 >= 0.f) ? o1 : 0.1f * o1;
            }
            u32 off2 = (u32)(n * X_LD + c) * 2;
            *(u32*)(smc + XH_OFF + off2) = pack_h2(o0, o1);
            *(u32*)(smc + XL_OFF + off2) = pack_l2(o0, o1);
        }
    }
}

// ---------------- prologue kernels ----------------
__global__ void adj_softmax_kernel(const float* __restrict__ adj0,
                                   const float* __restrict__ adj1)
{
    int gw = blockIdx.x * 16 + (threadIdx.x >> 5);
    int lane = threadIdx.x & 31;
    int mat = gw >> 6, r = gw & 63;
    const float* row = (mat ? adj1 : adj0) + r * 64;
    float v0 = row[lane], v1 = row[32 + lane];
    float mx = fmaxf(v0, v1);
#pragma unroll
    for (int off = 16; off > 0; off >>= 1)
        mx = fmaxf(mx, __shfl_xor_sync(0xffffffffu, mx, off));
    float e0 = __expf(v0 - mx), e1 = __expf(v1 - mx);
    float ss = e0 + e1;
#pragma unroll
    for (int off = 16; off > 0; off >>= 1)
        ss += __shfl_xor_sync(0xffffffffu, ss, off);
    float inv = 1.0f / ss;
    float* dst = g_Ast + mat * 4096 + r * 64;
    dst[lane] = e0 * inv;
    dst[32 + lane] = e1 * inv;
}

// split weights into fragment-packed fp16 hi/lo
__global__ void prep_weights(
    const float* __restrict__ th0, const float* __restrict__ ph0, const float* __restrict__ fcw0,
    const float* __restrict__ th1, const float* __restrict__ ph1, const float* __restrict__ fcw1)
{
    int idx = blockIdx.x * blockDim.x + threadIdx.x;  // 0..262143
    int k = idx & 255, r = (idx >> 8) & 255, g = (idx >> 16) & 1, l = idx >> 17;
    const float* th = l ? th1 : th0;
    const float* pw = l ? ph1 : ph0;
    const float* fw = l ? fcw1 : fcw0;
    float v;
    if (g == 0) v = (r < 128) ? th[r * 256 + k] : pw[(r - 128) * 256 + k];
    else        v = fw[r * 256 + k];
    __half hb = __float2half_rn(v);
    __half lb = __float2half_rn(v - __half2float(hb));
    u32 o8 = (u32)(r >> 3);
    u32 kp = (u32)(k >> 5);
    u32 lane = (u32)((r & 7) * 4 + ((k >> 1) & 3));
    u32 slot = (u32)(((k >> 4) & 1) * 2 + ((k >> 3) & 1));
    u32 off16 = ((((o8 * 8 + kp) * 32 + lane) * 4 + slot) << 1) | (u32)(k & 1);
    ((u16*)g_Wf[l][g][0])[off16] = __half_as_ushort(hb);
    ((u16*)g_Wf[l][g][1])[off16] = __half_as_ushort(lb);
}

// ---------------- main kernel ----------------
__global__ void __launch_bounds__(NT, 1) gconv_kernel(
    const float* __restrict__ graph,
    const float* __restrict__ ln_in_g, const float* __restrict__ ln_in_b,
    const float* __restrict__ fcb0,
    const float* __restrict__ ln0_g, const float* __restrict__ ln0_b,
    const float* __restrict__ fcb1,
    float* __restrict__ out)
{
    extern __shared__ char smc[];
    u32 smb = smem_u32(smc);
    int tid = threadIdx.x;
    int warp = tid >> 5, lane = tid & 31;
    int b = blockIdx.x;

    // input LN + split
    ln_split(smc, graph + (size_t)b * 64 * 256, 256, nullptr, ln_in_g, ln_in_b, false, tid);
    __syncthreads();

    float wacc[4][2][4];
    float cacc[8][4];

#pragma unroll 1
    for (int l = 0; l < 2; l++) {
        // ---- qk = X @ W_qk^T (hi-only: softmax-damped path) ----
        wgemm_reg<false>(smb, XH_OFF, g_Wf[l][0][0], g_Wf[l][0][1], wacc, warp, lane);
        wstore_hi(smc, wacc, QKH_OFF, QK_LD, warp, lane);
        __syncthreads();

        // ---- scores = q @ k^T / sqrt(128) ----
        {
            float sacc[2][4];
            scores_tc(smb, sacc, warp, lane);
            const float sscale = 0.08838834764831845f;
            float* abf = (float*)(smc + ABF_OFF);
            int n0 = (warp & 3) * 16;
            int m0 = (warp >> 2) * 16;
            int r = n0 + (lane >> 2);
            int cb = m0 + 2 * (lane & 3);
#pragma unroll
            for (int t = 0; t < 2; t++)
#pragma unroll
                for (int rr = 0; rr < 2; rr++) {
                    float2 p;
                    p.x = sacc[t][rr * 2] * sscale;
                    p.y = sacc[t][rr * 2 + 1] * sscale;
                    *(float2*)(abf + (r + rr * 8) * ABF_LD + cb + t * 8) = p;
                }
        }
        __syncthreads();

        // ---- A_hat = Ast + softmax(scores) -> hi tile ----
        {
            const float* Ast = g_Ast + l * 4096;
            float* abf = (float*)(smc + ABF_OFF);
            u16* abh = (u16*)(smc + ABH_OFF);
            for (int n = warp; n < 64; n += 16) {
                float v0 = abf[n * ABF_LD + lane];
                float v1 = abf[n * ABF_LD + 32 + lane];
                float mx = fmaxf(v0, v1);
#pragma unroll
                for (int off = 16; off > 0; off >>= 1)
                    mx = fmaxf(mx, __shfl_xor_sync(0xffffffffu, mx, off));
                float e0 = __expf(v0 - mx);
                float e1 = __expf(v1 - mx);
                float ss = e0 + e1;
#pragma unroll
                for (int off = 16; off > 0; off >>= 1)
                    ss += __shfl_xor_sync(0xffffffffu, ss, off);
                float inv = 1.0f / ss;
                float a0 = Ast[n * 64 + lane] + e0 * inv;
                float a1 = Ast[n * 64 + 32 + lane] + e1 * inv;
                abh[n * AB_LD + lane]      = __half_as_ushort(__float2half_rn(a0));
                abh[n * AB_LD + 32 + lane] = __half_as_ushort(__float2half_rn(a1));
            }
        }
        __syncthreads();

        // ---- agg = A_hat @ X -> overwrite X hi tiles ----
        agg_tc(smc, smb, cacc, warp, lane);
        __syncthreads();  // all X reads done before overwrite
        store_hi_frag(smc, cacc, (warp & 3) * 16, (warp >> 2) * 64, XH_OFF, X_LD, lane);
        __syncthreads();

        // ---- fc = agg @ W_fc^T (hi+lo) ----
        wgemm_reg<true>(smb, XH_OFF, g_Wf[l][1][0], g_Wf[l][1][1], wacc, warp, lane);
        if (l == 0) {
            wstore_f32(smc, wacc, FC_OFF, FC_LD, warp, lane);
            __syncthreads();
            // LN(fc + bias) + leaky -> new X tiles (hi + lo)
            ln_split(smc, (float*)(smc + FC_OFF), FC_LD, fcb0, ln0_g, ln0_b, true, tid);
            __syncthreads();
        } else {
            // fc + bias -> global out, straight from fragments
            wstore_global(wacc, out + (size_t)b * 64 * 256, fcb1, warp, lane);
        }
    }
}

extern "C" void kernel_launch(void* const* d_in, const int* in_sizes, int n_in,
                              void* d_out, int out_size)
{
    const float* graph   = (const float*)d_in[0];
    const float* ln_in_g = (const float*)d_in[1];
    const float* ln_in_b = (const float*)d_in[2];
    const float* adj0    = (const float*)d_in[3];
    const float* th0     = (const float*)d_in[4];
    const float* ph0     = (const float*)d_in[5];
    const float* fcw0    = (const float*)d_in[6];
    const float* fcb0    = (const float*)d_in[7];
    const float* ln0_g   = (const float*)d_in[8];
    const float* ln0_b   = (const float*)d_in[9];
    const float* adj1    = (const float*)d_in[10];
    const float* th1     = (const float*)d_in[11];
    const float* ph1     = (const float*)d_in[12];
    const float* fcw1    = (const float*)d_in[13];
    const float* fcb1    = (const float*)d_in[14];
    float* out = (float*)d_out;

    cudaFuncSetAttribute(gconv_kernel,
                         cudaFuncAttributeMaxDynamicSharedMemorySize, SMEM_BYTES);

    adj_softmax_kernel<<<8, 512>>>(adj0, adj1);
    prep_weights<<<512, 512>>>(th0, ph0, fcw0, th1, ph1, fcw1);
    gconv_kernel<<<NB, NT, SMEM_BYTES>>>(
        graph, ln_in_g, ln_in_b, fcb0, ln0_g, ln0_b, fcb1, out);
}

// round 10
// speedup vs baseline: 5.8508x; 1.1175x over previous
#include <cuda_runtime.h>
#include <cuda_fp16.h>
#include <math.h>

#define NB 2048
#define NT 512

typedef unsigned long long ull;
typedef unsigned int u32;
typedef unsigned short u16;

// element strides
#define X_LD 264     // fp16 tiles [64][264]
#define QK_LD 264
#define ABF_LD 68    // fp32 scores
#define AB_LD 72     // fp16 A_hat (hi only)
#define FC_LD 260    // fp32 fc-out (layer 0 only)

// smem byte offsets
#define XH_OFF 0
#define XL_OFF 33792
#define QKH_OFF 67584
#define ABH_OFF 101376
#define ABF_OFF 110592
#define FC_OFF 67584         // alias QKH+ABH+ABF (all dead when FC is written)
#define SMEM_BYTES 134144

__device__ float g_Ast[2 * 64 * 64];
// fragment-packed weights: [layer][qk|fc][hi|lo], 131072 B each.
// index: (((o8*8 + kp)*32 + lane)*4 + slot) u32s; slot = (kstep&1)*2 + wsel.
__device__ uint4 g_Wf[2][2][2][8192];

// ---------------- PTX wrappers ----------------
__device__ __forceinline__ u32 smem_u32(const void* p) {
    u32 a;
    asm("{ .reg .u64 t; cvta.to.shared.u64 t, %1; cvt.u32.u64 %0, t; }" : "=r"(a) : "l"(p));
    return a;
}
__device__ __forceinline__ void ldmx4(u32 a, u32 r[4]) {
    asm volatile("ldmatrix.sync.aligned.m8n8.x4.shared.b16 {%0,%1,%2,%3}, [%4];"
                 : "=r"(r[0]), "=r"(r[1]), "=r"(r[2]), "=r"(r[3]) : "r"(a));
}
__device__ __forceinline__ void ldmx4t(u32 a, u32 r[4]) {
    asm volatile("ldmatrix.sync.aligned.m8n8.x4.trans.shared.b16 {%0,%1,%2,%3}, [%4];"
                 : "=r"(r[0]), "=r"(r[1]), "=r"(r[2]), "=r"(r[3]) : "r"(a));
}
__device__ __forceinline__ void mma16816(float d[4], const u32 a[4], u32 b0, u32 b1) {
    asm volatile("mma.sync.aligned.m16n8k16.row.col.f32.f16.f16.f32 "
                 "{%0,%1,%2,%3}, {%4,%5,%6,%7}, {%8,%9}, {%0,%1,%2,%3};"
                 : "+f"(d[0]), "+f"(d[1]), "+f"(d[2]), "+f"(d[3])
                 : "r"(a[0]), "r"(a[1]), "r"(a[2]), "r"(a[3]), "r"(b0), "r"(b1));
}

__device__ __forceinline__ u32 pack_h2(float v0, float v1) {
    __half2 h = __floats2half2_rn(v0, v1);
    return *(u32*)&h;
}
__device__ __forceinline__ u32 pack_l2(float v0, float v1) {
    float h0 = __half2float(__float2half_rn(v0));
    float h1 = __half2float(__float2half_rn(v1));
    __half2 h = __floats2half2_rn(v0 - h0, v1 - h1);
    return *(u32*)&h;
}

// ---------------- weight GEMM: C[64 n][256 o], warp tile 64n x 16o ----------------
// A = X hi tiles from smem (ldmatrix); B = fragment-packed W hi direct from global.
__device__ __forceinline__ void wgemm_reg(
    u32 smb, u32 xh_off, const uint4* __restrict__ wH,
    float acc[4][2][4], int warp, int lane)
{
#pragma unroll
    for (int nf = 0; nf < 4; nf++)
#pragma unroll
        for (int o = 0; o < 2; o++)
#pragma unroll
            for (int j = 0; j < 4; j++) acc[nf][o][j] = 0.f;

    int arow = lane & 15;
    int acol = 8 * (lane >> 4);
    u32 fbase0 = (u32)(((warp * 2 + 0) * 8) * 32 + lane);
    u32 fbase1 = (u32)(((warp * 2 + 1) * 8) * 32 + lane);

    uint4 bh[2];
    bh[0] = wH[fbase0]; bh[1] = wH[fbase1];

#pragma unroll
    for (int kp = 0; kp < 8; kp++) {
        uint4 nh[2];
        if (kp < 7) {
            nh[0] = wH[fbase0 + (kp + 1) * 32]; nh[1] = wH[fbase1 + (kp + 1) * 32];
        }
#pragma unroll
        for (int ks = 0; ks < 2; ks++) {
            int kg = (kp * 2 + ks) * 16;
#pragma unroll
            for (int nf = 0; nf < 4; nf++) {
                u32 ah[4];
                u32 aoff = (u32)((nf * 16 + arow) * X_LD + kg + acol) * 2;
                ldmx4(smb + xh_off + aoff, ah);
#pragma unroll
                for (int o = 0; o < 2; o++) {
                    u32 b0h = ks ? bh[o].z : bh[o].x;
                    u32 b1h = ks ? bh[o].w : bh[o].y;
                    mma16816(acc[nf][o], ah, b0h, b1h);
                }
            }
        }
        if (kp < 7) { bh[0] = nh[0]; bh[1] = nh[1]; }
    }
}

// store wgemm acc as fp16 hi tiles (qk epilogue)
__device__ __forceinline__ void wstore_hi(
    char* smc, const float acc[4][2][4], u32 hoff, int ld, int warp, int lane)
{
    int rb = lane >> 2;
    int cb = warp * 16 + 2 * (lane & 3);
#pragma unroll
    for (int nf = 0; nf < 4; nf++)
#pragma unroll
        for (int o = 0; o < 2; o++)
#pragma unroll
            for (int rr = 0; rr < 2; rr++) {
                int r = nf * 16 + rb + rr * 8;
                int c = cb + o * 8;
                *(u32*)(smc + hoff + (u32)(r * ld + c) * 2) =
                    pack_h2(acc[nf][o][rr * 2], acc[nf][o][rr * 2 + 1]);
            }
}

// store wgemm acc as fp32 to smem (fc epilogue, layer 0)
__device__ __forceinline__ void wstore_f32(
    char* smc, const float acc[4][2][4], u32 foff, int ld, int warp, int lane)
{
    float* f = (float*)(smc + foff);
    int rb = lane >> 2;
    int cb = warp * 16 + 2 * (lane & 3);
#pragma unroll
    for (int nf = 0; nf < 4; nf++)
#pragma unroll
        for (int o = 0; o < 2; o++)
#pragma unroll
            for (int rr = 0; rr < 2; rr++) {
                int r = nf * 16 + rb + rr * 8;
                int c = cb + o * 8;
                *(float2*)(f + r * ld + c) =
                    make_float2(acc[nf][o][rr * 2], acc[nf][o][rr * 2 + 1]);
            }
}

// store wgemm acc + bias directly to global (fc epilogue, layer 1)
__device__ __forceinline__ void wstore_global(
    const float acc[4][2][4], float* __restrict__ og,
    const float* __restrict__ bias, int warp, int lane)
{
    int rb = lane >> 2;
    int cb = warp * 16 + 2 * (lane & 3);
    float b00 = bias[cb], b01 = bias[cb + 1];
    float b10 = bias[cb + 8], b11 = bias[cb + 9];
#pragma unroll
    for (int nf = 0; nf < 4; nf++)
#pragma unroll
        for (int o = 0; o < 2; o++)
#pragma unroll
            for (int rr = 0; rr < 2; rr++) {
                int r = nf * 16 + rb + rr * 8;
                int c = cb + o * 8;
                float2 p;
                p.x = acc[nf][o][rr * 2] + (o ? b10 : b00);
                p.y = acc[nf][o][rr * 2 + 1] + (o ? b11 : b01);
                *(float2*)(og + r * 256 + c) = p;
            }
}

// ---------------- scores: C[64 n][64 m] = q @ k^T (hi only) ----------------
__device__ __forceinline__ void scores_tc(u32 smb, float sacc[2][4], int warp, int lane)
{
    int n0 = (warp & 3) * 16;
    int m0 = (warp >> 2) * 16;
#pragma unroll
    for (int t = 0; t < 2; t++)
#pragma unroll
        for (int j = 0; j < 4; j++) sacc[t][j] = 0.f;
    int arow = n0 + (lane & 15);
    int acolsel = 8 * (lane >> 4);
    int brow = m0 + (lane & 7) + 8 * ((lane >> 4) & 1);
    int bksel = 8 * ((lane >> 3) & 1);
#pragma unroll
    for (int ks = 0; ks < 8; ks++) {
        int kg = ks * 16;
        u32 ah[4], bh[4];
        ldmx4(smb + QKH_OFF + (u32)(arow * QK_LD + kg + acolsel) * 2, ah);
        ldmx4(smb + QKH_OFF + (u32)(brow * QK_LD + 128 + kg + bksel) * 2, bh);
        mma16816(sacc[0], ah, bh[0], bh[1]);
        mma16816(sacc[1], ah, bh[2], bh[3]);
    }
}

// ---------------- agg: C[64 n][256 d] = A_hat @ X (X hi + lo) ----------------
__device__ __forceinline__ void agg_tc(char* smc, u32 smb, float cacc[8][4],
                                       int warp, int lane)
{
    int n0 = (warp & 3) * 16;
    int d0 = (warp >> 2) * 64;
#pragma unroll
    for (int t = 0; t < 8; t++)
#pragma unroll
        for (int j = 0; j < 4; j++) cacc[t][j] = 0.f;
    int arow = n0 + (lane & 15);
    int acolsel = 8 * (lane >> 4);
    int xrow = lane & 15;
    int xcol = 8 * (lane >> 4);
#pragma unroll
    for (int ks = 0; ks < 4; ks++) {
        int kg = ks * 16;
        u32 ah[4];
        ldmx4(smb + ABH_OFF + (u32)(arow * AB_LD + kg + acolsel) * 2, ah);
#pragma unroll
        for (int p = 0; p < 4; p++) {
            int xr = kg + xrow;
            int xc = d0 + p * 16 + xcol;
            u32 bh[4], bl[4];
            ldmx4t(smb + XH_OFF + (u32)(xr * X_LD + xc) * 2, bh);
            ldmx4t(smb + XL_OFF + (u32)(xr * X_LD + xc) * 2, bl);
            mma16816(cacc[2 * p], ah, bh[0], bh[1]);
            mma16816(cacc[2 * p], ah, bl[0], bl[1]);
            mma16816(cacc[2 * p + 1], ah, bh[2], bh[3]);
            mma16816(cacc[2 * p + 1], ah, bl[2], bl[3]);
        }
    }
}

// write agg C frags as fp16 hi tiles only (fc reads A hi only)
__device__ __forceinline__ void store_hi_frag(
    char* smc, const float cacc[8][4], int n0, int o0, u32 hoff, int ld, int lane)
{
    int r = n0 + (lane >> 2);
    int cbase = o0 + 2 * (lane & 3);
#pragma unroll
    for (int t = 0; t < 8; t++) {
        int col = cbase + t * 8;
#pragma unroll
        for (int rr = 0; rr < 2; rr++) {
            u32 off = (u32)((r + rr * 8) * ld + col) * 2;
            *(u32*)(smc + hoff + off) = pack_h2(cacc[t][rr * 2], cacc[t][rr * 2 + 1]);
        }
    }
}

// ---------------- LayerNorm -> split fp16 X tiles (hi + lo) ----------------
__device__ __forceinline__ void ln_split(
    char* smc, const float* __restrict__ src, int lds, const float* __restrict__ bias,
    const float* __restrict__ gg, const float* __restrict__ bb, bool leaky, int tid)
{
    int warp = tid >> 5, lane = tid & 31;
    for (int n = warp; n < 64; n += 16) {
        const float* row = src + (size_t)n * lds;
        float v[8];
        float s = 0.f, sq = 0.f;
#pragma unroll
        for (int i = 0; i < 4; i++) {
            int c = 2 * lane + 64 * i;
            float2 t = *(const float2*)(row + c);
            if (bias) {
                float2 bv = *(const float2*)(bias + c);
                t.x += bv.x; t.y += bv.y;
            }
            v[2 * i] = t.x; v[2 * i + 1] = t.y;
            s += t.x + t.y;
            sq += t.x * t.x + t.y * t.y;
        }
#pragma unroll
        for (int off = 16; off > 0; off >>= 1) {
            s += __shfl_xor_sync(0xffffffffu, s, off);
            sq += __shfl_xor_sync(0xffffffffu, sq, off);
        }
        float mean = s * (1.0f / 256.0f);
        float var = sq * (1.0f / 256.0f) - mean * mean;
        float rstd = rsqrtf(var + 1e-5f);
#pragma unroll
        for (int i = 0; i < 4; i++) {
            int c = 2 * lane + 64 * i;
            float o0 = (v[2 * i] - mean) * rstd * gg[c] + bb[c];
            float o1 = (v[2 * i + 1] - mean) * rstd * gg[c + 1] + bb[c + 1];
            if (leaky) {
                o0 = (o0 >= 0.f) ? o0 : 0.1f * o0;
                o1 = (o1 >= 0.f) ? o1 : 0.1f * o1;
            }
            u32 off2 = (u32)(n * X_LD + c) * 2;
            *(u32*)(smc + XH_OFF + off2) = pack_h2(o0, o1);
            *(u32*)(smc + XL_OFF + off2) = pack_l2(o0, o1);
        }
    }
}

// ---------------- prologue: weights (fragment-packed fp16 hi/lo) + adj softmax ----------------
__global__ void prep_kernel(
    const float* __restrict__ th0, const float* __restrict__ ph0, const float* __restrict__ fcw0,
    const float* __restrict__ th1, const float* __restrict__ ph1, const float* __restrict__ fcw1,
    const float* __restrict__ adj0, const float* __restrict__ adj1)
{
    if (blockIdx.x >= 512) {
        // adjacency softmax: blocks 512..519, 1 row per warp
        int gw = (blockIdx.x - 512) * 16 + (threadIdx.x >> 5);
        int lane = threadIdx.x & 31;
        int mat = gw >> 6, r = gw & 63;
        const float* row = (mat ? adj1 : adj0) + r * 64;
        float v0 = row[lane], v1 = row[32 + lane];
        float mx = fmaxf(v0, v1);
#pragma unroll
        for (int off = 16; off > 0; off >>= 1)
            mx = fmaxf(mx, __shfl_xor_sync(0xffffffffu, mx, off));
        float e0 = __expf(v0 - mx), e1 = __expf(v1 - mx);
        float ss = e0 + e1;
#pragma unroll
        for (int off = 16; off > 0; off >>= 1)
            ss += __shfl_xor_sync(0xffffffffu, ss, off);
        float inv = 1.0f / ss;
        float* dst = g_Ast + mat * 4096 + r * 64;
        dst[lane] = e0 * inv;
        dst[32 + lane] = e1 * inv;
        return;
    }
    int idx = blockIdx.x * 512 + threadIdx.x;  // 0..262143
    int k = idx & 255, r = (idx >> 8) & 255, g = (idx >> 16) & 1, l = idx >> 17;
    const float* th = l ? th1 : th0;
    const float* pw = l ? ph1 : ph0;
    const float* fw = l ? fcw1 : fcw0;
    float v;
    if (g == 0) v = (r < 128) ? th[r * 256 + k] : pw[(r - 128) * 256 + k];
    else        v = fw[r * 256 + k];
    __half hb = __float2half_rn(v);
    __half lb = __float2half_rn(v - __half2float(hb));
    u32 o8 = (u32)(r >> 3);
    u32 kp = (u32)(k >> 5);
    u32 lane = (u32)((r & 7) * 4 + ((k >> 1) & 3));
    u32 slot = (u32)(((k >> 4) & 1) * 2 + ((k >> 3) & 1));
    u32 off16 = ((((o8 * 8 + kp) * 32 + lane) * 4 + slot) << 1) | (u32)(k & 1);
    ((u16*)g_Wf[l][g][0])[off16] = __half_as_ushort(hb);
    ((u16*)g_Wf[l][g][1])[off16] = __half_as_ushort(lb);
}

// ---------------- main kernel ----------------
__global__ void __launch_bounds__(NT, 1) gconv_kernel(
    const float* __restrict__ graph,
    const float* __restrict__ ln_in_g, const float* __restrict__ ln_in_b,
    const float* __restrict__ fcb0,
    const float* __restrict__ ln0_g, const float* __restrict__ ln0_b,
    const float* __restrict__ fcb1,
    float* __restrict__ out)
{
    extern __shared__ char smc[];
    u32 smb = smem_u32(smc);
    int tid = threadIdx.x;
    int warp = tid >> 5, lane = tid & 31;
    int b = blockIdx.x;

    // input LN + split
    ln_split(smc, graph + (size_t)b * 64 * 256, 256, nullptr, ln_in_g, ln_in_b, false, tid);
    __syncthreads();

    float wacc[4][2][4];
    float cacc[8][4];

#pragma unroll 1
    for (int l = 0; l < 2; l++) {
        // ---- qk = X @ W_qk^T (hi-only) ----
        wgemm_reg(smb, XH_OFF, g_Wf[l][0][0], wacc, warp, lane);
        wstore_hi(smc, wacc, QKH_OFF, QK_LD, warp, lane);
        __syncthreads();

        // ---- scores = q @ k^T / sqrt(128) ----
        {
            float sacc[2][4];
            scores_tc(smb, sacc, warp, lane);
            const float sscale = 0.08838834764831845f;
            float* abf = (float*)(smc + ABF_OFF);
            int n0 = (warp & 3) * 16;
            int m0 = (warp >> 2) * 16;
            int r = n0 + (lane >> 2);
            int cb = m0 + 2 * (lane & 3);
#pragma unroll
            for (int t = 0; t < 2; t++)
#pragma unroll
                for (int rr = 0; rr < 2; rr++) {
                    float2 p;
                    p.x = sacc[t][rr * 2] * sscale;
                    p.y = sacc[t][rr * 2 + 1] * sscale;
                    *(float2*)(abf + (r + rr * 8) * ABF_LD + cb + t * 8) = p;
                }
        }
        __syncthreads();

        // ---- A_hat = Ast + softmax(scores) -> hi tile ----
        {
            const float* Ast = g_Ast + l * 4096;
            float* abf = (float*)(smc + ABF_OFF);
            u16* abh = (u16*)(smc + ABH_OFF);
            for (int n = warp; n < 64; n += 16) {
                float v0 = abf[n * ABF_LD + lane];
                float v1 = abf[n * ABF_LD + 32 + lane];
                float mx = fmaxf(v0, v1);
#pragma unroll
                for (int off = 16; off > 0; off >>= 1)
                    mx = fmaxf(mx, __shfl_xor_sync(0xffffffffu, mx, off));
                float e0 = __expf(v0 - mx);
                float e1 = __expf(v1 - mx);
                float ss = e0 + e1;
#pragma unroll
                for (int off = 16; off > 0; off >>= 1)
                    ss += __shfl_xor_sync(0xffffffffu, ss, off);
                float inv = 1.0f / ss;
                float a0 = Ast[n * 64 + lane] + e0 * inv;
                float a1 = Ast[n * 64 + 32 + lane] + e1 * inv;
                abh[n * AB_LD + lane]      = __half_as_ushort(__float2half_rn(a0));
                abh[n * AB_LD + 32 + lane] = __half_as_ushort(__float2half_rn(a1));
            }
        }
        __syncthreads();

        // ---- agg = A_hat @ X -> overwrite X hi tiles ----
        agg_tc(smc, smb, cacc, warp, lane);
        __syncthreads();  // all X reads done before overwrite
        store_hi_frag(smc, cacc, (warp & 3) * 16, (warp >> 2) * 64, XH_OFF, X_LD, lane);
        __syncthreads();

        // ---- fc = agg @ W_fc^T (hi-only) ----
        wgemm_reg(smb, XH_OFF, g_Wf[l][1][0], wacc, warp, lane);
        if (l == 0) {
            wstore_f32(smc, wacc, FC_OFF, FC_LD, warp, lane);
            __syncthreads();
            // LN(fc + bias) + leaky -> new X tiles (hi + lo)
            ln_split(smc, (float*)(smc + FC_OFF), FC_LD, fcb0, ln0_g, ln0_b, true, tid);
            __syncthreads();
        } else {
            // fc + bias -> global out, straight from fragments
            wstore_global(wacc, out + (size_t)b * 64 * 256, fcb1, warp, lane);
        }
    }
}

extern "C" void kernel_launch(void* const* d_in, const int* in_sizes, int n_in,
                              void* d_out, int out_size)
{
    const float* graph   = (const float*)d_in[0];
    const float* ln_in_g = (const float*)d_in[1];
    const float* ln_in_b = (const float*)d_in[2];
    const float* adj0    = (const float*)d_in[3];
    const float* th0     = (const float*)d_in[4];
    const float* ph0     = (const float*)d_in[5];
    const float* fcw0    = (const float*)d_in[6];
    const float* fcb0    = (const float*)d_in[7];
    const float* ln0_g   = (const float*)d_in[8];
    const float* ln0_b   = (const float*)d_in[9];
    const float* adj1    = (const float*)d_in[10];
    const float* th1     = (const float*)d_in[11];
    const float* ph1     = (const float*)d_in[12];
    const float* fcw1    = (const float*)d_in[13];
    const float* fcb1    = (const float*)d_in[14];
    float* out = (float*)d_out;

    cudaFuncSetAttribute(gconv_kernel,
                         cudaFuncAttributeMaxDynamicSharedMemorySize, SMEM_BYTES);

    prep_kernel<<<520, 512>>>(th0, ph0, fcw0, th1, ph1, fcw1, adj0, adj1);
    gconv_kernel<<<NB, NT, SMEM_BYTES>>>(
        graph, ln_in_g, ln_in_b, fcb0, ln0_g, ln0_b, fcb1, out);
}

// round 11
// speedup vs baseline: 6.4437x; 1.1013x over previous
#include <cuda_runtime.h>
#include <cuda_fp16.h>
#include <math.h>

#define NB 2048
#define NT 512

typedef unsigned long long ull;
typedef unsigned int u32;
typedef unsigned short u16;

// element strides
#define X_LD 264     // fp16 X tile [64][264]
#define QK_LD 264
#define ABF_LD 68    // fp32 scores
#define AB_LD 72     // fp16 A_hat
#define FC_LD 260    // fp32 fc-out (layer 0 only)

// smem byte offsets
#define XH_OFF 0
#define QKH_OFF 33792
#define ABH_OFF 67584
#define ABF_OFF 76800
#define FC_OFF 33792         // alias QKH+ABH+ABF (all dead when FC is written)
#define SMEM_BYTES 100352

__device__ float g_Ast[2 * 64 * 64];
// fragment-packed fp16 weights (hi, lo kept for possible fallback but only hi used):
// index: (((o8*8 + kp)*32 + lane)) uint4; .x/.y = kstep0 b0/b1, .z/.w = kstep1.
__device__ uint4 g_Wf[2][2][2][8192];

// ---------------- PTX wrappers ----------------
__device__ __forceinline__ u32 smem_u32(const void* p) {
    u32 a;
    asm("{ .reg .u64 t; cvta.to.shared.u64 t, %1; cvt.u32.u64 %0, t; }" : "=r"(a) : "l"(p));
    return a;
}
__device__ __forceinline__ void ldmx4(u32 a, u32 r[4]) {
    asm volatile("ldmatrix.sync.aligned.m8n8.x4.shared.b16 {%0,%1,%2,%3}, [%4];"
                 : "=r"(r[0]), "=r"(r[1]), "=r"(r[2]), "=r"(r[3]) : "r"(a));
}
__device__ __forceinline__ void ldmx4t(u32 a, u32 r[4]) {
    asm volatile("ldmatrix.sync.aligned.m8n8.x4.trans.shared.b16 {%0,%1,%2,%3}, [%4];"
                 : "=r"(r[0]), "=r"(r[1]), "=r"(r[2]), "=r"(r[3]) : "r"(a));
}
__device__ __forceinline__ void mma16816(float d[4], const u32 a[4], u32 b0, u32 b1) {
    asm volatile("mma.sync.aligned.m16n8k16.row.col.f32.f16.f16.f32 "
                 "{%0,%1,%2,%3}, {%4,%5,%6,%7}, {%8,%9}, {%0,%1,%2,%3};"
                 : "+f"(d[0]), "+f"(d[1]), "+f"(d[2]), "+f"(d[3])
                 : "r"(a[0]), "r"(a[1]), "r"(a[2]), "r"(a[3]), "r"(b0), "r"(b1));
}

__device__ __forceinline__ u32 pack_h2(float v0, float v1) {
    __half2 h = __floats2half2_rn(v0, v1);
    return *(u32*)&h;
}

// ---------------- weight GEMM: C[64 n][256 o], warp tile 32n x 32o ----------------
// warp grid: wn = warp&1 (n half), wo = warp>>1 (o group of 32).
// A = X tile from smem (ldmatrix); B = fragment-packed W hi direct from global.
__device__ __forceinline__ void wgemm_reg(
    u32 smb, u32 xh_off, const uint4* __restrict__ wH,
    float acc[2][4][4], int warp, int lane)
{
#pragma unroll
    for (int nf = 0; nf < 2; nf++)
#pragma unroll
        for (int of = 0; of < 4; of++)
#pragma unroll
            for (int j = 0; j < 4; j++) acc[nf][of][j] = 0.f;

    int wn = warp & 1, wo = warp >> 1;
    int arow0 = wn * 32 + (lane & 15);
    int acol = 8 * (lane >> 4);
    u32 fb[4];
#pragma unroll
    for (int of = 0; of < 4; of++)
        fb[of] = (u32)(((wo * 4 + of) * 8) * 32 + lane);

    uint4 bh[4];
#pragma unroll
    for (int of = 0; of < 4; of++) bh[of] = wH[fb[of]];

#pragma unroll
    for (int kp = 0; kp < 8; kp++) {
        uint4 nh[4];
        if (kp < 7) {
#pragma unroll
            for (int of = 0; of < 4; of++) nh[of] = wH[fb[of] + (kp + 1) * 32];
        }
#pragma unroll
        for (int ks = 0; ks < 2; ks++) {
            int kg = (kp * 2 + ks) * 16;
#pragma unroll
            for (int nf = 0; nf < 2; nf++) {
                u32 ah[4];
                u32 aoff = (u32)((nf * 16 + arow0) * X_LD + kg + acol) * 2;
                ldmx4(smb + xh_off + aoff, ah);
#pragma unroll
                for (int of = 0; of < 4; of++) {
                    u32 b0 = ks ? bh[of].z : bh[of].x;
                    u32 b1 = ks ? bh[of].w : bh[of].y;
                    mma16816(acc[nf][of], ah, b0, b1);
                }
            }
        }
        if (kp < 7) {
#pragma unroll
            for (int of = 0; of < 4; of++) bh[of] = nh[of];
        }
    }
}

// store wgemm acc as fp16 tiles (qk epilogue)
__device__ __forceinline__ void wstore_hi(
    char* smc, const float acc[2][4][4], u32 hoff, int ld, int warp, int lane)
{
    int wn = warp & 1, wo = warp >> 1;
    int rb = wn * 32 + (lane >> 2);
    int cb = wo * 32 + 2 * (lane & 3);
#pragma unroll
    for (int nf = 0; nf < 2; nf++)
#pragma unroll
        for (int of = 0; of < 4; of++)
#pragma unroll
            for (int rr = 0; rr < 2; rr++) {
                int r = rb + nf * 16 + rr * 8;
                int c = cb + of * 8;
                *(u32*)(smc + hoff + (u32)(r * ld + c) * 2) =
                    pack_h2(acc[nf][of][rr * 2], acc[nf][of][rr * 2 + 1]);
            }
}

// store wgemm acc as fp32 to smem (fc epilogue, layer 0)
__device__ __forceinline__ void wstore_f32(
    char* smc, const float acc[2][4][4], u32 foff, int ld, int warp, int lane)
{
    float* f = (float*)(smc + foff);
    int wn = warp & 1, wo = warp >> 1;
    int rb = wn * 32 + (lane >> 2);
    int cb = wo * 32 + 2 * (lane & 3);
#pragma unroll
    for (int nf = 0; nf < 2; nf++)
#pragma unroll
        for (int of = 0; of < 4; of++)
#pragma unroll
            for (int rr = 0; rr < 2; rr++) {
                int r = rb + nf * 16 + rr * 8;
                int c = cb + of * 8;
                *(float2*)(f + r * ld + c) =
                    make_float2(acc[nf][of][rr * 2], acc[nf][of][rr * 2 + 1]);
            }
}

// store wgemm acc + bias directly to global (fc epilogue, layer 1)
__device__ __forceinline__ void wstore_global(
    const float acc[2][4][4], float* __restrict__ og,
    const float* __restrict__ bias, int warp, int lane)
{
    int wn = warp & 1, wo = warp >> 1;
    int rb = wn * 32 + (lane >> 2);
    int cb = wo * 32 + 2 * (lane & 3);
    float bv[4][2];
#pragma unroll
    for (int of = 0; of < 4; of++) {
        bv[of][0] = bias[cb + of * 8];
        bv[of][1] = bias[cb + of * 8 + 1];
    }
#pragma unroll
    for (int nf = 0; nf < 2; nf++)
#pragma unroll
        for (int of = 0; of < 4; of++)
#pragma unroll
            for (int rr = 0; rr < 2; rr++) {
                int r = rb + nf * 16 + rr * 8;
                int c = cb + of * 8;
                float2 p;
                p.x = acc[nf][of][rr * 2] + bv[of][0];
                p.y = acc[nf][of][rr * 2 + 1] + bv[of][1];
                *(float2*)(og + r * 256 + c) = p;
            }
}

// ---------------- scores: C[64 n][64 m] = q @ k^T ----------------
__device__ __forceinline__ void scores_tc(u32 smb, float sacc[2][4], int warp, int lane)
{
    int n0 = (warp & 3) * 16;
    int m0 = (warp >> 2) * 16;
#pragma unroll
    for (int t = 0; t < 2; t++)
#pragma unroll
        for (int j = 0; j < 4; j++) sacc[t][j] = 0.f;
    int arow = n0 + (lane & 15);
    int acolsel = 8 * (lane >> 4);
    int brow = m0 + (lane & 7) + 8 * ((lane >> 4) & 1);
    int bksel = 8 * ((lane >> 3) & 1);
#pragma unroll
    for (int ks = 0; ks < 8; ks++) {
        int kg = ks * 16;
        u32 ah[4], bh[4];
        ldmx4(smb + QKH_OFF + (u32)(arow * QK_LD + kg + acolsel) * 2, ah);
        ldmx4(smb + QKH_OFF + (u32)(brow * QK_LD + 128 + kg + bksel) * 2, bh);
        mma16816(sacc[0], ah, bh[0], bh[1]);
        mma16816(sacc[1], ah, bh[2], bh[3]);
    }
}

// ---------------- agg: C[64 n][256 d] = A_hat @ X (fp16) ----------------
__device__ __forceinline__ void agg_tc(char* smc, u32 smb, float cacc[8][4],
                                       int warp, int lane)
{
    int n0 = (warp & 3) * 16;
    int d0 = (warp >> 2) * 64;
#pragma unroll
    for (int t = 0; t < 8; t++)
#pragma unroll
        for (int j = 0; j < 4; j++) cacc[t][j] = 0.f;
    int arow = n0 + (lane & 15);
    int acolsel = 8 * (lane >> 4);
    int xrow = lane & 15;
    int xcol = 8 * (lane >> 4);
#pragma unroll
    for (int ks = 0; ks < 4; ks++) {
        int kg = ks * 16;
        u32 ah[4];
        ldmx4(smb + ABH_OFF + (u32)(arow * AB_LD + kg + acolsel) * 2, ah);
#pragma unroll
        for (int p = 0; p < 4; p++) {
            int xr = kg + xrow;
            int xc = d0 + p * 16 + xcol;
            u32 bh[4];
            ldmx4t(smb + XH_OFF + (u32)(xr * X_LD + xc) * 2, bh);
            mma16816(cacc[2 * p], ah, bh[0], bh[1]);
            mma16816(cacc[2 * p + 1], ah, bh[2], bh[3]);
        }
    }
}

// write agg C frags as fp16 tiles
__device__ __forceinline__ void store_hi_frag(
    char* smc, const float cacc[8][4], int n0, int o0, u32 hoff, int ld, int lane)
{
    int r = n0 + (lane >> 2);
    int cbase = o0 + 2 * (lane & 3);
#pragma unroll
    for (int t = 0; t < 8; t++) {
        int col = cbase + t * 8;
#pragma unroll
        for (int rr = 0; rr < 2; rr++) {
            u32 off = (u32)((r + rr * 8) * ld + col) * 2;
            *(u32*)(smc + hoff + off) = pack_h2(cacc[t][rr * 2], cacc[t][rr * 2 + 1]);
        }
    }
}

// ---------------- LayerNorm -> fp16 X tile ----------------
__device__ __forceinline__ void ln_split(
    char* smc, const float* __restrict__ src, int lds, const float* __restrict__ bias,
    const float* __restrict__ gg, const float* __restrict__ bb, bool leaky, int tid)
{
    int warp = tid >> 5, lane = tid & 31;
    for (int n = warp; n < 64; n += 16) {
        const float* row = src + (size_t)n * lds;
        float v[8];
        float s = 0.f, sq = 0.f;
#pragma unroll
        for (int i = 0; i < 4; i++) {
            int c = 2 * lane + 64 * i;
            float2 t = *(const float2*)(row + c);
            if (bias) {
                float2 bv = *(const float2*)(bias + c);
                t.x += bv.x; t.y += bv.y;
            }
            v[2 * i] = t.x; v[2 * i + 1] = t.y;
            s += t.x + t.y;
            sq += t.x * t.x + t.y * t.y;
        }
#pragma unroll
        for (int off = 16; off > 0; off >>= 1) {
            s += __shfl_xor_sync(0xffffffffu, s, off);
            sq += __shfl_xor_sync(0xffffffffu, sq, off);
        }
        float mean = s * (1.0f / 256.0f);
        float var = sq * (1.0f / 256.0f) - mean * mean;
        float rstd = rsqrtf(var + 1e-5f);
#pragma unroll
        for (int i = 0; i < 4; i++) {
            int c = 2 * lane + 64 * i;
            float o0 = (v[2 * i] - mean) * rstd * gg[c] + bb[c];
            float o1 = (v[2 * i + 1] - mean) * rstd * gg[c + 1] + bb[c + 1];
            if (leaky) {
                o0 = (o0 >= 0.f) ? o0 : 0.1f * o0;
                o1 = (o1 >= 0.f) ? o1 : 0.1f * o1;
            }
            *(u32*)(smc + XH_OFF + (u32)(n * X_LD + c) * 2) = pack_h2(o0, o1);
        }
    }
}

// ---------------- prologue: weights (fragment-packed fp16 hi/lo) + adj softmax ----------------
__global__ void prep_kernel(
    const float* __restrict__ th0, const float* __restrict__ ph0, const float* __restrict__ fcw0,
    const float* __restrict__ th1, const float* __restrict__ ph1, const float* __restrict__ fcw1,
    const float* __restrict__ adj0, const float* __restrict__ adj1)
{
    if (blockIdx.x >= 512) {
        int gw = (blockIdx.x - 512) * 16 + (threadIdx.x >> 5);
        int lane = threadIdx.x & 31;
        int mat = gw >> 6, r = gw & 63;
        const float* row = (mat ? adj1 : adj0) + r * 64;
        float v0 = row[lane], v1 = row[32 + lane];
        float mx = fmaxf(v0, v1);
#pragma unroll
        for (int off = 16; off > 0; off >>= 1)
            mx = fmaxf(mx, __shfl_xor_sync(0xffffffffu, mx, off));
        float e0 = __expf(v0 - mx), e1 = __expf(v1 - mx);
        float ss = e0 + e1;
#pragma unroll
        for (int off = 16; off > 0; off >>= 1)
            ss += __shfl_xor_sync(0xffffffffu, ss, off);
        float inv = 1.0f / ss;
        float* dst = g_Ast + mat * 4096 + r * 64;
        dst[lane] = e0 * inv;
        dst[32 + lane] = e1 * inv;
        return;
    }
    int idx = blockIdx.x * 512 + threadIdx.x;  // 0..262143
    int k = idx & 255, r = (idx >> 8) & 255, g = (idx >> 16) & 1, l = idx >> 17;
    const float* th = l ? th1 : th0;
    const float* pw = l ? ph1 : ph0;
    const float* fw = l ? fcw1 : fcw0;
    float v;
    if (g == 0) v = (r < 128) ? th[r * 256 + k] : pw[(r - 128) * 256 + k];
    else        v = fw[r * 256 + k];
    __half hb = __float2half_rn(v);
    __half lb = __float2half_rn(v - __half2float(hb));
    u32 o8 = (u32)(r >> 3);
    u32 kp = (u32)(k >> 5);
    u32 lane = (u32)((r & 7) * 4 + ((k >> 1) & 3));
    u32 slot = (u32)(((k >> 4) & 1) * 2 + ((k >> 3) & 1));
    u32 off16 = ((((o8 * 8 + kp) * 32 + lane) * 4 + slot) << 1) | (u32)(k & 1);
    ((u16*)g_Wf[l][g][0])[off16] = __half_as_ushort(hb);
    ((u16*)g_Wf[l][g][1])[off16] = __half_as_ushort(lb);
}

// ---------------- main kernel ----------------
__global__ void __launch_bounds__(NT, 1) gconv_kernel(
    const float* __restrict__ graph,
    const float* __restrict__ ln_in_g, const float* __restrict__ ln_in_b,
    const float* __restrict__ fcb0,
    const float* __restrict__ ln0_g, const float* __restrict__ ln0_b,
    const float* __restrict__ fcb1,
    float* __restrict__ out)
{
    extern __shared__ char smc[];
    u32 smb = smem_u32(smc);
    int tid = threadIdx.x;
    int warp = tid >> 5, lane = tid & 31;
    int b = blockIdx.x;

    // input LN
    ln_split(smc, graph + (size_t)b * 64 * 256, 256, nullptr, ln_in_g, ln_in_b, false, tid);
    __syncthreads();

    float wacc[2][4][4];
    float cacc[8][4];

#pragma unroll 1
    for (int l = 0; l < 2; l++) {
        // ---- qk = X @ W_qk^T ----
        wgemm_reg(smb, XH_OFF, g_Wf[l][0][0], wacc, warp, lane);
        wstore_hi(smc, wacc, QKH_OFF, QK_LD, warp, lane);
        __syncthreads();

        // ---- scores = q @ k^T / sqrt(128) ----
        {
            float sacc[2][4];
            scores_tc(smb, sacc, warp, lane);
            const float sscale = 0.08838834764831845f;
            float* abf = (float*)(smc + ABF_OFF);
            int n0 = (warp & 3) * 16;
            int m0 = (warp >> 2) * 16;
            int r = n0 + (lane >> 2);
            int cb = m0 + 2 * (lane & 3);
#pragma unroll
            for (int t = 0; t < 2; t++)
#pragma unroll
                for (int rr = 0; rr < 2; rr++) {
                    float2 p;
                    p.x = sacc[t][rr * 2] * sscale;
                    p.y = sacc[t][rr * 2 + 1] * sscale;
                    *(float2*)(abf + (r + rr * 8) * ABF_LD + cb + t * 8) = p;
                }
        }
        __syncthreads();

        // ---- A_hat = Ast + softmax(scores) -> fp16 tile ----
        {
            const float* Ast = g_Ast + l * 4096;
            float* abf = (float*)(smc + ABF_OFF);
            u16* abh = (u16*)(smc + ABH_OFF);
            for (int n = warp; n < 64; n += 16) {
                float v0 = abf[n * ABF_LD + lane];
                float v1 = abf[n * ABF_LD + 32 + lane];
                float mx = fmaxf(v0, v1);
#pragma unroll
                for (int off = 16; off > 0; off >>= 1)
                    mx = fmaxf(mx, __shfl_xor_sync(0xffffffffu, mx, off));
                float e0 = __expf(v0 - mx);
                float e1 = __expf(v1 - mx);
                float ss = e0 + e1;
#pragma unroll
                for (int off = 16; off > 0; off >>= 1)
                    ss += __shfl_xor_sync(0xffffffffu, ss, off);
                float inv = 1.0f / ss;
                float a0 = Ast[n * 64 + lane] + e0 * inv;
                float a1 = Ast[n * 64 + 32 + lane] + e1 * inv;
                abh[n * AB_LD + lane]      = __half_as_ushort(__float2half_rn(a0));
                abh[n * AB_LD + 32 + lane] = __half_as_ushort(__float2half_rn(a1));
            }
        }
        __syncthreads();

        // ---- agg = A_hat @ X -> overwrite X tile ----
        agg_tc(smc, smb, cacc, warp, lane);
        __syncthreads();  // all X reads done before overwrite
        store_hi_frag(smc, cacc, (warp & 3) * 16, (warp >> 2) * 64, XH_OFF, X_LD, lane);
        __syncthreads();

        // ---- fc = agg @ W_fc^T ----
        wgemm_reg(smb, XH_OFF, g_Wf[l][1][0], wacc, warp, lane);
        if (l == 0) {
            wstore_f32(smc, wacc, FC_OFF, FC_LD, warp, lane);
            __syncthreads();
            ln_split(smc, (float*)(smc + FC_OFF), FC_LD, fcb0, ln0_g, ln0_b, true, tid);
            __syncthreads();
        } else {
            wstore_global(wacc, out + (size_t)b * 64 * 256, fcb1, warp, lane);
        }
    }
}

extern "C" void kernel_launch(void* const* d_in, const int* in_sizes, int n_in,
                              void* d_out, int out_size)
{
    const float* graph   = (const float*)d_in[0];
    const float* ln_in_g = (const float*)d_in[1];
    const float* ln_in_b = (const float*)d_in[2];
    const float* adj0    = (const float*)d_in[3];
    const float* th0     = (const float*)d_in[4];
    const float* ph0     = (const float*)d_in[5];
    const float* fcw0    = (const float*)d_in[6];
    const float* fcb0    = (const float*)d_in[7];
    const float* ln0_g   = (const float*)d_in[8];
    const float* ln0_b   = (const float*)d_in[9];
    const float* adj1    = (const float*)d_in[10];
    const float* th1     = (const float*)d_in[11];
    const float* ph1     = (const float*)d_in[12];
    const float* fcw1    = (const float*)d_in[13];
    const float* fcb1    = (const float*)d_in[14];
    float* out = (float*)d_out;

    cudaFuncSetAttribute(gconv_kernel,
                         cudaFuncAttributeMaxDynamicSharedMemorySize, SMEM_BYTES);

    prep_kernel<<<520, 512>>>(th0, ph0, fcw0, th1, ph1, fcw1, adj0, adj1);
    gconv_kernel<<<NB, NT, SMEM_BYTES>>>(
        graph, ln_in_g, ln_in_b, fcb0, ln0_g, ln0_b, fcb1, out);
}

// round 12
// speedup vs baseline: 7.7586x; 1.2041x over previous
#include <cuda_runtime.h>
#include <cuda_fp16.h>
#include <math.h>

#define NB 2048
#define NT 256

typedef unsigned int u32;
typedef unsigned short u16;

// element strides
#define X_LD 264     // fp16 X tile [64][264]
#define QK_LD 264
#define ABF_LD 68    // fp32 scores
#define AB_LD 72     // fp16 A_hat
#define FC_LD 260    // fp32 fc-out (layer 0 only)

// smem byte offsets
#define XH_OFF 0
#define QKH_OFF 33792
#define ABH_OFF 67584
#define ABF_OFF 76800
#define FC_OFF 33792         // alias QKH+ABH+ABF (all dead when FC is written)
#define SMEM_BYTES 100352

__device__ float g_Ast[2 * 64 * 64];
// fragment-packed fp16 weights: index (((o8*8 + kp)*32 + lane)) uint4;
// .x/.y = kstep0 b0/b1, .z/.w = kstep1. [layer][qk|fc][hi|lo]
__device__ uint4 g_Wf[2][2][2][8192];

// ---------------- PTX wrappers ----------------
__device__ __forceinline__ u32 smem_u32(const void* p) {
    u32 a;
    asm("{ .reg .u64 t; cvta.to.shared.u64 t, %1; cvt.u32.u64 %0, t; }" : "=r"(a) : "l"(p));
    return a;
}
__device__ __forceinline__ void ldmx4(u32 a, u32 r[4]) {
    asm volatile("ldmatrix.sync.aligned.m8n8.x4.shared.b16 {%0,%1,%2,%3}, [%4];"
                 : "=r"(r[0]), "=r"(r[1]), "=r"(r[2]), "=r"(r[3]) : "r"(a));
}
__device__ __forceinline__ void ldmx4t(u32 a, u32 r[4]) {
    asm volatile("ldmatrix.sync.aligned.m8n8.x4.trans.shared.b16 {%0,%1,%2,%3}, [%4];"
                 : "=r"(r[0]), "=r"(r[1]), "=r"(r[2]), "=r"(r[3]) : "r"(a));
}
__device__ __forceinline__ void mma16816(float* d, const u32 a[4], u32 b0, u32 b1) {
    asm volatile("mma.sync.aligned.m16n8k16.row.col.f32.f16.f16.f32 "
                 "{%0,%1,%2,%3}, {%4,%5,%6,%7}, {%8,%9}, {%0,%1,%2,%3};"
                 : "+f"(d[0]), "+f"(d[1]), "+f"(d[2]), "+f"(d[3])
                 : "r"(a[0]), "r"(a[1]), "r"(a[2]), "r"(a[3]), "r"(b0), "r"(b1));
}

__device__ __forceinline__ u32 pack_h2(float v0, float v1) {
    __half2 h = __floats2half2_rn(v0, v1);
    return *(u32*)&h;
}

// ---------------- weight GEMM: C[64 n][256 o], 8 warps, warp tile 64n x 32o ----------------
// acc layout: acc[(nf*4 + of)*4 + j], nf = 16n frag, of = 8o frag.
__device__ __forceinline__ void wgemm_reg(
    u32 smb, u32 xh_off, const uint4* __restrict__ wH,
    float* acc, int warp, int lane)
{
#pragma unroll
    for (int i = 0; i < 64; i++) acc[i] = 0.f;

    int arow = lane & 15;
    int acol = 8 * (lane >> 4);
    u32 fb = (u32)((warp * 4 * 8) * 32 + lane);  // of stride = 8*32 = 256

    uint4 bh[4];
#pragma unroll
    for (int of = 0; of < 4; of++) bh[of] = wH[fb + of * 256];

#pragma unroll
    for (int kp = 0; kp < 8; kp++) {
        uint4 nh[4];
        if (kp < 7) {
#pragma unroll
            for (int of = 0; of < 4; of++) nh[of] = wH[fb + of * 256 + (kp + 1) * 32];
        }
#pragma unroll
        for (int ks = 0; ks < 2; ks++) {
            int kg = (kp * 2 + ks) * 16;
#pragma unroll
            for (int nf = 0; nf < 4; nf++) {
                u32 ah[4];
                u32 aoff = (u32)((nf * 16 + arow) * X_LD + kg + acol) * 2;
                ldmx4(smb + xh_off + aoff, ah);
#pragma unroll
                for (int of = 0; of < 4; of++) {
                    u32 b0 = ks ? bh[of].z : bh[of].x;
                    u32 b1 = ks ? bh[of].w : bh[of].y;
                    mma16816(acc + (nf * 4 + of) * 4, ah, b0, b1);
                }
            }
        }
        if (kp < 7) {
#pragma unroll
            for (int of = 0; of < 4; of++) bh[of] = nh[of];
        }
    }
}

// store wgemm acc as fp16 tiles (qk epilogue)
__device__ __forceinline__ void wstore_hi(
    char* smc, const float* acc, u32 hoff, int ld, int warp, int lane)
{
    int rb = lane >> 2;
    int cb = warp * 32 + 2 * (lane & 3);
#pragma unroll
    for (int nf = 0; nf < 4; nf++)
#pragma unroll
        for (int of = 0; of < 4; of++)
#pragma unroll
            for (int rr = 0; rr < 2; rr++) {
                int r = nf * 16 + rb + rr * 8;
                int c = cb + of * 8;
                const float* a = acc + (nf * 4 + of) * 4;
                *(u32*)(smc + hoff + (u32)(r * ld + c) * 2) =
                    pack_h2(a[rr * 2], a[rr * 2 + 1]);
            }
}

// store wgemm acc as fp32 to smem (fc epilogue, layer 0)
__device__ __forceinline__ void wstore_f32(
    char* smc, const float* acc, u32 foff, int ld, int warp, int lane)
{
    float* f = (float*)(smc + foff);
    int rb = lane >> 2;
    int cb = warp * 32 + 2 * (lane & 3);
#pragma unroll
    for (int nf = 0; nf < 4; nf++)
#pragma unroll
        for (int of = 0; of < 4; of++)
#pragma unroll
            for (int rr = 0; rr < 2; rr++) {
                int r = nf * 16 + rb + rr * 8;
                int c = cb + of * 8;
                const float* a = acc + (nf * 4 + of) * 4;
                *(float2*)(f + r * ld + c) = make_float2(a[rr * 2], a[rr * 2 + 1]);
            }
}

// store wgemm acc + bias directly to global (fc epilogue, layer 1)
__device__ __forceinline__ void wstore_global(
    const float* acc, float* __restrict__ og,
    const float* __restrict__ bias, int warp, int lane)
{
    int rb = lane >> 2;
    int cb = warp * 32 + 2 * (lane & 3);
    float bv[4][2];
#pragma unroll
    for (int of = 0; of < 4; of++) {
        bv[of][0] = bias[cb + of * 8];
        bv[of][1] = bias[cb + of * 8 + 1];
    }
#pragma unroll
    for (int nf = 0; nf < 4; nf++)
#pragma unroll
        for (int of = 0; of < 4; of++)
#pragma unroll
            for (int rr = 0; rr < 2; rr++) {
                int r = nf * 16 + rb + rr * 8;
                int c = cb + of * 8;
                const float* a = acc + (nf * 4 + of) * 4;
                float2 p;
                p.x = a[rr * 2] + bv[of][0];
                p.y = a[rr * 2 + 1] + bv[of][1];
                *(float2*)(og + r * 256 + c) = p;
            }
}

// ---------------- scores: C[64 n][64 m] = q @ k^T, 8 warps, tile 16n x 32m ----------------
__device__ __forceinline__ void scores_tc(u32 smb, float sacc[4][4], int warp, int lane)
{
    int n0 = (warp & 3) * 16;
    int m0 = (warp >> 2) * 32;
#pragma unroll
    for (int t = 0; t < 4; t++)
#pragma unroll
        for (int j = 0; j < 4; j++) sacc[t][j] = 0.f;
    int arow = n0 + (lane & 15);
    int acolsel = 8 * (lane >> 4);
    int brow0 = m0 + (lane & 7) + 8 * ((lane >> 4) & 1);
    int bksel = 8 * ((lane >> 3) & 1);
#pragma unroll
    for (int ks = 0; ks < 8; ks++) {
        int kg = ks * 16;
        u32 ah[4], bh0[4], bh1[4];
        ldmx4(smb + QKH_OFF + (u32)(arow * QK_LD + kg + acolsel) * 2, ah);
        ldmx4(smb + QKH_OFF + (u32)(brow0 * QK_LD + 128 + kg + bksel) * 2, bh0);
        ldmx4(smb + QKH_OFF + (u32)((brow0 + 16) * QK_LD + 128 + kg + bksel) * 2, bh1);
        mma16816(sacc[0], ah, bh0[0], bh0[1]);
        mma16816(sacc[1], ah, bh0[2], bh0[3]);
        mma16816(sacc[2], ah, bh1[0], bh1[1]);
        mma16816(sacc[3], ah, bh1[2], bh1[3]);
    }
}

// ---------------- agg: C[64 n][256 d] = A_hat @ X, 8 warps, tile 16n x 128d ----------------
// acc layout: acc[t*4 + j], t = 2*p + half, p = 16d group.
__device__ __forceinline__ void agg_tc(char* smc, u32 smb, float* acc,
                                       int warp, int lane)
{
    int n0 = (warp & 3) * 16;
    int d0 = (warp >> 2) * 128;
#pragma unroll
    for (int i = 0; i < 64; i++) acc[i] = 0.f;
    int arow = n0 + (lane & 15);
    int acolsel = 8 * (lane >> 4);
    int xrow = lane & 15;
    int xcol = 8 * (lane >> 4);
#pragma unroll
    for (int ks = 0; ks < 4; ks++) {
        int kg = ks * 16;
        u32 ah[4];
        ldmx4(smb + ABH_OFF + (u32)(arow * AB_LD + kg + acolsel) * 2, ah);
#pragma unroll
        for (int p = 0; p < 8; p++) {
            int xr = kg + xrow;
            int xc = d0 + p * 16 + xcol;
            u32 bh[4];
            ldmx4t(smb + XH_OFF + (u32)(xr * X_LD + xc) * 2, bh);
            mma16816(acc + (2 * p) * 4, ah, bh[0], bh[1]);
            mma16816(acc + (2 * p + 1) * 4, ah, bh[2], bh[3]);
        }
    }
}

// write agg C frags as fp16 tiles
__device__ __forceinline__ void store_hi_frag(
    char* smc, const float* acc, int n0, int o0, u32 hoff, int ld, int lane)
{
    int r = n0 + (lane >> 2);
    int cbase = o0 + 2 * (lane & 3);
#pragma unroll
    for (int t = 0; t < 16; t++) {
        int col = cbase + t * 8;
        const float* a = acc + t * 4;
#pragma unroll
        for (int rr = 0; rr < 2; rr++) {
            u32 off = (u32)((r + rr * 8) * ld + col) * 2;
            *(u32*)(smc + hoff + off) = pack_h2(a[rr * 2], a[rr * 2 + 1]);
        }
    }
}

// ---------------- LayerNorm -> fp16 X tile ----------------
__device__ __forceinline__ void ln_split(
    char* smc, const float* __restrict__ src, int lds, const float* __restrict__ bias,
    const float* __restrict__ gg, const float* __restrict__ bb, bool leaky, int tid)
{
    int warp = tid >> 5, lane = tid & 31;
    for (int n = warp; n < 64; n += 8) {
        const float* row = src + (size_t)n * lds;
        float v[8];
        float s = 0.f, sq = 0.f;
#pragma unroll
        for (int i = 0; i < 4; i++) {
            int c = 2 * lane + 64 * i;
            float2 t = *(const float2*)(row + c);
            if (bias) {
                float2 bv = *(const float2*)(bias + c);
                t.x += bv.x; t.y += bv.y;
            }
            v[2 * i] = t.x; v[2 * i + 1] = t.y;
            s += t.x + t.y;
            sq += t.x * t.x + t.y * t.y;
        }
#pragma unroll
        for (int off = 16; off > 0; off >>= 1) {
            s += __shfl_xor_sync(0xffffffffu, s, off);
            sq += __shfl_xor_sync(0xffffffffu, sq, off);
        }
        float mean = s * (1.0f / 256.0f);
        float var = sq * (1.0f / 256.0f) - mean * mean;
        float rstd = rsqrtf(var + 1e-5f);
#pragma unroll
        for (int i = 0; i < 4; i++) {
            int c = 2 * lane + 64 * i;
            float o0 = (v[2 * i] - mean) * rstd * gg[c] + bb[c];
            float o1 = (v[2 * i + 1] - mean) * rstd * gg[c + 1] + bb[c + 1];
            if (leaky) {
                o0 = (o0 >= 0.f) ? o0 : 0.1f * o0;
                o1 = (o1 >= 0.f) ? o1 : 0.1f * o1;
            }
            *(u32*)(smc + XH_OFF + (u32)(n * X_LD + c) * 2) = pack_h2(o0, o1);
        }
    }
}

// ---------------- prologue: weights (fragment-packed fp16 hi/lo) + adj softmax ----------------
__global__ void prep_kernel(
    const float* __restrict__ th0, const float* __restrict__ ph0, const float* __restrict__ fcw0,
    const float* __restrict__ th1, const float* __restrict__ ph1, const float* __restrict__ fcw1,
    const float* __restrict__ adj0, const float* __restrict__ adj1)
{
    if (blockIdx.x >= 512) {
        int gw = (blockIdx.x - 512) * 16 + (threadIdx.x >> 5);
        int lane = threadIdx.x & 31;
        int mat = gw >> 6, r = gw & 63;
        const float* row = (mat ? adj1 : adj0) + r * 64;
        float v0 = row[lane], v1 = row[32 + lane];
        float mx = fmaxf(v0, v1);
#pragma unroll
        for (int off = 16; off > 0; off >>= 1)
            mx = fmaxf(mx, __shfl_xor_sync(0xffffffffu, mx, off));
        float e0 = __expf(v0 - mx), e1 = __expf(v1 - mx);
        float ss = e0 + e1;
#pragma unroll
        for (int off = 16; off > 0; off >>= 1)
            ss += __shfl_xor_sync(0xffffffffu, ss, off);
        float inv = 1.0f / ss;
        float* dst = g_Ast + mat * 4096 + r * 64;
        dst[lane] = e0 * inv;
        dst[32 + lane] = e1 * inv;
        return;
    }
    int idx = blockIdx.x * 512 + threadIdx.x;  // 0..262143
    int k = idx & 255, r = (idx >> 8) & 255, g = (idx >> 16) & 1, l = idx >> 17;
    const float* th = l ? th1 : th0;
    const float* pw = l ? ph1 : ph0;
    const float* fw = l ? fcw1 : fcw0;
    float v;
    if (g == 0) v = (r < 128) ? th[r * 256 + k] : pw[(r - 128) * 256 + k];
    else        v = fw[r * 256 + k];
    __half hb = __float2half_rn(v);
    __half lb = __float2half_rn(v - __half2float(hb));
    u32 o8 = (u32)(r >> 3);
    u32 kp = (u32)(k >> 5);
    u32 lane = (u32)((r & 7) * 4 + ((k >> 1) & 3));
    u32 slot = (u32)(((k >> 4) & 1) * 2 + ((k >> 3) & 1));
    u32 off16 = ((((o8 * 8 + kp) * 32 + lane) * 4 + slot) << 1) | (u32)(k & 1);
    ((u16*)g_Wf[l][g][0])[off16] = __half_as_ushort(hb);
    ((u16*)g_Wf[l][g][1])[off16] = __half_as_ushort(lb);
}

// ---------------- main kernel: 256 threads, 2 CTAs/SM ----------------
__global__ void __launch_bounds__(NT, 2) gconv_kernel(
    const float* __restrict__ graph,
    const float* __restrict__ ln_in_g, const float* __restrict__ ln_in_b,
    const float* __restrict__ fcb0,
    const float* __restrict__ ln0_g, const float* __restrict__ ln0_b,
    const float* __restrict__ fcb1,
    float* __restrict__ out)
{
    extern __shared__ char smc[];
    u32 smb = smem_u32(smc);
    int tid = threadIdx.x;
    int warp = tid >> 5, lane = tid & 31;
    int b = blockIdx.x;

    // input LN
    ln_split(smc, graph + (size_t)b * 64 * 256, 256, nullptr, ln_in_g, ln_in_b, false, tid);
    __syncthreads();

    float acc[64];  // shared accumulator buffer for wgemm and agg

#pragma unroll 1
    for (int l = 0; l < 2; l++) {
        // ---- qk = X @ W_qk^T ----
        wgemm_reg(smb, XH_OFF, g_Wf[l][0][0], acc, warp, lane);
        wstore_hi(smc, acc, QKH_OFF, QK_LD, warp, lane);
        __syncthreads();

        // ---- scores = q @ k^T / sqrt(128) ----
        {
            float sacc[4][4];
            scores_tc(smb, sacc, warp, lane);
            const float sscale = 0.08838834764831845f;
            float* abf = (float*)(smc + ABF_OFF);
            int n0 = (warp & 3) * 16;
            int m0 = (warp >> 2) * 32;
            int r = n0 + (lane >> 2);
            int cb = m0 + 2 * (lane & 3);
#pragma unroll
            for (int t = 0; t < 4; t++)
#pragma unroll
                for (int rr = 0; rr < 2; rr++) {
                    float2 p;
                    p.x = sacc[t][rr * 2] * sscale;
                    p.y = sacc[t][rr * 2 + 1] * sscale;
                    *(float2*)(abf + (r + rr * 8) * ABF_LD + cb + t * 8) = p;
                }
        }
        __syncthreads();

        // ---- A_hat = Ast + softmax(scores) -> fp16 tile ----
        {
            const float* Ast = g_Ast + l * 4096;
            float* abf = (float*)(smc + ABF_OFF);
            u16* abh = (u16*)(smc + ABH_OFF);
            for (int n = warp; n < 64; n += 8) {
                float v0 = abf[n * ABF_LD + lane];
                float v1 = abf[n * ABF_LD + 32 + lane];
                float mx = fmaxf(v0, v1);
#pragma unroll
                for (int off = 16; off > 0; off >>= 1)
                    mx = fmaxf(mx, __shfl_xor_sync(0xffffffffu, mx, off));
                float e0 = __expf(v0 - mx);
                float e1 = __expf(v1 - mx);
                float ss = e0 + e1;
#pragma unroll
                for (int off = 16; off > 0; off >>= 1)
                    ss += __shfl_xor_sync(0xffffffffu, ss, off);
                float inv = 1.0f / ss;
                float a0 = Ast[n * 64 + lane] + e0 * inv;
                float a1 = Ast[n * 64 + 32 + lane] + e1 * inv;
                abh[n * AB_LD + lane]      = __half_as_ushort(__float2half_rn(a0));
                abh[n * AB_LD + 32 + lane] = __half_as_ushort(__float2half_rn(a1));
            }
        }
        __syncthreads();

        // ---- agg = A_hat @ X -> overwrite X tile ----
        agg_tc(smc, smb, acc, warp, lane);
        __syncthreads();  // all X reads done before overwrite
        store_hi_frag(smc, acc, (warp & 3) * 16, (warp >> 2) * 128, XH_OFF, X_LD, lane);
        __syncthreads();

        // ---- fc = agg @ W_fc^T ----
        wgemm_reg(smb, XH_OFF, g_Wf[l][1][0], acc, warp, lane);
        if (l == 0) {
            wstore_f32(smc, acc, FC_OFF, FC_LD, warp, lane);
            __syncthreads();
            ln_split(smc, (float*)(smc + FC_OFF), FC_LD, fcb0, ln0_g, ln0_b, true, tid);
            __syncthreads();
        } else {
            wstore_global(acc, out + (size_t)b * 64 * 256, fcb1, warp, lane);
        }
    }
}

extern "C" void kernel_launch(void* const* d_in, const int* in_sizes, int n_in,
                              void* d_out, int out_size)
{
    const float* graph   = (const float*)d_in[0];
    const float* ln_in_g = (const float*)d_in[1];
    const float* ln_in_b = (const float*)d_in[2];
    const float* adj0    = (const float*)d_in[3];
    const float* th0     = (const float*)d_in[4];
    const float* ph0     = (const float*)d_in[5];
    const float* fcw0    = (const float*)d_in[6];
    const float* fcb0    = (const float*)d_in[7];
    const float* ln0_g   = (const float*)d_in[8];
    const float* ln0_b   = (const float*)d_in[9];
    const float* adj1    = (const float*)d_in[10];
    const float* th1     = (const float*)d_in[11];
    const float* ph1     = (const float*)d_in[12];
    const float* fcw1    = (const float*)d_in[13];
    const float* fcb1    = (const float*)d_in[14];
    float* out = (float*)d_out;

    cudaFuncSetAttribute(gconv_kernel,
                         cudaFuncAttributeMaxDynamicSharedMemorySize, SMEM_BYTES);

    prep_kernel<<<520, 512>>>(th0, ph0, fcw0, th1, ph1, fcw1, adj0, adj1);
    gconv_kernel<<<NB, NT, SMEM_BYTES>>>(
        graph, ln_in_g, ln_in_b, fcb0, ln0_g, ln0_b, fcb1, out);
}

// round 13
// speedup vs baseline: 8.4587x; 1.0902x over previous
#include <cuda_runtime.h>
#include <cuda_fp16.h>
#include <math.h>

#define NB 2048
#define NT 256

typedef unsigned int u32;
typedef unsigned short u16;

// element strides
#define X_LD 264     // fp16 X tile [64][264]
#define QK_LD 264
#define AB_LD 72     // fp16 A_hat
#define FC_LD 260    // fp32 fc-out (layer 0 only)
#define AST_LD 66    // fp16 staged Ast

// smem byte offsets
#define XH_OFF 0
#define QKH_OFF 33792
#define ABH_OFF 67584        // 64*72*2 = 9216
#define AST_OFF 76800        // 64*66*2 = 8448
#define PART_OFF 85248       // 64*2 float2 = 1024
#define FC_OFF 33792         // alias QKH+ABH+AST+PART (all dead when FC written)
#define SMEM_BYTES 100352

__device__ float g_Ast[2 * 64 * 64];
// fragment-packed fp16 weights: index (((o8*8 + kp)*32 + lane)) uint4;
// .x/.y = kstep0 b0/b1, .z/.w = kstep1. [layer][qk|fc][hi|lo]
__device__ uint4 g_Wf[2][2][2][8192];

// ---------------- PTX wrappers ----------------
__device__ __forceinline__ u32 smem_u32(const void* p) {
    u32 a;
    asm("{ .reg .u64 t; cvta.to.shared.u64 t, %1; cvt.u32.u64 %0, t; }" : "=r"(a) : "l"(p));
    return a;
}
__device__ __forceinline__ void ldmx4(u32 a, u32 r[4]) {
    asm volatile("ldmatrix.sync.aligned.m8n8.x4.shared.b16 {%0,%1,%2,%3}, [%4];"
                 : "=r"(r[0]), "=r"(r[1]), "=r"(r[2]), "=r"(r[3]) : "r"(a));
}
__device__ __forceinline__ void ldmx4t(u32 a, u32 r[4]) {
    asm volatile("ldmatrix.sync.aligned.m8n8.x4.trans.shared.b16 {%0,%1,%2,%3}, [%4];"
                 : "=r"(r[0]), "=r"(r[1]), "=r"(r[2]), "=r"(r[3]) : "r"(a));
}
__device__ __forceinline__ void mma16816(float* d, const u32 a[4], u32 b0, u32 b1) {
    asm volatile("mma.sync.aligned.m16n8k16.row.col.f32.f16.f16.f32 "
                 "{%0,%1,%2,%3}, {%4,%5,%6,%7}, {%8,%9}, {%0,%1,%2,%3};"
                 : "+f"(d[0]), "+f"(d[1]), "+f"(d[2]), "+f"(d[3])
                 : "r"(a[0]), "r"(a[1]), "r"(a[2]), "r"(a[3]), "r"(b0), "r"(b1));
}

__device__ __forceinline__ u32 pack_h2(float v0, float v1) {
    __half2 h = __floats2half2_rn(v0, v1);
    return *(u32*)&h;
}

// ---------------- weight GEMM: C[64 n][256 o], 8 warps, warp tile 64n x 32o ----------------
// acc layout: acc[(nf*4 + of)*4 + j], nf = 16n frag, of = 8o frag.
__device__ __forceinline__ void wgemm_reg(
    u32 smb, u32 xh_off, const uint4* __restrict__ wH,
    float* acc, int warp, int lane)
{
#pragma unroll
    for (int i = 0; i < 64; i++) acc[i] = 0.f;

    int arow = lane & 15;
    int acol = 8 * (lane >> 4);
    u32 fb = (u32)((warp * 4 * 8) * 32 + lane);  // of stride = 8*32 = 256

    uint4 bh[4];
#pragma unroll
    for (int of = 0; of < 4; of++) bh[of] = wH[fb + of * 256];

#pragma unroll
    for (int kp = 0; kp < 8; kp++) {
        uint4 nh[4];
        if (kp < 7) {
#pragma unroll
            for (int of = 0; of < 4; of++) nh[of] = wH[fb + of * 256 + (kp + 1) * 32];
        }
#pragma unroll
        for (int ks = 0; ks < 2; ks++) {
            int kg = (kp * 2 + ks) * 16;
#pragma unroll
            for (int nf = 0; nf < 4; nf++) {
                u32 ah[4];
                u32 aoff = (u32)((nf * 16 + arow) * X_LD + kg + acol) * 2;
                ldmx4(smb + xh_off + aoff, ah);
#pragma unroll
                for (int of = 0; of < 4; of++) {
                    u32 b0 = ks ? bh[of].z : bh[of].x;
                    u32 b1 = ks ? bh[of].w : bh[of].y;
                    mma16816(acc + (nf * 4 + of) * 4, ah, b0, b1);
                }
            }
        }
        if (kp < 7) {
#pragma unroll
            for (int of = 0; of < 4; of++) bh[of] = nh[of];
        }
    }
}

// store acc as fp16 tiles (qk / agg epilogues; col base = warp*32)
__device__ __forceinline__ void wstore_hi(
    char* smc, const float* acc, u32 hoff, int ld, int warp, int lane)
{
    int rb = lane >> 2;
    int cb = warp * 32 + 2 * (lane & 3);
#pragma unroll
    for (int nf = 0; nf < 4; nf++)
#pragma unroll
        for (int of = 0; of < 4; of++)
#pragma unroll
            for (int rr = 0; rr < 2; rr++) {
                int r = nf * 16 + rb + rr * 8;
                int c = cb + of * 8;
                const float* a = acc + (nf * 4 + of) * 4;
                *(u32*)(smc + hoff + (u32)(r * ld + c) * 2) =
                    pack_h2(a[rr * 2], a[rr * 2 + 1]);
            }
}

// store acc as fp32 to smem (fc epilogue, layer 0)
__device__ __forceinline__ void wstore_f32(
    char* smc, const float* acc, u32 foff, int ld, int warp, int lane)
{
    float* f = (float*)(smc + foff);
    int rb = lane >> 2;
    int cb = warp * 32 + 2 * (lane & 3);
#pragma unroll
    for (int nf = 0; nf < 4; nf++)
#pragma unroll
        for (int of = 0; of < 4; of++)
#pragma unroll
            for (int rr = 0; rr < 2; rr++) {
                int r = nf * 16 + rb + rr * 8;
                int c = cb + of * 8;
                const float* a = acc + (nf * 4 + of) * 4;
                *(float2*)(f + r * ld + c) = make_float2(a[rr * 2], a[rr * 2 + 1]);
            }
}

// store acc + bias directly to global (fc epilogue, layer 1)
__device__ __forceinline__ void wstore_global(
    const float* acc, float* __restrict__ og,
    const float* __restrict__ bias, int warp, int lane)
{
    int rb = lane >> 2;
    int cb = warp * 32 + 2 * (lane & 3);
    float bv[4][2];
#pragma unroll
    for (int of = 0; of < 4; of++) {
        bv[of][0] = bias[cb + of * 8];
        bv[of][1] = bias[cb + of * 8 + 1];
    }
#pragma unroll
    for (int nf = 0; nf < 4; nf++)
#pragma unroll
        for (int of = 0; of < 4; of++)
#pragma unroll
            for (int rr = 0; rr < 2; rr++) {
                int r = nf * 16 + rb + rr * 8;
                int c = cb + of * 8;
                const float* a = acc + (nf * 4 + of) * 4;
                float2 p;
                p.x = a[rr * 2] + bv[of][0];
                p.y = a[rr * 2 + 1] + bv[of][1];
                *(float2*)(og + r * 256 + c) = p;
            }
}

// ---------------- scores: C[64 n][64 m] = q @ k^T, 8 warps, tile 16n x 32m ----------------
__device__ __forceinline__ void scores_tc(u32 smb, float sacc[4][4], int warp, int lane)
{
    int n0 = (warp & 3) * 16;
    int m0 = (warp >> 2) * 32;
#pragma unroll
    for (int t = 0; t < 4; t++)
#pragma unroll
        for (int j = 0; j < 4; j++) sacc[t][j] = 0.f;
    int arow = n0 + (lane & 15);
    int acolsel = 8 * (lane >> 4);
    int brow0 = m0 + (lane & 7) + 8 * ((lane >> 4) & 1);
    int bksel = 8 * ((lane >> 3) & 1);
#pragma unroll
    for (int ks = 0; ks < 8; ks++) {
        int kg = ks * 16;
        u32 ah[4], bh0[4], bh1[4];
        ldmx4(smb + QKH_OFF + (u32)(arow * QK_LD + kg + acolsel) * 2, ah);
        ldmx4(smb + QKH_OFF + (u32)(brow0 * QK_LD + 128 + kg + bksel) * 2, bh0);
        ldmx4(smb + QKH_OFF + (u32)((brow0 + 16) * QK_LD + 128 + kg + bksel) * 2, bh1);
        mma16816(sacc[0], ah, bh0[0], bh0[1]);
        mma16816(sacc[1], ah, bh0[2], bh0[3]);
        mma16816(sacc[2], ah, bh1[0], bh1[1]);
        mma16816(sacc[3], ah, bh1[2], bh1[3]);
    }
}

// ---------------- agg: C[64 n][256 d] = A_hat @ X, warp tile 64n x 32d ----------------
__device__ __forceinline__ void agg_tc(char* smc, u32 smb, float* acc,
                                       int warp, int lane)
{
#pragma unroll
    for (int i = 0; i < 64; i++) acc[i] = 0.f;
    int arow = lane & 15;
    int acol = 8 * (lane >> 4);
    int xrow = lane & 15;
    int xcol = warp * 32 + 8 * (lane >> 4);
#pragma unroll
    for (int ks = 0; ks < 4; ks++) {
        int kg = ks * 16;
        u32 ah[4][4];
#pragma unroll
        for (int nf = 0; nf < 4; nf++)
            ldmx4(smb + ABH_OFF + (u32)((nf * 16 + arow) * AB_LD + kg + acol) * 2, ah[nf]);
#pragma unroll
        for (int dg = 0; dg < 2; dg++) {
            u32 bh[4];
            ldmx4t(smb + XH_OFF + (u32)((kg + xrow) * X_LD + xcol + dg * 16) * 2, bh);
#pragma unroll
            for (int nf = 0; nf < 4; nf++) {
                mma16816(acc + (nf * 4 + dg * 2) * 4, ah[nf], bh[0], bh[1]);
                mma16816(acc + (nf * 4 + dg * 2 + 1) * 4, ah[nf], bh[2], bh[3]);
            }
        }
    }
}

// ---------------- LayerNorm -> fp16 X tile ----------------
__device__ __forceinline__ void ln_split(
    char* smc, const float* __restrict__ src, int lds, const float* __restrict__ bias,
    const float* __restrict__ gg, const float* __restrict__ bb, bool leaky, int tid)
{
    int warp = tid >> 5, lane = tid & 31;
    for (int n = warp; n < 64; n += 8) {
        const float* row = src + (size_t)n * lds;
        float v[8];
        float s = 0.f, sq = 0.f;
#pragma unroll
        for (int i = 0; i < 4; i++) {
            int c = 2 * lane + 64 * i;
            float2 t = *(const float2*)(row + c);
            if (bias) {
                float2 bv = *(const float2*)(bias + c);
                t.x += bv.x; t.y += bv.y;
            }
            v[2 * i] = t.x; v[2 * i + 1] = t.y;
            s += t.x + t.y;
            sq += t.x * t.x + t.y * t.y;
        }
#pragma unroll
        for (int off = 16; off > 0; off >>= 1) {
            s += __shfl_xor_sync(0xffffffffu, s, off);
            sq += __shfl_xor_sync(0xffffffffu, sq, off);
        }
        float mean = s * (1.0f / 256.0f);
        float var = sq * (1.0f / 256.0f) - mean * mean;
        float rstd = rsqrtf(var + 1e-5f);
#pragma unroll
        for (int i = 0; i < 4; i++) {
            int c = 2 * lane + 64 * i;
            float o0 = (v[2 * i] - mean) * rstd * gg[c] + bb[c];
            float o1 = (v[2 * i + 1] - mean) * rstd * gg[c + 1] + bb[c + 1];
            if (leaky) {
                o0 = (o0 >= 0.f) ? o0 : 0.1f * o0;
                o1 = (o1 >= 0.f) ? o1 : 0.1f * o1;
            }
            *(u32*)(smc + XH_OFF + (u32)(n * X_LD + c) * 2) = pack_h2(o0, o1);
        }
    }
}

// stage layer-l Ast into smem as fp16 [64][AST_LD]
__device__ __forceinline__ void stage_ast(char* smc, int l, int tid) {
    const float* src = g_Ast + l * 4096;
    u16* dst = (u16*)(smc + AST_OFF);
    for (int i = tid; i < 4096; i += NT) {
        int r = i >> 6, m = i & 63;
        dst[r * AST_LD + m] = __half_as_ushort(__float2half_rn(src[i]));
    }
}

// ---------------- prologue: weights (fragment-packed fp16 hi/lo) + adj softmax ----------------
__global__ void prep_kernel(
    const float* __restrict__ th0, const float* __restrict__ ph0, const float* __restrict__ fcw0,
    const float* __restrict__ th1, const float* __restrict__ ph1, const float* __restrict__ fcw1,
    const float* __restrict__ adj0, const float* __restrict__ adj1)
{
    if (blockIdx.x >= 512) {
        int gw = (blockIdx.x - 512) * 16 + (threadIdx.x >> 5);
        int lane = threadIdx.x & 31;
        int mat = gw >> 6, r = gw & 63;
        const float* row = (mat ? adj1 : adj0) + r * 64;
        float v0 = row[lane], v1 = row[32 + lane];
        float mx = fmaxf(v0, v1);
#pragma unroll
        for (int off = 16; off > 0; off >>= 1)
            mx = fmaxf(mx, __shfl_xor_sync(0xffffffffu, mx, off));
        float e0 = __expf(v0 - mx), e1 = __expf(v1 - mx);
        float ss = e0 + e1;
#pragma unroll
        for (int off = 16; off > 0; off >>= 1)
            ss += __shfl_xor_sync(0xffffffffu, ss, off);
        float inv = 1.0f / ss;
        float* dst = g_Ast + mat * 4096 + r * 64;
        dst[lane] = e0 * inv;
        dst[32 + lane] = e1 * inv;
        return;
    }
    int idx = blockIdx.x * 512 + threadIdx.x;  // 0..262143
    int k = idx & 255, r = (idx >> 8) & 255, g = (idx >> 16) & 1, l = idx >> 17;
    const float* th = l ? th1 : th0;
    const float* pw = l ? ph1 : ph0;
    const float* fw = l ? fcw1 : fcw0;
    float v;
    if (g == 0) v = (r < 128) ? th[r * 256 + k] : pw[(r - 128) * 256 + k];
    else        v = fw[r * 256 + k];
    __half hb = __float2half_rn(v);
    __half lb = __float2half_rn(v - __half2float(hb));
    u32 o8 = (u32)(r >> 3);
    u32 kp = (u32)(k >> 5);
    u32 lane = (u32)((r & 7) * 4 + ((k >> 1) & 3));
    u32 slot = (u32)(((k >> 4) & 1) * 2 + ((k >> 3) & 1));
    u32 off16 = ((((o8 * 8 + kp) * 32 + lane) * 4 + slot) << 1) | (u32)(k & 1);
    ((u16*)g_Wf[l][g][0])[off16] = __half_as_ushort(hb);
    ((u16*)g_Wf[l][g][1])[off16] = __half_as_ushort(lb);
}

// ---------------- main kernel: 256 threads, 2 CTAs/SM ----------------
__global__ void __launch_bounds__(NT, 2) gconv_kernel(
    const float* __restrict__ graph,
    const float* __restrict__ ln_in_g, const float* __restrict__ ln_in_b,
    const float* __restrict__ fcb0,
    const float* __restrict__ ln0_g, const float* __restrict__ ln0_b,
    const float* __restrict__ fcb1,
    float* __restrict__ out)
{
    extern __shared__ char smc[];
    u32 smb = smem_u32(smc);
    int tid = threadIdx.x;
    int warp = tid >> 5, lane = tid & 31;
    int b = blockIdx.x;

    // input LN
    ln_split(smc, graph + (size_t)b * 64 * 256, 256, nullptr, ln_in_g, ln_in_b, false, tid);
    __syncthreads();

    float acc[64];  // shared accumulator buffer for wgemm and agg

#pragma unroll 1
    for (int l = 0; l < 2; l++) {
        // ---- qk = X @ W_qk^T ----
        wgemm_reg(smb, XH_OFF, g_Wf[l][0][0], acc, warp, lane);
        wstore_hi(smc, acc, QKH_OFF, QK_LD, warp, lane);
        stage_ast(smc, l, tid);   // Ast area free here (FC of prev layer dead)
        __syncthreads();

        // ---- scores + in-register softmax -> A_hat fp16 tile ----
        {
            float sacc[4][4];
            scores_tc(smb, sacc, warp, lane);
            const float sscale = 0.08838834764831845f;  // 1/sqrt(128)
#pragma unroll
            for (int t = 0; t < 4; t++)
#pragma unroll
                for (int j = 0; j < 4; j++) sacc[t][j] *= sscale;
            // local row max (rows r, r+8 over this warp's 32 m)
            float mx0 = sacc[0][0], mx1 = sacc[0][2];
#pragma unroll
            for (int t = 0; t < 4; t++) {
                mx0 = fmaxf(mx0, fmaxf(sacc[t][0], sacc[t][1]));
                mx1 = fmaxf(mx1, fmaxf(sacc[t][2], sacc[t][3]));
            }
#pragma unroll
            for (int d = 1; d <= 2; d <<= 1) {
                mx0 = fmaxf(mx0, __shfl_xor_sync(0xffffffffu, mx0, d));
                mx1 = fmaxf(mx1, __shfl_xor_sync(0xffffffffu, mx1, d));
            }
            float s0 = 0.f, s1 = 0.f;
#pragma unroll
            for (int t = 0; t < 4; t++) {
                sacc[t][0] = __expf(sacc[t][0] - mx0);
                sacc[t][1] = __expf(sacc[t][1] - mx0);
                sacc[t][2] = __expf(sacc[t][2] - mx1);
                sacc[t][3] = __expf(sacc[t][3] - mx1);
                s0 += sacc[t][0] + sacc[t][1];
                s1 += sacc[t][2] + sacc[t][3];
            }
#pragma unroll
            for (int d = 1; d <= 2; d <<= 1) {
                s0 += __shfl_xor_sync(0xffffffffu, s0, d);
                s1 += __shfl_xor_sync(0xffffffffu, s1, d);
            }
            int n0 = (warp & 3) * 16;
            int mw = warp >> 2;
            int r = n0 + (lane >> 2);
            float2* part = (float2*)(smc + PART_OFF);
            if ((lane & 3) == 0) {
                part[r * 2 + mw] = make_float2(mx0, s0);
                part[(r + 8) * 2 + mw] = make_float2(mx1, s1);
            }
            __syncthreads();
            float2 pa0 = part[r * 2],        pb0 = part[r * 2 + 1];
            float2 pa1 = part[(r + 8) * 2],  pb1 = part[(r + 8) * 2 + 1];
            float M0 = fmaxf(pa0.x, pb0.x);
            float S0 = pa0.y * __expf(pa0.x - M0) + pb0.y * __expf(pb0.x - M0);
            float corr0 = __expf(mx0 - M0) / S0;
            float M1 = fmaxf(pa1.x, pb1.x);
            float S1 = pa1.y * __expf(pa1.x - M1) + pb1.y * __expf(pb1.x - M1);
            float corr1 = __expf(mx1 - M1) / S1;
            int m0 = mw * 32;
            const u16* ast = (const u16*)(smc + AST_OFF);
            u16* abh = (u16*)(smc + ABH_OFF);
#pragma unroll
            for (int t = 0; t < 4; t++) {
                int m = m0 + 2 * (lane & 3) + t * 8;
                u32 av0 = *(const u32*)(ast + r * AST_LD + m);
                __half2 h0 = *(__half2*)&av0;
                float2 a0 = __half22float2(h0);
                *(u32*)(abh + r * AB_LD + m) =
                    pack_h2(a0.x + sacc[t][0] * corr0, a0.y + sacc[t][1] * corr0);
                u32 av1 = *(const u32*)(ast + (r + 8) * AST_LD + m);
                __half2 h1 = *(__half2*)&av1;
                float2 a1 = __half22float2(h1);
                *(u32*)(abh + (r + 8) * AB_LD + m) =
                    pack_h2(a1.x + sacc[t][2] * corr1, a1.y + sacc[t][3] * corr1);
            }
        }
        __syncthreads();

        // ---- agg = A_hat @ X -> overwrite X tile ----
        agg_tc(smc, smb, acc, warp, lane);
        __syncthreads();  // all X reads done before overwrite
        wstore_hi(smc, acc, XH_OFF, X_LD, warp, lane);
        __syncthreads();

        // ---- fc = agg @ W_fc^T ----
        wgemm_reg(smb, XH_OFF, g_Wf[l][1][0], acc, warp, lane);
        if (l == 0) {
            wstore_f32(smc, acc, FC_OFF, FC_LD, warp, lane);
            __syncthreads();
            ln_split(smc, (float*)(smc + FC_OFF), FC_LD, fcb0, ln0_g, ln0_b, true, tid);
            __syncthreads();
        } else {
            wstore_global(acc, out + (size_t)b * 64 * 256, fcb1, warp, lane);
        }
    }
}

extern "C" void kernel_launch(void* const* d_in, const int* in_sizes, int n_in,
                              void* d_out, int out_size)
{
    const float* graph   = (const float*)d_in[0];
    const float* ln_in_g = (const float*)d_in[1];
    const float* ln_in_b = (const float*)d_in[2];
    const float* adj0    = (const float*)d_in[3];
    const float* th0     = (const float*)d_in[4];
    const float* ph0     = (const float*)d_in[5];
    const float* fcw0    = (const float*)d_in[6];
    const float* fcb0    = (const float*)d_in[7];
    const float* ln0_g   = (const float*)d_in[8];
    const float* ln0_b   = (const float*)d_in[9];
    const float* adj1    = (const float*)d_in[10];
    const float* th1     = (const float*)d_in[11];
    const float* ph1     = (const float*)d_in[12];
    const float* fcw1    = (const float*)d_in[13];
    const float* fcb1    = (const float*)d_in[14];
    float* out = (float*)d_out;

    cudaFuncSetAttribute(gconv_kernel,
                         cudaFuncAttributeMaxDynamicSharedMemorySize, SMEM_BYTES);

    prep_kernel<<<520, 512>>>(th0, ph0, fcw0, th1, ph1, fcw1, adj0, adj1);
    gconv_kernel<<<NB, NT, SMEM_BYTES>>>(
        graph, ln_in_g, ln_in_b, fcb0, ln0_g, ln0_b, fcb1, out);
}

// round 14
// speedup vs baseline: 9.3452x; 1.1048x over previous
#include <cuda_runtime.h>
#include <cuda_fp16.h>
#include <math.h>

#define NB 2048
#define NT 256

typedef unsigned int u32;
typedef unsigned short u16;

// element strides
#define X_LD 264     // fp16 tiles [64][264]
#define AB_LD 72     // fp16 A_hat
#define AST_LD 66    // fp16 staged Ast

// smem byte offsets
#define X0_OFF 0             // X (LN output / layer input)     33792
#define X1_OFF 33792         // qk, then agg output (ping-pong) 33792
#define ABH_OFF 67584        // 64*72*2 = 9216
#define AST_OFF 76800        // 2 layers * 64*66*2 = 16896
#define PART_OFF 93696       // softmax partials: 64*2 float2 = 1024
#define P2_OFF 94720         // LN partials: 64*8 float2 = 4096
#define P3_OFF 98816         // LN mean/rstd: 64 float2 = 512
#define SMEM_BYTES 99328

__device__ float g_Ast[2 * 64 * 64];
// fragment-packed fp16 weights: index (((o8*8 + kp)*32 + lane)) uint4;
// .x/.y = kstep0 b0/b1, .z/.w = kstep1. [layer][qk|fc][hi|lo]
__device__ uint4 g_Wf[2][2][2][8192];

// ---------------- PTX wrappers ----------------
__device__ __forceinline__ u32 smem_u32(const void* p) {
    u32 a;
    asm("{ .reg .u64 t; cvta.to.shared.u64 t, %1; cvt.u32.u64 %0, t; }" : "=r"(a) : "l"(p));
    return a;
}
__device__ __forceinline__ void ldmx4(u32 a, u32 r[4]) {
    asm volatile("ldmatrix.sync.aligned.m8n8.x4.shared.b16 {%0,%1,%2,%3}, [%4];"
                 : "=r"(r[0]), "=r"(r[1]), "=r"(r[2]), "=r"(r[3]) : "r"(a));
}
__device__ __forceinline__ void ldmx4t(u32 a, u32 r[4]) {
    asm volatile("ldmatrix.sync.aligned.m8n8.x4.trans.shared.b16 {%0,%1,%2,%3}, [%4];"
                 : "=r"(r[0]), "=r"(r[1]), "=r"(r[2]), "=r"(r[3]) : "r"(a));
}
__device__ __forceinline__ void mma16816(float* d, const u32 a[4], u32 b0, u32 b1) {
    asm volatile("mma.sync.aligned.m16n8k16.row.col.f32.f16.f16.f32 "
                 "{%0,%1,%2,%3}, {%4,%5,%6,%7}, {%8,%9}, {%0,%1,%2,%3};"
                 : "+f"(d[0]), "+f"(d[1]), "+f"(d[2]), "+f"(d[3])
                 : "r"(a[0]), "r"(a[1]), "r"(a[2]), "r"(a[3]), "r"(b0), "r"(b1));
}

__device__ __forceinline__ u32 pack_h2(float v0, float v1) {
    __half2 h = __floats2half2_rn(v0, v1);
    return *(u32*)&h;
}

// ---------------- weight GEMM: C[64 n][256 o], 8 warps, warp tile 64n x 32o ----------------
// acc layout: acc[(nf*4 + of)*4 + j], nf = 16n frag, of = 8o frag.
__device__ __forceinline__ void wgemm_reg(
    u32 smb, u32 x_off, const uint4* __restrict__ wH,
    float* acc, int warp, int lane)
{
#pragma unroll
    for (int i = 0; i < 64; i++) acc[i] = 0.f;

    int arow = lane & 15;
    int acol = 8 * (lane >> 4);
    u32 fb = (u32)((warp * 4 * 8) * 32 + lane);  // of stride = 8*32 = 256

    uint4 bh[4];
#pragma unroll
    for (int of = 0; of < 4; of++) bh[of] = wH[fb + of * 256];

#pragma unroll
    for (int kp = 0; kp < 8; kp++) {
        uint4 nh[4];
        if (kp < 7) {
#pragma unroll
            for (int of = 0; of < 4; of++) nh[of] = wH[fb + of * 256 + (kp + 1) * 32];
        }
#pragma unroll
        for (int ks = 0; ks < 2; ks++) {
            int kg = (kp * 2 + ks) * 16;
#pragma unroll
            for (int nf = 0; nf < 4; nf++) {
                u32 ah[4];
                u32 aoff = (u32)((nf * 16 + arow) * X_LD + kg + acol) * 2;
                ldmx4(smb + x_off + aoff, ah);
#pragma unroll
                for (int of = 0; of < 4; of++) {
                    u32 b0 = ks ? bh[of].z : bh[of].x;
                    u32 b1 = ks ? bh[of].w : bh[of].y;
                    mma16816(acc + (nf * 4 + of) * 4, ah, b0, b1);
                }
            }
        }
        if (kp < 7) {
#pragma unroll
            for (int of = 0; of < 4; of++) bh[of] = nh[of];
        }
    }
}

// store acc as fp16 tiles (qk / agg epilogues; col base = warp*32)
__device__ __forceinline__ void wstore_hi(
    char* smc, const float* acc, u32 hoff, int ld, int warp, int lane)
{
    int rb = lane >> 2;
    int cb = warp * 32 + 2 * (lane & 3);
#pragma unroll
    for (int nf = 0; nf < 4; nf++)
#pragma unroll
        for (int of = 0; of < 4; of++)
#pragma unroll
            for (int rr = 0; rr < 2; rr++) {
                int r = nf * 16 + rb + rr * 8;
                int c = cb + of * 8;
                const float* a = acc + (nf * 4 + of) * 4;
                *(u32*)(smc + hoff + (u32)(r * ld + c) * 2) =
                    pack_h2(a[rr * 2], a[rr * 2 + 1]);
            }
}

// store acc + bias directly to global (fc epilogue, layer 1)
__device__ __forceinline__ void wstore_global(
    const float* acc, float* __restrict__ og,
    const float* __restrict__ bias, int warp, int lane)
{
    int rb = lane >> 2;
    int cb = warp * 32 + 2 * (lane & 3);
    float bv[4][2];
#pragma unroll
    for (int of = 0; of < 4; of++) {
        bv[of][0] = bias[cb + of * 8];
        bv[of][1] = bias[cb + of * 8 + 1];
    }
#pragma unroll
    for (int nf = 0; nf < 4; nf++)
#pragma unroll
        for (int of = 0; of < 4; of++)
#pragma unroll
            for (int rr = 0; rr < 2; rr++) {
                int r = nf * 16 + rb + rr * 8;
                int c = cb + of * 8;
                const float* a = acc + (nf * 4 + of) * 4;
                float2 p;
                p.x = a[rr * 2] + bv[of][0];
                p.y = a[rr * 2 + 1] + bv[of][1];
                *(float2*)(og + r * 256 + c) = p;
            }
}

// ---------------- scores: C[64 n][64 m] = q @ k^T, 8 warps, tile 16n x 32m ----------------
__device__ __forceinline__ void scores_tc(u32 smb, float sacc[4][4], int warp, int lane)
{
    int n0 = (warp & 3) * 16;
    int m0 = (warp >> 2) * 32;
#pragma unroll
    for (int t = 0; t < 4; t++)
#pragma unroll
        for (int j = 0; j < 4; j++) sacc[t][j] = 0.f;
    int arow = n0 + (lane & 15);
    int acolsel = 8 * (lane >> 4);
    int brow0 = m0 + (lane & 7) + 8 * ((lane >> 4) & 1);
    int bksel = 8 * ((lane >> 3) & 1);
#pragma unroll
    for (int ks = 0; ks < 8; ks++) {
        int kg = ks * 16;
        u32 ah[4], bh0[4], bh1[4];
        ldmx4(smb + X1_OFF + (u32)(arow * X_LD + kg + acolsel) * 2, ah);
        ldmx4(smb + X1_OFF + (u32)(brow0 * X_LD + 128 + kg + bksel) * 2, bh0);
        ldmx4(smb + X1_OFF + (u32)((brow0 + 16) * X_LD + 128 + kg + bksel) * 2, bh1);
        mma16816(sacc[0], ah, bh0[0], bh0[1]);
        mma16816(sacc[1], ah, bh0[2], bh0[3]);
        mma16816(sacc[2], ah, bh1[0], bh1[1]);
        mma16816(sacc[3], ah, bh1[2], bh1[3]);
    }
}

// ---------------- agg: C[64 n][256 d] = A_hat @ X0, warp tile 64n x 32d ----------------
__device__ __forceinline__ void agg_tc(char* smc, u32 smb, float* acc,
                                       int warp, int lane)
{
#pragma unroll
    for (int i = 0; i < 64; i++) acc[i] = 0.f;
    int arow = lane & 15;
    int acol = 8 * (lane >> 4);
    int xrow = lane & 15;
    int xcol = warp * 32 + 8 * (lane >> 4);
#pragma unroll
    for (int ks = 0; ks < 4; ks++) {
        int kg = ks * 16;
        u32 ah[4][4];
#pragma unroll
        for (int nf = 0; nf < 4; nf++)
            ldmx4(smb + ABH_OFF + (u32)((nf * 16 + arow) * AB_LD + kg + acol) * 2, ah[nf]);
#pragma unroll
        for (int dg = 0; dg < 2; dg++) {
            u32 bh[4];
            ldmx4t(smb + X0_OFF + (u32)((kg + xrow) * X_LD + xcol + dg * 16) * 2, bh);
#pragma unroll
            for (int nf = 0; nf < 4; nf++) {
                mma16816(acc + (nf * 4 + dg * 2) * 4, ah[nf], bh[0], bh[1]);
                mma16816(acc + (nf * 4 + dg * 2 + 1) * 4, ah[nf], bh[2], bh[3]);
            }
        }
    }
}

// ---------------- LayerNorm (global fp32 source) -> fp16 X0 tile ----------------
__device__ __forceinline__ void ln_global(
    char* smc, const float* __restrict__ src,
    const float* __restrict__ gg, const float* __restrict__ bb, int tid)
{
    int warp = tid >> 5, lane = tid & 31;
    for (int n = warp; n < 64; n += 8) {
        const float* row = src + (size_t)n * 256;
        float v[8];
        float s = 0.f, sq = 0.f;
#pragma unroll
        for (int i = 0; i < 4; i++) {
            int c = 2 * lane + 64 * i;
            float2 t = *(const float2*)(row + c);
            v[2 * i] = t.x; v[2 * i + 1] = t.y;
            s += t.x + t.y;
            sq += t.x * t.x + t.y * t.y;
        }
#pragma unroll
        for (int off = 16; off > 0; off >>= 1) {
            s += __shfl_xor_sync(0xffffffffu, s, off);
            sq += __shfl_xor_sync(0xffffffffu, sq, off);
        }
        float mean = s * (1.0f / 256.0f);
        float var = sq * (1.0f / 256.0f) - mean * mean;
        float rstd = rsqrtf(var + 1e-5f);
#pragma unroll
        for (int i = 0; i < 4; i++) {
            int c = 2 * lane + 64 * i;
            float o0 = (v[2 * i] - mean) * rstd * gg[c] + bb[c];
            float o1 = (v[2 * i + 1] - mean) * rstd * gg[c + 1] + bb[c + 1];
            *(u32*)(smc + X0_OFF + (u32)(n * X_LD + c) * 2) = pack_h2(o0, o1);
        }
    }
}

// stage both layers' Ast into smem as fp16
__device__ __forceinline__ void stage_ast(char* smc, int tid) {
    u16* dst = (u16*)(smc + AST_OFF);
    for (int i = tid; i < 8192; i += NT) {
        int l = i >> 12, j = i & 4095;
        int r = j >> 6, m = j & 63;
        dst[l * 64 * AST_LD + r * AST_LD + m] =
            __half_as_ushort(__float2half_rn(g_Ast[l * 4096 + j]));
    }
}

// ---------------- prologue: weights (fragment-packed fp16 hi/lo) + adj softmax ----------------
__global__ void prep_kernel(
    const float* __restrict__ th0, const float* __restrict__ ph0, const float* __restrict__ fcw0,
    const float* __restrict__ th1, const float* __restrict__ ph1, const float* __restrict__ fcw1,
    const float* __restrict__ adj0, const float* __restrict__ adj1)
{
    if (blockIdx.x >= 512) {
        int gw = (blockIdx.x - 512) * 16 + (threadIdx.x >> 5);
        int lane = threadIdx.x & 31;
        int mat = gw >> 6, r = gw & 63;
        const float* row = (mat ? adj1 : adj0) + r * 64;
        float v0 = row[lane], v1 = row[32 + lane];
        float mx = fmaxf(v0, v1);
#pragma unroll
        for (int off = 16; off > 0; off >>= 1)
            mx = fmaxf(mx, __shfl_xor_sync(0xffffffffu, mx, off));
        float e0 = __expf(v0 - mx), e1 = __expf(v1 - mx);
        float ss = e0 + e1;
#pragma unroll
        for (int off = 16; off > 0; off >>= 1)
            ss += __shfl_xor_sync(0xffffffffu, ss, off);
        float inv = 1.0f / ss;
        float* dst = g_Ast + mat * 4096 + r * 64;
        dst[lane] = e0 * inv;
        dst[32 + lane] = e1 * inv;
        return;
    }
    int idx = blockIdx.x * 512 + threadIdx.x;  // 0..262143
    int k = idx & 255, r = (idx >> 8) & 255, g = (idx >> 16) & 1, l = idx >> 17;
    const float* th = l ? th1 : th0;
    const float* pw = l ? ph1 : ph0;
    const float* fw = l ? fcw1 : fcw0;
    float v;
    if (g == 0) v = (r < 128) ? th[r * 256 + k] : pw[(r - 128) * 256 + k];
    else        v = fw[r * 256 + k];
    __half hb = __float2half_rn(v);
    __half lb = __float2half_rn(v - __half2float(hb));
    u32 o8 = (u32)(r >> 3);
    u32 kp = (u32)(k >> 5);
    u32 lane = (u32)((r & 7) * 4 + ((k >> 1) & 3));
    u32 slot = (u32)(((k >> 4) & 1) * 2 + ((k >> 3) & 1));
    u32 off16 = ((((o8 * 8 + kp) * 32 + lane) * 4 + slot) << 1) | (u32)(k & 1);
    ((u16*)g_Wf[l][g][0])[off16] = __half_as_ushort(hb);
    ((u16*)g_Wf[l][g][1])[off16] = __half_as_ushort(lb);
}

// ---------------- main kernel: 256 threads, 2 CTAs/SM ----------------
__global__ void __launch_bounds__(NT, 2) gconv_kernel(
    const float* __restrict__ graph,
    const float* __restrict__ ln_in_g, const float* __restrict__ ln_in_b,
    const float* __restrict__ fcb0,
    const float* __restrict__ ln0_g, const float* __restrict__ ln0_b,
    const float* __restrict__ fcb1,
    float* __restrict__ out)
{
    extern __shared__ char smc[];
    u32 smb = smem_u32(smc);
    int tid = threadIdx.x;
    int warp = tid >> 5, lane = tid & 31;
    int b = blockIdx.x;

    // input LN -> X0; stage both Ast layers
    ln_global(smc, graph + (size_t)b * 64 * 256, ln_in_g, ln_in_b, tid);
    stage_ast(smc, tid);
    __syncthreads();

    float acc[64];

#pragma unroll 1
    for (int l = 0; l < 2; l++) {
        // ---- qk = X0 @ W_qk^T -> X1 ----
        wgemm_reg(smb, X0_OFF, g_Wf[l][0][0], acc, warp, lane);
        wstore_hi(smc, acc, X1_OFF, X_LD, warp, lane);
        __syncthreads();

        // ---- scores (reads X1) + in-register softmax -> A_hat fp16 (ABH) ----
        {
            float sacc[4][4];
            scores_tc(smb, sacc, warp, lane);
            const float sscale = 0.08838834764831845f;  // 1/sqrt(128)
#pragma unroll
            for (int t = 0; t < 4; t++)
#pragma unroll
                for (int j = 0; j < 4; j++) sacc[t][j] *= sscale;
            float mx0 = sacc[0][0], mx1 = sacc[0][2];
#pragma unroll
            for (int t = 0; t < 4; t++) {
                mx0 = fmaxf(mx0, fmaxf(sacc[t][0], sacc[t][1]));
                mx1 = fmaxf(mx1, fmaxf(sacc[t][2], sacc[t][3]));
            }
#pragma unroll
            for (int d = 1; d <= 2; d <<= 1) {
                mx0 = fmaxf(mx0, __shfl_xor_sync(0xffffffffu, mx0, d));
                mx1 = fmaxf(mx1, __shfl_xor_sync(0xffffffffu, mx1, d));
            }
            float s0 = 0.f, s1 = 0.f;
#pragma unroll
            for (int t = 0; t < 4; t++) {
                sacc[t][0] = __expf(sacc[t][0] - mx0);
                sacc[t][1] = __expf(sacc[t][1] - mx0);
                sacc[t][2] = __expf(sacc[t][2] - mx1);
                sacc[t][3] = __expf(sacc[t][3] - mx1);
                s0 += sacc[t][0] + sacc[t][1];
                s1 += sacc[t][2] + sacc[t][3];
            }
#pragma unroll
            for (int d = 1; d <= 2; d <<= 1) {
                s0 += __shfl_xor_sync(0xffffffffu, s0, d);
                s1 += __shfl_xor_sync(0xffffffffu, s1, d);
            }
            int n0 = (warp & 3) * 16;
            int mw = warp >> 2;
            int r = n0 + (lane >> 2);
            float2* part = (float2*)(smc + PART_OFF);
            if ((lane & 3) == 0) {
                part[r * 2 + mw] = make_float2(mx0, s0);
                part[(r + 8) * 2 + mw] = make_float2(mx1, s1);
            }
            __syncthreads();
            float2 pa0 = part[r * 2],       pb0 = part[r * 2 + 1];
            float2 pa1 = part[(r + 8) * 2], pb1 = part[(r + 8) * 2 + 1];
            float M0 = fmaxf(pa0.x, pb0.x);
            float S0 = pa0.y * __expf(pa0.x - M0) + pb0.y * __expf(pb0.x - M0);
            float corr0 = __expf(mx0 - M0) / S0;
            float M1 = fmaxf(pa1.x, pb1.x);
            float S1 = pa1.y * __expf(pa1.x - M1) + pb1.y * __expf(pb1.x - M1);
            float corr1 = __expf(mx1 - M1) / S1;
            int m0 = mw * 32;
            const u16* ast = (const u16*)(smc + AST_OFF) + l * 64 * AST_LD;
            u16* abh = (u16*)(smc + ABH_OFF);
#pragma unroll
            for (int t = 0; t < 4; t++) {
                int m = m0 + 2 * (lane & 3) + t * 8;
                u32 av0 = *(const u32*)(ast + r * AST_LD + m);
                __half2 h0 = *(__half2*)&av0;
                float2 a0 = __half22float2(h0);
                *(u32*)(abh + r * AB_LD + m) =
                    pack_h2(a0.x + sacc[t][0] * corr0, a0.y + sacc[t][1] * corr0);
                u32 av1 = *(const u32*)(ast + (r + 8) * AST_LD + m);
                __half2 h1 = *(__half2*)&av1;
                float2 a1 = __half22float2(h1);
                *(u32*)(abh + (r + 8) * AB_LD + m) =
                    pack_h2(a1.x + sacc[t][2] * corr1, a1.y + sacc[t][3] * corr1);
            }
        }
        __syncthreads();   // ABH ready; X1 (qk) now dead

        // ---- agg = A_hat @ X0 -> X1 (overwrites qk) ----
        agg_tc(smc, smb, acc, warp, lane);
        wstore_hi(smc, acc, X1_OFF, X_LD, warp, lane);
        __syncthreads();

        // ---- fc = agg(X1) @ W_fc^T ----
        wgemm_reg(smb, X1_OFF, g_Wf[l][1][0], acc, warp, lane);
        if (l == 0) {
            // fragment-resident bias + LayerNorm + leaky -> X0
            int rb = lane >> 2;
            int cb = warp * 32 + 2 * (lane & 3);
#pragma unroll
            for (int of = 0; of < 4; of++) {
                float b0 = fcb0[cb + of * 8], b1 = fcb0[cb + of * 8 + 1];
#pragma unroll
                for (int nf = 0; nf < 4; nf++) {
                    float* a = acc + (nf * 4 + of) * 4;
                    a[0] += b0; a[1] += b1; a[2] += b0; a[3] += b1;
                }
            }
            float2* p2 = (float2*)(smc + P2_OFF);
#pragma unroll
            for (int nf = 0; nf < 4; nf++)
#pragma unroll
                for (int rr = 0; rr < 2; rr++) {
                    float s = 0.f, sq = 0.f;
#pragma unroll
                    for (int of = 0; of < 4; of++) {
                        const float* a = acc + (nf * 4 + of) * 4;
                        float x0 = a[rr * 2], x1 = a[rr * 2 + 1];
                        s += x0 + x1;
                        sq += x0 * x0 + x1 * x1;
                    }
#pragma unroll
                    for (int d = 1; d <= 2; d <<= 1) {
                        s += __shfl_xor_sync(0xffffffffu, s, d);
                        sq += __shfl_xor_sync(0xffffffffu, sq, d);
                    }
                    if ((lane & 3) == 0)
                        p2[(nf * 16 + rb + rr * 8) * 8 + warp] = make_float2(s, sq);
                }
            __syncthreads();
            float2* p3 = (float2*)(smc + P3_OFF);
            if (tid < 64) {
                float s = 0.f, sq = 0.f;
#pragma unroll
                for (int w = 0; w < 8; w++) {
                    float2 v = p2[tid * 8 + w];
                    s += v.x; sq += v.y;
                }
                float mean = s * (1.0f / 256.0f);
                float var = sq * (1.0f / 256.0f) - mean * mean;
                p3[tid] = make_float2(mean, rsqrtf(var + 1e-5f));
            }
            __syncthreads();
#pragma unroll
            for (int nf = 0; nf < 4; nf++)
#pragma unroll
                for (int rr = 0; rr < 2; rr++) {
                    int r = nf * 16 + rb + rr * 8;
                    float2 mr = p3[r];
#pragma unroll
                    for (int of = 0; of < 4; of++) {
                        int c = cb + of * 8;
                        const float* a = acc + (nf * 4 + of) * 4;
                        float o0 = (a[rr * 2] - mr.x) * mr.y * ln0_g[c] + ln0_b[c];
                        float o1 = (a[rr * 2 + 1] - mr.x) * mr.y * ln0_g[c + 1] + ln0_b[c + 1];
                        o0 = (o0 >= 0.f) ? o0 : 0.1f * o0;
                        o1 = (o1 >= 0.f) ? o1 : 0.1f * o1;
                        *(u32*)(smc + X0_OFF + (u32)(r * X_LD + c) * 2) = pack_h2(o0, o1);
                    }
                }
            __syncthreads();
        } else {
            wstore_global(acc, out + (size_t)b * 64 * 256, fcb1, warp, lane);
        }
    }
}

extern "C" void kernel_launch(void* const* d_in, const int* in_sizes, int n_in,
                              void* d_out, int out_size)
{
    const float* graph   = (const float*)d_in[0];
    const float* ln_in_g = (const float*)d_in[1];
    const float* ln_in_b = (const float*)d_in[2];
    const float* adj0    = (const float*)d_in[3];
    const float* th0     = (const float*)d_in[4];
    const float* ph0     = (const float*)d_in[5];
    const float* fcw0    = (const float*)d_in[6];
    const float* fcb0    = (const float*)d_in[7];
    const float* ln0_g   = (const float*)d_in[8];
    const float* ln0_b   = (const float*)d_in[9];
    const float* adj1    = (const float*)d_in[10];
    const float* th1     = (const float*)d_in[11];
    const float* ph1     = (const float*)d_in[12];
    const float* fcw1    = (const float*)d_in[13];
    const float* fcb1    = (const float*)d_in[14];
    float* out = (float*)d_out;

    cudaFuncSetAttribute(gconv_kernel,
                         cudaFuncAttributeMaxDynamicSharedMemorySize, SMEM_BYTES);

    prep_kernel<<<520, 512>>>(th0, ph0, fcw0, th1, ph1, fcw1, adj0, adj1);
    gconv_kernel<<<NB, NT, SMEM_BYTES>>>(
        graph, ln_in_g, ln_in_b, fcb0, ln0_g, ln0_b, fcb1, out);
}

// round 15
// speedup vs baseline: 9.6716x; 1.0349x over previous
#include <cuda_runtime.h>
#include <cuda_fp16.h>
#include <math.h>

#define NB 2048
#define NT 256

typedef unsigned int u32;
typedef unsigned short u16;

// element strides
#define X_LD 264     // fp16 tiles [64][264]
#define AB_LD 72     // fp16 A_hat
#define AST_LD 66    // fp16 staged Ast

// smem byte offsets
#define X0_OFF 0             // X (LN output / layer input)     33792
#define X1_OFF 33792         // qk, then agg output (ping-pong) 33792
#define ABH_OFF 67584        // 64*72*2 = 9216
#define AST_OFF 76800        // 2 layers * 64*66*2 = 16896
#define PART_OFF 93696       // softmax partial sums: 64*2 float = 512
#define P2_OFF 94720         // LN partials: 64*8 float2 = 4096
#define P3_OFF 98816         // LN mean/rstd: 64 float2 = 512
#define SMEM_BYTES 99328

__device__ float g_Ast[2 * 64 * 64];
// fragment-packed fp16 weights: index (((o8*8 + kp)*32 + lane)) uint4;
// .x/.y = kstep0 b0/b1, .z/.w = kstep1. [layer][qk|fc][hi|lo]
__device__ uint4 g_Wf[2][2][2][8192];

// ---------------- PTX wrappers ----------------
__device__ __forceinline__ u32 smem_u32(const void* p) {
    u32 a;
    asm("{ .reg .u64 t; cvta.to.shared.u64 t, %1; cvt.u32.u64 %0, t; }" : "=r"(a) : "l"(p));
    return a;
}
__device__ __forceinline__ void ldmx4(u32 a, u32 r[4]) {
    asm volatile("ldmatrix.sync.aligned.m8n8.x4.shared.b16 {%0,%1,%2,%3}, [%4];"
                 : "=r"(r[0]), "=r"(r[1]), "=r"(r[2]), "=r"(r[3]) : "r"(a));
}
__device__ __forceinline__ void ldmx4t(u32 a, u32 r[4]) {
    asm volatile("ldmatrix.sync.aligned.m8n8.x4.trans.shared.b16 {%0,%1,%2,%3}, [%4];"
                 : "=r"(r[0]), "=r"(r[1]), "=r"(r[2]), "=r"(r[3]) : "r"(a));
}
__device__ __forceinline__ void mma16816(float* d, const u32 a[4], u32 b0, u32 b1) {
    asm volatile("mma.sync.aligned.m16n8k16.row.col.f32.f16.f16.f32 "
                 "{%0,%1,%2,%3}, {%4,%5,%6,%7}, {%8,%9}, {%0,%1,%2,%3};"
                 : "+f"(d[0]), "+f"(d[1]), "+f"(d[2]), "+f"(d[3])
                 : "r"(a[0]), "r"(a[1]), "r"(a[2]), "r"(a[3]), "r"(b0), "r"(b1));
}

__device__ __forceinline__ u32 pack_h2(float v0, float v1) {
    __half2 h = __floats2half2_rn(v0, v1);
    return *(u32*)&h;
}

// ---------------- weight GEMM: C[64 n][256 o], 8 warps, warp tile 64n x 32o ----------------
// acc layout: acc[(nf*4 + of)*4 + j], nf = 16n frag, of = 8o frag.
__device__ __forceinline__ void wgemm_reg(
    u32 smb, u32 x_off, const uint4* __restrict__ wH,
    float* acc, int warp, int lane)
{
#pragma unroll
    for (int i = 0; i < 64; i++) acc[i] = 0.f;

    int arow = lane & 15;
    int acol = 8 * (lane >> 4);
    u32 fb = (u32)((warp * 4 * 8) * 32 + lane);  // of stride = 8*32 = 256

    uint4 bh[4];
#pragma unroll
    for (int of = 0; of < 4; of++) bh[of] = wH[fb + of * 256];

#pragma unroll
    for (int kp = 0; kp < 8; kp++) {
        uint4 nh[4];
        if (kp < 7) {
#pragma unroll
            for (int of = 0; of < 4; of++) nh[of] = wH[fb + of * 256 + (kp + 1) * 32];
        }
#pragma unroll
        for (int ks = 0; ks < 2; ks++) {
            int kg = (kp * 2 + ks) * 16;
#pragma unroll
            for (int nf = 0; nf < 4; nf++) {
                u32 ah[4];
                u32 aoff = (u32)((nf * 16 + arow) * X_LD + kg + acol) * 2;
                ldmx4(smb + x_off + aoff, ah);
#pragma unroll
                for (int of = 0; of < 4; of++) {
                    u32 b0 = ks ? bh[of].z : bh[of].x;
                    u32 b1 = ks ? bh[of].w : bh[of].y;
                    mma16816(acc + (nf * 4 + of) * 4, ah, b0, b1);
                }
            }
        }
        if (kp < 7) {
#pragma unroll
            for (int of = 0; of < 4; of++) bh[of] = nh[of];
        }
    }
}

// store acc as fp16 tiles (qk / agg epilogues; col base = warp*32)
__device__ __forceinline__ void wstore_hi(
    char* smc, const float* acc, u32 hoff, int ld, int warp, int lane)
{
    int rb = lane >> 2;
    int cb = warp * 32 + 2 * (lane & 3);
#pragma unroll
    for (int nf = 0; nf < 4; nf++)
#pragma unroll
        for (int of = 0; of < 4; of++)
#pragma unroll
            for (int rr = 0; rr < 2; rr++) {
                int r = nf * 16 + rb + rr * 8;
                int c = cb + of * 8;
                const float* a = acc + (nf * 4 + of) * 4;
                *(u32*)(smc + hoff + (u32)(r * ld + c) * 2) =
                    pack_h2(a[rr * 2], a[rr * 2 + 1]);
            }
}

// store acc + bias directly to global (fc epilogue, layer 1)
__device__ __forceinline__ void wstore_global(
    const float* acc, float* __restrict__ og,
    const float* __restrict__ bias, int warp, int lane)
{
    int rb = lane >> 2;
    int cb = warp * 32 + 2 * (lane & 3);
    float bv[4][2];
#pragma unroll
    for (int of = 0; of < 4; of++) {
        bv[of][0] = bias[cb + of * 8];
        bv[of][1] = bias[cb + of * 8 + 1];
    }
#pragma unroll
    for (int nf = 0; nf < 4; nf++)
#pragma unroll
        for (int of = 0; of < 4; of++)
#pragma unroll
            for (int rr = 0; rr < 2; rr++) {
                int r = nf * 16 + rb + rr * 8;
                int c = cb + of * 8;
                const float* a = acc + (nf * 4 + of) * 4;
                float2 p;
                p.x = a[rr * 2] + bv[of][0];
                p.y = a[rr * 2 + 1] + bv[of][1];
                *(float2*)(og + r * 256 + c) = p;
            }
}

// ---------------- scores: C[64 n][64 m] = q @ k^T, 8 warps, tile 16n x 32m ----------------
__device__ __forceinline__ void scores_tc(u32 smb, float sacc[4][4], int warp, int lane)
{
    int n0 = (warp & 3) * 16;
    int m0 = (warp >> 2) * 32;
#pragma unroll
    for (int t = 0; t < 4; t++)
#pragma unroll
        for (int j = 0; j < 4; j++) sacc[t][j] = 0.f;
    int arow = n0 + (lane & 15);
    int acolsel = 8 * (lane >> 4);
    int brow0 = m0 + (lane & 7) + 8 * ((lane >> 4) & 1);
    int bksel = 8 * ((lane >> 3) & 1);
#pragma unroll
    for (int ks = 0; ks < 8; ks++) {
        int kg = ks * 16;
        u32 ah[4], bh0[4], bh1[4];
        ldmx4(smb + X1_OFF + (u32)(arow * X_LD + kg + acolsel) * 2, ah);
        ldmx4(smb + X1_OFF + (u32)(brow0 * X_LD + 128 + kg + bksel) * 2, bh0);
        ldmx4(smb + X1_OFF + (u32)((brow0 + 16) * X_LD + 128 + kg + bksel) * 2, bh1);
        mma16816(sacc[0], ah, bh0[0], bh0[1]);
        mma16816(sacc[1], ah, bh0[2], bh0[3]);
        mma16816(sacc[2], ah, bh1[0], bh1[1]);
        mma16816(sacc[3], ah, bh1[2], bh1[3]);
    }
}

// ---------------- agg: C[64 n][256 d] = A_hat @ X0, warp tile 64n x 32d ----------------
__device__ __forceinline__ void agg_tc(char* smc, u32 smb, float* acc,
                                       int warp, int lane)
{
#pragma unroll
    for (int i = 0; i < 64; i++) acc[i] = 0.f;
    int arow = lane & 15;
    int acol = 8 * (lane >> 4);
    int xrow = lane & 15;
    int xcol = warp * 32 + 8 * (lane >> 4);
#pragma unroll
    for (int ks = 0; ks < 4; ks++) {
        int kg = ks * 16;
        u32 ah[4][4];
#pragma unroll
        for (int nf = 0; nf < 4; nf++)
            ldmx4(smb + ABH_OFF + (u32)((nf * 16 + arow) * AB_LD + kg + acol) * 2, ah[nf]);
#pragma unroll
        for (int dg = 0; dg < 2; dg++) {
            u32 bh[4];
            ldmx4t(smb + X0_OFF + (u32)((kg + xrow) * X_LD + xcol + dg * 16) * 2, bh);
#pragma unroll
            for (int nf = 0; nf < 4; nf++) {
                mma16816(acc + (nf * 4 + dg * 2) * 4, ah[nf], bh[0], bh[1]);
                mma16816(acc + (nf * 4 + dg * 2 + 1) * 4, ah[nf], bh[2], bh[3]);
            }
        }
    }
}

// ---------------- LayerNorm (global fp32 source) -> fp16 X0 tile ----------------
__device__ __forceinline__ void ln_global(
    char* smc, const float* __restrict__ src,
    const float* __restrict__ gg, const float* __restrict__ bb, int tid)
{
    int warp = tid >> 5, lane = tid & 31;
    for (int n = warp; n < 64; n += 8) {
        const float* row = src + (size_t)n * 256;
        float v[8];
        float s = 0.f, sq = 0.f;
#pragma unroll
        for (int i = 0; i < 4; i++) {
            int c = 2 * lane + 64 * i;
            float2 t = *(const float2*)(row + c);
            v[2 * i] = t.x; v[2 * i + 1] = t.y;
            s += t.x + t.y;
            sq += t.x * t.x + t.y * t.y;
        }
#pragma unroll
        for (int off = 16; off > 0; off >>= 1) {
            s += __shfl_xor_sync(0xffffffffu, s, off);
            sq += __shfl_xor_sync(0xffffffffu, sq, off);
        }
        float mean = s * (1.0f / 256.0f);
        float var = sq * (1.0f / 256.0f) - mean * mean;
        float rstd = rsqrtf(var + 1e-5f);
#pragma unroll
        for (int i = 0; i < 4; i++) {
            int c = 2 * lane + 64 * i;
            float o0 = (v[2 * i] - mean) * rstd * gg[c] + bb[c];
            float o1 = (v[2 * i + 1] - mean) * rstd * gg[c + 1] + bb[c + 1];
            *(u32*)(smc + X0_OFF + (u32)(n * X_LD + c) * 2) = pack_h2(o0, o1);
        }
    }
}

// stage both layers' Ast into smem as fp16
__device__ __forceinline__ void stage_ast(char* smc, int tid) {
    u16* dst = (u16*)(smc + AST_OFF);
    for (int i = tid; i < 8192; i += NT) {
        int l = i >> 12, j = i & 4095;
        int r = j >> 6, m = j & 63;
        dst[l * 64 * AST_LD + r * AST_LD + m] =
            __half_as_ushort(__float2half_rn(g_Ast[l * 4096 + j]));
    }
}

// ---------------- prologue: weights (fragment-packed fp16 hi/lo) + adj softmax ----------------
__global__ void prep_kernel(
    const float* __restrict__ th0, const float* __restrict__ ph0, const float* __restrict__ fcw0,
    const float* __restrict__ th1, const float* __restrict__ ph1, const float* __restrict__ fcw1,
    const float* __restrict__ adj0, const float* __restrict__ adj1)
{
    if (blockIdx.x >= 512) {
        int gw = (blockIdx.x - 512) * 16 + (threadIdx.x >> 5);
        int lane = threadIdx.x & 31;
        int mat = gw >> 6, r = gw & 63;
        const float* row = (mat ? adj1 : adj0) + r * 64;
        float v0 = row[lane], v1 = row[32 + lane];
        float mx = fmaxf(v0, v1);
#pragma unroll
        for (int off = 16; off > 0; off >>= 1)
            mx = fmaxf(mx, __shfl_xor_sync(0xffffffffu, mx, off));
        float e0 = __expf(v0 - mx), e1 = __expf(v1 - mx);
        float ss = e0 + e1;
#pragma unroll
        for (int off = 16; off > 0; off >>= 1)
            ss += __shfl_xor_sync(0xffffffffu, ss, off);
        float inv = 1.0f / ss;
        float* dst = g_Ast + mat * 4096 + r * 64;
        dst[lane] = e0 * inv;
        dst[32 + lane] = e1 * inv;
        return;
    }
    int idx = blockIdx.x * 512 + threadIdx.x;  // 0..262143
    int k = idx & 255, r = (idx >> 8) & 255, g = (idx >> 16) & 1, l = idx >> 17;
    const float* th = l ? th1 : th0;
    const float* pw = l ? ph1 : ph0;
    const float* fw = l ? fcw1 : fcw0;
    float v;
    if (g == 0) v = (r < 128) ? th[r * 256 + k] : pw[(r - 128) * 256 + k];
    else        v = fw[r * 256 + k];
    __half hb = __float2half_rn(v);
    __half lb = __float2half_rn(v - __half2float(hb));
    u32 o8 = (u32)(r >> 3);
    u32 kp = (u32)(k >> 5);
    u32 lane = (u32)((r & 7) * 4 + ((k >> 1) & 3));
    u32 slot = (u32)(((k >> 4) & 1) * 2 + ((k >> 3) & 1));
    u32 off16 = ((((o8 * 8 + kp) * 32 + lane) * 4 + slot) << 1) | (u32)(k & 1);
    ((u16*)g_Wf[l][g][0])[off16] = __half_as_ushort(hb);
    ((u16*)g_Wf[l][g][1])[off16] = __half_as_ushort(lb);
}

// ---------------- main kernel: 256 threads, 2 CTAs/SM ----------------
__global__ void __launch_bounds__(NT, 2) gconv_kernel(
    const float* __restrict__ graph,
    const float* __restrict__ ln_in_g, const float* __restrict__ ln_in_b,
    const float* __restrict__ fcb0,
    const float* __restrict__ ln0_g, const float* __restrict__ ln0_b,
    const float* __restrict__ fcb1,
    float* __restrict__ out)
{
    extern __shared__ char smc[];
    u32 smb = smem_u32(smc);
    int tid = threadIdx.x;
    int warp = tid >> 5, lane = tid & 31;
    int b = blockIdx.x;

    // input LN -> X0; stage both Ast layers
    ln_global(smc, graph + (size_t)b * 64 * 256, ln_in_g, ln_in_b, tid);
    stage_ast(smc, tid);
    __syncthreads();

    float acc[64];

#pragma unroll 1
    for (int l = 0; l < 2; l++) {
        // ---- qk = X0 @ W_qk^T -> X1 ----
        wgemm_reg(smb, X0_OFF, g_Wf[l][0][0], acc, warp, lane);
        wstore_hi(smc, acc, X1_OFF, X_LD, warp, lane);
        __syncthreads();

        // ---- scores (reads X1) + max-free softmax -> A_hat fp16 (ABH) ----
        // LN-bounded inputs => |score| <= ~12, exp() safe without max-shift.
        {
            float sacc[4][4];
            scores_tc(smb, sacc, warp, lane);
            const float sscale = 0.08838834764831845f;  // 1/sqrt(128)
            float s0 = 0.f, s1 = 0.f;
#pragma unroll
            for (int t = 0; t < 4; t++) {
                sacc[t][0] = __expf(sacc[t][0] * sscale);
                sacc[t][1] = __expf(sacc[t][1] * sscale);
                sacc[t][2] = __expf(sacc[t][2] * sscale);
                sacc[t][3] = __expf(sacc[t][3] * sscale);
                s0 += sacc[t][0] + sacc[t][1];
                s1 += sacc[t][2] + sacc[t][3];
            }
#pragma unroll
            for (int d = 1; d <= 2; d <<= 1) {
                s0 += __shfl_xor_sync(0xffffffffu, s0, d);
                s1 += __shfl_xor_sync(0xffffffffu, s1, d);
            }
            int n0 = (warp & 3) * 16;
            int mw = warp >> 2;
            int r = n0 + (lane >> 2);
            float* part = (float*)(smc + PART_OFF);
            if ((lane & 3) == 0) {
                part[r * 2 + mw] = s0;
                part[(r + 8) * 2 + mw] = s1;
            }
            // prefetch Ast rows while waiting on the barrier
            int m0 = mw * 32;
            const u16* ast = (const u16*)(smc + AST_OFF) + l * 64 * AST_LD;
            u32 av0[4], av1[4];
#pragma unroll
            for (int t = 0; t < 4; t++) {
                int m = m0 + 2 * (lane & 3) + t * 8;
                av0[t] = *(const u32*)(ast + r * AST_LD + m);
                av1[t] = *(const u32*)(ast + (r + 8) * AST_LD + m);
            }
            __syncthreads();
            float corr0 = 1.0f / (part[r * 2] + part[r * 2 + 1]);
            float corr1 = 1.0f / (part[(r + 8) * 2] + part[(r + 8) * 2 + 1]);
            u16* abh = (u16*)(smc + ABH_OFF);
#pragma unroll
            for (int t = 0; t < 4; t++) {
                int m = m0 + 2 * (lane & 3) + t * 8;
                __half2 h0 = *(__half2*)&av0[t];
                float2 a0 = __half22float2(h0);
                *(u32*)(abh + r * AB_LD + m) =
                    pack_h2(a0.x + sacc[t][0] * corr0, a0.y + sacc[t][1] * corr0);
                __half2 h1 = *(__half2*)&av1[t];
                float2 a1 = __half22float2(h1);
                *(u32*)(abh + (r + 8) * AB_LD + m) =
                    pack_h2(a1.x + sacc[t][2] * corr1, a1.y + sacc[t][3] * corr1);
            }
        }
        __syncthreads();   // ABH ready; X1 (qk) now dead

        // ---- agg = A_hat @ X0 -> X1 (overwrites qk) ----
        agg_tc(smc, smb, acc, warp, lane);
        wstore_hi(smc, acc, X1_OFF, X_LD, warp, lane);
        __syncthreads();

        // ---- fc = agg(X1) @ W_fc^T ----
        wgemm_reg(smb, X1_OFF, g_Wf[l][1][0], acc, warp, lane);
        if (l == 0) {
            // fragment-resident bias + LayerNorm + leaky -> X0
            int rb = lane >> 2;
            int cb = warp * 32 + 2 * (lane & 3);
#pragma unroll
            for (int of = 0; of < 4; of++) {
                float b0 = fcb0[cb + of * 8], b1 = fcb0[cb + of * 8 + 1];
#pragma unroll
                for (int nf = 0; nf < 4; nf++) {
                    float* a = acc + (nf * 4 + of) * 4;
                    a[0] += b0; a[1] += b1; a[2] += b0; a[3] += b1;
                }
            }
            float2* p2 = (float2*)(smc + P2_OFF);
#pragma unroll
            for (int nf = 0; nf < 4; nf++)
#pragma unroll
                for (int rr = 0; rr < 2; rr++) {
                    float s = 0.f, sq = 0.f;
#pragma unroll
                    for (int of = 0; of < 4; of++) {
                        const float* a = acc + (nf * 4 + of) * 4;
                        float x0 = a[rr * 2], x1 = a[rr * 2 + 1];
                        s += x0 + x1;
                        sq += x0 * x0 + x1 * x1;
                    }
#pragma unroll
                    for (int d = 1; d <= 2; d <<= 1) {
                        s += __shfl_xor_sync(0xffffffffu, s, d);
                        sq += __shfl_xor_sync(0xffffffffu, sq, d);
                    }
                    if ((lane & 3) == 0)
                        p2[(nf * 16 + rb + rr * 8) * 8 + warp] = make_float2(s, sq);
                }
            __syncthreads();
            float2* p3 = (float2*)(smc + P3_OFF);
            if (tid < 64) {
                float s = 0.f, sq = 0.f;
#pragma unroll
                for (int w = 0; w < 8; w++) {
                    float2 v = p2[tid * 8 + w];
                    s += v.x; sq += v.y;
                }
                float mean = s * (1.0f / 256.0f);
                float var = sq * (1.0f / 256.0f) - mean * mean;
                p3[tid] = make_float2(mean, rsqrtf(var + 1e-5f));
            }
            __syncthreads();
#pragma unroll
            for (int nf = 0; nf < 4; nf++)
#pragma unroll
                for (int rr = 0; rr < 2; rr++) {
                    int r = nf * 16 + rb + rr * 8;
                    float2 mr = p3[r];
#pragma unroll
                    for (int of = 0; of < 4; of++) {
                        int c = cb + of * 8;
                        const float* a = acc + (nf * 4 + of) * 4;
                        float o0 = (a[rr * 2] - mr.x) * mr.y * ln0_g[c] + ln0_b[c];
                        float o1 = (a[rr * 2 + 1] - mr.x) * mr.y * ln0_g[c + 1] + ln0_b[c + 1];
                        o0 = (o0 >= 0.f) ? o0 : 0.1f * o0;
                        o1 = (o1 >= 0.f) ? o1 : 0.1f * o1;
                        *(u32*)(smc + X0_OFF + (u32)(r * X_LD + c) * 2) = pack_h2(o0, o1);
                    }
                }
            __syncthreads();
        } else {
            wstore_global(acc, out + (size_t)b * 64 * 256, fcb1, warp, lane);
        }
    }
}

extern "C" void kernel_launch(void* const* d_in, const int* in_sizes, int n_in,
                              void* d_out, int out_size)
{
    const float* graph   = (const float*)d_in[0];
    const float* ln_in_g = (const float*)d_in[1];
    const float* ln_in_b = (const float*)d_in[2];
    const float* adj0    = (const float*)d_in[3];
    const float* th0     = (const float*)d_in[4];
    const float* ph0     = (const float*)d_in[5];
    const float* fcw0    = (const float*)d_in[6];
    const float* fcb0    = (const float*)d_in[7];
    const float* ln0_g   = (const float*)d_in[8];
    const float* ln0_b   = (const float*)d_in[9];
    const float* adj1    = (const float*)d_in[10];
    const float* th1     = (const float*)d_in[11];
    const float* ph1     = (const float*)d_in[12];
    const float* fcw1    = (const float*)d_in[13];
    const float* fcb1    = (const float*)d_in[14];
    float* out = (float*)d_out;

    cudaFuncSetAttribute(gconv_kernel,
                         cudaFuncAttributeMaxDynamicSharedMemorySize, SMEM_BYTES);

    prep_kernel<<<520, 512>>>(th0, ph0, fcw0, th1, ph1, fcw1, adj0, adj1);
    gconv_kernel<<<NB, NT, SMEM_BYTES>>>(
        graph, ln_in_g, ln_in_b, fcb0, ln0_g, ln0_b, fcb1, out);
}